// round 8
// baseline (speedup 1.0000x reference)
#include <cuda_runtime.h>
#include <cuda_fp16.h>
#include <cuda_bf16.h>
#include <math.h>
#include <stdint.h>

#define A_ANG 180
#define R_RHO 180
#define AR    32400
#define Hh    128
#define Ww    128
#define HW    16384
#define Nn    8
#define CI1   256
#define DIM   128
#define NC    1024   /* Nn*DIM */

// ---------------- static device scratch ----------------
__device__ unsigned char  g_seg[A_ANG * HW];
__device__ __half         g_ft[(size_t)HW * NC];           // conv1 out, [pixel][n*128+c] fp16
__device__ float          g_acc[(size_t)Nn * DIM * AR];    // DHT out, NCHW [n][c][a][r]
__device__ float          g_y2 [(size_t)Nn * DIM * AR];    // conv2 out
__device__ __half2        g_w2h[9 * 64 * 128];             // weights [tap][ci2][co], half2 over ci pair
__device__ __half2        g_w3h[9 * 64 * 128];
__device__ unsigned short g_csr_idx[A_ANG * HW];           // pixel lists per (angle, bin)
__device__ int            g_csr_ptr[A_ANG * 181];          // row pointers per angle

// ---------------- seg table: fp64, bit-matches numpy binning ----------------
__global__ void seg_kernel() {
    int a = blockIdx.x;
    int p = blockIdx.y * 256 + threadIdx.x;
    double irho = (double)((int)(sqrt((double)(Hh * Hh + Ww * Ww)) + 1.0)) / (double)(R_RHO - 1);
    double theta = (double)a * (3.141592653589793 / (double)A_ANG);
    double tc = cos(theta) / irho;
    double ts = sin(theta) / irho;
    int y = p >> 7, x = p & (Ww - 1);
    double val = __dadd_rn(__dmul_rn(tc, (double)(x - Ww / 2)),
                           __dmul_rn(ts, (double)(y - Hh / 2)));
    long long r = (long long)rint(val) + R_RHO / 2;
    if (r < 0) r = 0;
    if (r > R_RHO - 1) r = R_RHO - 1;
    g_seg[a * HW + p] = (unsigned char)r;
}

// ---------------- CSR build: per angle, deterministic two-pass rank fill ----------------
__global__ __launch_bounds__(128) void csr_kernel() {
    __shared__ unsigned short hist[128][180];
    __shared__ int off[181];
    int a = blockIdx.x, t = threadIdx.x;

    for (int r = 0; r < 180; r++) hist[t][r] = 0;
    const unsigned char* segrow = g_seg + a * HW + t * 128;
    for (int x = 0; x < 128; x++) hist[t][segrow[x]]++;
    __syncthreads();

    for (int r = t; r < 180; r += 128) {
        int run = 0;
        for (int q = 0; q < 128; q++) {
            int tmp = hist[q][r];
            hist[q][r] = (unsigned short)run;
            run += tmp;
        }
        off[r] = run;
    }
    __syncthreads();
    if (t == 0) {
        int run = 0;
        for (int r = 0; r < 180; r++) { int tot = off[r]; off[r] = run; run += tot; }
        off[180] = run;
    }
    __syncthreads();

    unsigned short* myh = hist[t];
    for (int x = 0; x < 128; x++) {
        int r = segrow[x];
        int pos = off[r] + myh[r];
        myh[r]++;
        g_csr_idx[a * HW + pos] = (unsigned short)(t * 128 + x);
    }
    for (int i = t; i < 181; i += 128) g_csr_ptr[a * 181 + i] = off[i];
}

// ---------------- weight prep: w[co][ci][tap] -> half2 [tap][ci2][co] ----------------
__global__ void wpreph_kernel(const float* __restrict__ w, __half2* __restrict__ wh) {
    int e = blockIdx.x * 256 + threadIdx.x;
    if (e < 9 * 64 * 128) {
        int tap = e >> 13;
        int ci2 = (e >> 7) & 63;
        int co  = e & 127;
        float lo = w[co * 1152 + (2 * ci2) * 9 + tap];
        float hi = w[co * 1152 + (2 * ci2 + 1) * 9 + tap];
        wh[e] = __floats2half2_rn(lo, hi);
    }
}

// ---------------- conv1: 1x1 conv + BN + ReLU, GEMM 128co x 64px, K=256 ----------------
__global__ __launch_bounds__(256) void conv1_kernel(
    const float* __restrict__ x, const float* __restrict__ w,
    const float* __restrict__ b, const float* __restrict__ g,
    const float* __restrict__ be, const float* __restrict__ m,
    const float* __restrict__ v)
{
    __shared__ float As[8][128];
    __shared__ float Bs[8][64];
    __shared__ float sS[128], tS[128];
    int t = threadIdx.x;
    if (t < 128) {
        float sc = g[t] * rsqrtf(v[t] + 1e-5f);
        sS[t] = sc;
        tS[t] = (b[t] - m[t]) * sc + be[t];
    }
    int col0 = blockIdx.x * 64;
    int n  = col0 >> 14;
    int p0 = col0 & (HW - 1);

    float acc[8][4];
#pragma unroll
    for (int i = 0; i < 8; i++)
#pragma unroll
        for (int j = 0; j < 4; j++) acc[i][j] = 0.f;

    int a_kk = t & 7;
    int b_cc = t & 63;
    int b_kb = t >> 6;

    for (int k0 = 0; k0 < CI1; k0 += 8) {
        __syncthreads();
#pragma unroll
        for (int i = 0; i < 4; i++) {
            int co = (t >> 3) + 32 * i;
            As[a_kk][co] = w[co * CI1 + k0 + a_kk];
        }
#pragma unroll
        for (int i = 0; i < 2; i++) {
            int kk = b_kb + 4 * i;
            Bs[kk][b_cc] = x[(size_t)(n * CI1 + k0 + kk) * HW + p0 + b_cc];
        }
        __syncthreads();
#pragma unroll
        for (int kk = 0; kk < 8; kk++) {
            float av[8], bv[4];
#pragma unroll
            for (int i = 0; i < 8; i++) av[i] = As[kk][(t & 15) + 16 * i];
#pragma unroll
            for (int j = 0; j < 4; j++) bv[j] = Bs[kk][(t >> 4) + 16 * j];
#pragma unroll
            for (int i = 0; i < 8; i++)
#pragma unroll
                for (int j = 0; j < 4; j++) acc[i][j] += av[i] * bv[j];
        }
    }
#pragma unroll
    for (int i = 0; i < 8; i++) {
        int co = (t & 15) + 16 * i;
        float sc = sS[co], tt = tS[co];
#pragma unroll
        for (int j = 0; j < 4; j++) {
            int p = p0 + (t >> 4) + 16 * j;
            float yv = fmaxf(acc[i][j] * sc + tt, 0.f);
            g_ft[(size_t)p * NC + n * DIM + co] = __float2half_rn(yv);
        }
    }
}

// ---------------- DHT gather: block (a, n-pair); warp = pixel-balanced bin range ----------------
// 256 threads: t>>7 selects n within the pair; idxS/ptrS staging shared across both n.
__global__ __launch_bounds__(256) void dhtg_kernel() {
    __shared__ unsigned short idxS[HW];
    __shared__ int ptrS[181];
    int a = blockIdx.x, t = threadIdx.x;
    int n = blockIdx.y * 2 + (t >> 7);

    {
        const int4* gs = (const int4*)(g_csr_idx + a * HW);
        int4* ss = (int4*)idxS;
#pragma unroll
        for (int i = 0; i < 8; i++) ss[t + 256 * i] = gs[t + 256 * i];   // 2048 int4 = full 16384 idx
        for (int i = t; i < 181; i += 256) ptrS[i] = g_csr_ptr[a * 181 + i];
    }
    __syncthreads();

    int w = (t >> 5) & 3, lane = t & 31;
    int b0 = 0;
    while (b0 < 180 && ptrS[b0] < w * 4096) b0++;
    int b1;
    if (w == 3) b1 = 180;
    else { b1 = 0; while (b1 < 180 && ptrS[b1] < (w + 1) * 4096) b1++; }

    const __half* fbase = g_ft + n * DIM + (lane << 2);

    for (int r = b0; r < b1; r++) {
        int s = ptrS[r], e = ptrS[r + 1];
        float a0 = 0.f, a1 = 0.f, a2 = 0.f, a3 = 0.f;
        float c0 = 0.f, c1 = 0.f, c2 = 0.f, c3 = 0.f;
        int i = s;
        for (; i + 4 <= e; i += 4) {
            int p0 = idxS[i], p1 = idxS[i + 1], p2 = idxS[i + 2], p3 = idxS[i + 3];
            uint2 u0 = *(const uint2*)(fbase + (size_t)p0 * NC);
            uint2 u1 = *(const uint2*)(fbase + (size_t)p1 * NC);
            uint2 u2 = *(const uint2*)(fbase + (size_t)p2 * NC);
            uint2 u3 = *(const uint2*)(fbase + (size_t)p3 * NC);
            float2 f;
            f = __half22float2(*(__half2*)&u0.x); a0 += f.x; a1 += f.y;
            f = __half22float2(*(__half2*)&u0.y); a2 += f.x; a3 += f.y;
            f = __half22float2(*(__half2*)&u1.x); c0 += f.x; c1 += f.y;
            f = __half22float2(*(__half2*)&u1.y); c2 += f.x; c3 += f.y;
            f = __half22float2(*(__half2*)&u2.x); a0 += f.x; a1 += f.y;
            f = __half22float2(*(__half2*)&u2.y); a2 += f.x; a3 += f.y;
            f = __half22float2(*(__half2*)&u3.x); c0 += f.x; c1 += f.y;
            f = __half22float2(*(__half2*)&u3.y); c2 += f.x; c3 += f.y;
        }
        for (; i < e; i++) {
            int p = idxS[i];
            uint2 u = *(const uint2*)(fbase + (size_t)p * NC);
            float2 f;
            f = __half22float2(*(__half2*)&u.x); a0 += f.x; a1 += f.y;
            f = __half22float2(*(__half2*)&u.y); a2 += f.x; a3 += f.y;
        }
        a0 += c0; a1 += c1; a2 += c2; a3 += c3;
        float* dst = g_acc + ((size_t)(n * DIM + (lane << 2)) * 180 + a) * 180 + r;
        dst[0]              = a0;
        dst[AR]             = a1;
        dst[2 * AR]         = a2;
        dst[3 * (size_t)AR] = a3;
    }
}

// ---------------- conv3x3 + BN + ReLU: fp16 mma m16n8k16, 2 angles per block ----------------
// 512 threads: warps 0-7 -> angle a0, warps 8-15 -> a0+1. 96 cols per block half.
// smem half2: Wh2[tap s1088][ci2 s136][co], Bh2[ci2 s408][ar 4 s102][q 0..97]
#define WH2_N   (9 * 8 * 136)      /* 9792 half2 */
#define BH2_N   (8 * 408)          /* 3264 half2 */
#define C3_SMEM (WH2_N * 4 + BH2_N * 4 + 256 * 4)

__global__ __launch_bounds__(512) void conv3h_kernel(
    const float* __restrict__ src, const __half2* __restrict__ wh,
    const float* __restrict__ b,  const float* __restrict__ g,
    const float* __restrict__ be, const float* __restrict__ m,
    const float* __restrict__ v,  float* __restrict__ dst)
{
    extern __shared__ __align__(16) char smraw[];
    __half2* Wh2 = (__half2*)smraw;
    __half2* Bh2 = (__half2*)(smraw + WH2_N * 4);
    float*   sS  = (float*)(smraw + WH2_N * 4 + BH2_N * 4);
    float*   tS  = sS + 128;

    int t  = threadIdx.x;
    int r0 = blockIdx.x * 84;         // 0 or 84 (12-col overlap, identical values)
    int a0 = blockIdx.y * 2;
    int n  = blockIdx.z;
    if (t < 128) {
        float sc = g[t] * rsqrtf(v[t] + 1e-5f);
        sS[t] = sc;
        tS[t] = (b[t] - m[t]) * sc + be[t];
    }

    int lane = t & 31, warp = t >> 5;
    int wa = warp >> 3;               // angle within pair
    int grp = lane >> 2, q4 = lane & 3;
    int co_base = (warp & 7) * 16;

    float acc[12][4];
#pragma unroll
    for (int j = 0; j < 12; j++)
#pragma unroll
        for (int i = 0; i < 4; i++) acc[j][i] = 0.f;

    const float* srcn = src + (size_t)n * DIM * AR;

#pragma unroll 1
    for (int c0 = 0; c0 < DIM; c0 += 16) {
        int ci2g = c0 >> 1;
        __syncthreads();
        // stage weights: Wh2[tap][ci2 0..7][co]
        for (int e = t; e < 9 * 8 * 128; e += 512) {
            int tap = e >> 10;
            int ci2 = (e >> 7) & 7;
            int co  = e & 127;
            Wh2[tap * 1088 + ci2 * 136 + co] = wh[((size_t)tap * 64 + ci2g + ci2) * 128 + co];
        }
        // stage input: ci 0..15, rows a0-1..a0+2 (ar 0..3), q 0..97 (r = r0-1+q)
        __half* Bh = (__half*)Bh2;
        for (int e = t; e < 16 * 4 * 98; e += 512) {
            int ci  = e / 392;
            int rem = e - ci * 392;
            int ar  = rem / 98;
            int qq  = rem - ar * 98;
            int as  = a0 - 1 + ar;
            int rs  = r0 - 1 + qq;
            float val = 0.f;
            if ((unsigned)as < 180u && (unsigned)rs < 180u)
                val = srcn[((size_t)(c0 + ci) * 180 + as) * 180 + rs];
            Bh[(ci >> 1) * 816 + ar * 204 + qq * 2 + (ci & 1)] = __float2half_rn(val);
        }
        __syncthreads();

#pragma unroll
        for (int tap = 0; tap < 9; tap++) {
            int ky = tap / 3, kx = tap - 3 * (tap / 3);
            const __half2* wA = Wh2 + tap * 1088;
            unsigned a0r = *(const unsigned*)(wA + q4 * 136 + co_base + grp);
            unsigned a1r = *(const unsigned*)(wA + q4 * 136 + co_base + grp + 8);
            unsigned a2r = *(const unsigned*)(wA + (q4 + 4) * 136 + co_base + grp);
            unsigned a3r = *(const unsigned*)(wA + (q4 + 4) * 136 + co_base + grp + 8);
            const __half2* bB = Bh2 + (wa + ky) * 102 + kx + grp;
#pragma unroll
            for (int jn = 0; jn < 12; jn++) {
                unsigned b0r = *(const unsigned*)(bB + q4 * 408 + jn * 8);
                unsigned b1r = *(const unsigned*)(bB + (q4 + 4) * 408 + jn * 8);
                asm volatile(
                    "mma.sync.aligned.m16n8k16.row.col.f32.f16.f16.f32 "
                    "{%0,%1,%2,%3}, {%4,%5,%6,%7}, {%8,%9}, {%0,%1,%2,%3};"
                    : "+f"(acc[jn][0]), "+f"(acc[jn][1]),
                      "+f"(acc[jn][2]), "+f"(acc[jn][3])
                    : "r"(a0r), "r"(a1r), "r"(a2r), "r"(a3r),
                      "r"(b0r), "r"(b1r));
            }
        }
    }

    int a = a0 + wa;
    int co0 = co_base + grp;
    int co1 = co0 + 8;
    float sc0 = sS[co0], tt0 = tS[co0];
    float sc1 = sS[co1], tt1 = tS[co1];
    float* d0 = dst + ((size_t)(n * DIM + co0) * 180 + a) * 180 + r0 + q4 * 2;
    float* d1 = dst + ((size_t)(n * DIM + co1) * 180 + a) * 180 + r0 + q4 * 2;
#pragma unroll
    for (int jn = 0; jn < 12; jn++) {
        float2 o0, o1;
        o0.x = fmaxf(acc[jn][0] * sc0 + tt0, 0.f);
        o0.y = fmaxf(acc[jn][1] * sc0 + tt0, 0.f);
        o1.x = fmaxf(acc[jn][2] * sc1 + tt1, 0.f);
        o1.y = fmaxf(acc[jn][3] * sc1 + tt1, 0.f);
        *(float2*)(d0 + jn * 8) = o0;
        *(float2*)(d1 + jn * 8) = o1;
    }
}

// ---------------- launch ----------------
extern "C" void kernel_launch(void* const* d_in, const int* in_sizes, int n_in,
                              void* d_out, int out_size) {
    const float* x   = (const float*)d_in[0];
    const float* w1  = (const float*)d_in[1];
    const float* b1  = (const float*)d_in[2];
    const float* g1  = (const float*)d_in[3];
    const float* be1 = (const float*)d_in[4];
    const float* m1  = (const float*)d_in[5];
    const float* v1  = (const float*)d_in[6];
    const float* w2  = (const float*)d_in[7];
    const float* b2  = (const float*)d_in[8];
    const float* g2  = (const float*)d_in[9];
    const float* be2 = (const float*)d_in[10];
    const float* m2  = (const float*)d_in[11];
    const float* v2  = (const float*)d_in[12];
    const float* w3  = (const float*)d_in[13];
    const float* b3  = (const float*)d_in[14];
    const float* g3  = (const float*)d_in[15];
    const float* be3 = (const float*)d_in[16];
    const float* m3  = (const float*)d_in[17];
    const float* v3  = (const float*)d_in[18];
    float* out = (float*)d_out;

    void *p_w2h, *p_w3h, *p_acc, *p_y2;
    cudaGetSymbolAddress(&p_w2h, g_w2h);
    cudaGetSymbolAddress(&p_w3h, g_w3h);
    cudaGetSymbolAddress(&p_acc, g_acc);
    cudaGetSymbolAddress(&p_y2,  g_y2);

    cudaFuncSetAttribute(conv3h_kernel, cudaFuncAttributeMaxDynamicSharedMemorySize, C3_SMEM);

    seg_kernel<<<dim3(A_ANG, HW / 256), 256>>>();
    conv1_kernel<<<(Nn * HW) / 64, 256>>>(x, w1, b1, g1, be1, m1, v1);
    csr_kernel<<<A_ANG, 128>>>();
    dhtg_kernel<<<dim3(A_ANG, Nn / 2), 256>>>();
    wpreph_kernel<<<(9 * 64 * 128 + 255) / 256, 256>>>(w2, (__half2*)p_w2h);
    wpreph_kernel<<<(9 * 64 * 128 + 255) / 256, 256>>>(w3, (__half2*)p_w3h);
    conv3h_kernel<<<dim3(2, A_ANG / 2, Nn), 512, C3_SMEM>>>(
        (const float*)p_acc, (const __half2*)p_w2h, b2, g2, be2, m2, v2, (float*)p_y2);
    conv3h_kernel<<<dim3(2, A_ANG / 2, Nn), 512, C3_SMEM>>>(
        (const float*)p_y2, (const __half2*)p_w3h, b3, g3, be3, m3, v3, out);
}

// round 10
// speedup vs baseline: 1.1986x; 1.1986x over previous
#include <cuda_runtime.h>
#include <cuda_fp16.h>
#include <cuda_bf16.h>
#include <math.h>
#include <stdint.h>

#define A_ANG 180
#define R_RHO 180
#define AR    32400
#define Hh    128
#define Ww    128
#define HW    16384
#define Nn    8
#define CI1   256
#define DIM   128
#define NC    1024   /* Nn*DIM */

// ---------------- static device scratch ----------------
__device__ unsigned char  g_seg[A_ANG * HW];
__device__ __half         g_ft[(size_t)HW * NC];           // conv1 out, [pixel][n*128+c] fp16
__device__ __half         g_acc[(size_t)Nn * DIM * AR];    // DHT out, NCHW [n][c][a][r], fp16
__device__ __half         g_y2 [(size_t)Nn * DIM * AR];    // conv2 out, fp16
__device__ __half2        g_w2h[9 * 64 * 128];             // weights [tap][ci2][co], half2 ci pair
__device__ __half2        g_w3h[9 * 64 * 128];
__device__ unsigned short g_csr_idx[A_ANG * HW];
__device__ int            g_csr_ptr[A_ANG * 181];

__device__ __forceinline__ uint32_t smem_u32(const void* p) {
    uint32_t a;
    asm("{ .reg .u64 t; cvta.to.shared.u64 t, %1; cvt.u32.u64 %0, t; }" : "=r"(a) : "l"(p));
    return a;
}
#define CP_ASYNC16(dst_u32, src_ptr) \
    asm volatile("cp.async.ca.shared.global [%0], [%1], 16;" :: "r"(dst_u32), "l"(src_ptr))
#define CP_COMMIT()  asm volatile("cp.async.commit_group;")
#define CP_WAIT0()   asm volatile("cp.async.wait_group 0;" ::: "memory")

// ---------------- seg table: fp64, bit-matches numpy binning ----------------
__global__ void seg_kernel() {
    int a = blockIdx.x;
    int p = blockIdx.y * 256 + threadIdx.x;
    double irho = (double)((int)(sqrt((double)(Hh * Hh + Ww * Ww)) + 1.0)) / (double)(R_RHO - 1);
    double theta = (double)a * (3.141592653589793 / (double)A_ANG);
    double tc = cos(theta) / irho;
    double ts = sin(theta) / irho;
    int y = p >> 7, x = p & (Ww - 1);
    double val = __dadd_rn(__dmul_rn(tc, (double)(x - Ww / 2)),
                           __dmul_rn(ts, (double)(y - Hh / 2)));
    long long r = (long long)rint(val) + R_RHO / 2;
    if (r < 0) r = 0;
    if (r > R_RHO - 1) r = R_RHO - 1;
    g_seg[a * HW + p] = (unsigned char)r;
}

// ---------------- CSR build ----------------
__global__ __launch_bounds__(128) void csr_kernel() {
    __shared__ unsigned short hist[128][180];
    __shared__ int off[181];
    int a = blockIdx.x, t = threadIdx.x;

    for (int r = 0; r < 180; r++) hist[t][r] = 0;
    const unsigned char* segrow = g_seg + a * HW + t * 128;
    for (int x = 0; x < 128; x++) hist[t][segrow[x]]++;
    __syncthreads();

    for (int r = t; r < 180; r += 128) {
        int run = 0;
        for (int q = 0; q < 128; q++) {
            int tmp = hist[q][r];
            hist[q][r] = (unsigned short)run;
            run += tmp;
        }
        off[r] = run;
    }
    __syncthreads();
    if (t == 0) {
        int run = 0;
        for (int r = 0; r < 180; r++) { int tot = off[r]; off[r] = run; run += tot; }
        off[180] = run;
    }
    __syncthreads();

    unsigned short* myh = hist[t];
    for (int x = 0; x < 128; x++) {
        int r = segrow[x];
        int pos = off[r] + myh[r];
        myh[r]++;
        g_csr_idx[a * HW + pos] = (unsigned short)(t * 128 + x);
    }
    for (int i = t; i < 181; i += 128) g_csr_ptr[a * 181 + i] = off[i];
}

// ---------------- weight prep: w[co][ci][tap] -> half2 [tap][ci2][co] ----------------
__global__ void wpreph_kernel(const float* __restrict__ w, __half2* __restrict__ wh) {
    int e = blockIdx.x * 256 + threadIdx.x;
    if (e < 9 * 64 * 128) {
        int tap = e >> 13;
        int ci2 = (e >> 7) & 63;
        int co  = e & 127;
        float lo = w[co * 1152 + (2 * ci2) * 9 + tap];
        float hi = w[co * 1152 + (2 * ci2 + 1) * 9 + tap];
        wh[e] = __floats2half2_rn(lo, hi);
    }
}

// ---------------- conv1: 1x1 conv + BN + ReLU ----------------
__global__ __launch_bounds__(256) void conv1_kernel(
    const float* __restrict__ x, const float* __restrict__ w,
    const float* __restrict__ b, const float* __restrict__ g,
    const float* __restrict__ be, const float* __restrict__ m,
    const float* __restrict__ v)
{
    __shared__ float As[8][128];
    __shared__ float Bs[8][64];
    __shared__ float sS[128], tS[128];
    int t = threadIdx.x;
    if (t < 128) {
        float sc = g[t] * rsqrtf(v[t] + 1e-5f);
        sS[t] = sc;
        tS[t] = (b[t] - m[t]) * sc + be[t];
    }
    int col0 = blockIdx.x * 64;
    int n  = col0 >> 14;
    int p0 = col0 & (HW - 1);

    float acc[8][4];
#pragma unroll
    for (int i = 0; i < 8; i++)
#pragma unroll
        for (int j = 0; j < 4; j++) acc[i][j] = 0.f;

    int a_kk = t & 7;
    int b_cc = t & 63;
    int b_kb = t >> 6;

    for (int k0 = 0; k0 < CI1; k0 += 8) {
        __syncthreads();
#pragma unroll
        for (int i = 0; i < 4; i++) {
            int co = (t >> 3) + 32 * i;
            As[a_kk][co] = w[co * CI1 + k0 + a_kk];
        }
#pragma unroll
        for (int i = 0; i < 2; i++) {
            int kk = b_kb + 4 * i;
            Bs[kk][b_cc] = x[(size_t)(n * CI1 + k0 + kk) * HW + p0 + b_cc];
        }
        __syncthreads();
#pragma unroll
        for (int kk = 0; kk < 8; kk++) {
            float av[8], bv[4];
#pragma unroll
            for (int i = 0; i < 8; i++) av[i] = As[kk][(t & 15) + 16 * i];
#pragma unroll
            for (int j = 0; j < 4; j++) bv[j] = Bs[kk][(t >> 4) + 16 * j];
#pragma unroll
            for (int i = 0; i < 8; i++)
#pragma unroll
                for (int j = 0; j < 4; j++) acc[i][j] += av[i] * bv[j];
        }
    }
#pragma unroll
    for (int i = 0; i < 8; i++) {
        int co = (t & 15) + 16 * i;
        float sc = sS[co], tt = tS[co];
#pragma unroll
        for (int j = 0; j < 4; j++) {
            int p = p0 + (t >> 4) + 16 * j;
            float yv = fmaxf(acc[i][j] * sc + tt, 0.f);
            g_ft[(size_t)p * NC + n * DIM + co] = __float2half_rn(yv);
        }
    }
}

// ---------------- DHT gather (R8-proven, half output) ----------------
__global__ __launch_bounds__(256) void dhtg_kernel() {
    __shared__ unsigned short idxS[HW];
    __shared__ int ptrS[181];
    int a = blockIdx.x, t = threadIdx.x;
    int n = blockIdx.y * 2 + (t >> 7);

    {
        const int4* gs = (const int4*)(g_csr_idx + a * HW);
        int4* ss = (int4*)idxS;
#pragma unroll
        for (int i = 0; i < 8; i++) ss[t + 256 * i] = gs[t + 256 * i];
        for (int i = t; i < 181; i += 256) ptrS[i] = g_csr_ptr[a * 181 + i];
    }
    __syncthreads();

    int w = (t >> 5) & 3, lane = t & 31;
    int b0 = 0;
    while (b0 < 180 && ptrS[b0] < w * 4096) b0++;
    int b1;
    if (w == 3) b1 = 180;
    else { b1 = 0; while (b1 < 180 && ptrS[b1] < (w + 1) * 4096) b1++; }

    const __half* fbase = g_ft + n * DIM + (lane << 2);

    for (int r = b0; r < b1; r++) {
        int s = ptrS[r], e = ptrS[r + 1];
        float a0 = 0.f, a1 = 0.f, a2 = 0.f, a3 = 0.f;
        float c0 = 0.f, c1 = 0.f, c2 = 0.f, c3 = 0.f;
        int i = s;
        for (; i + 4 <= e; i += 4) {
            int p0 = idxS[i], p1 = idxS[i + 1], p2 = idxS[i + 2], p3 = idxS[i + 3];
            uint2 u0 = *(const uint2*)(fbase + (size_t)p0 * NC);
            uint2 u1 = *(const uint2*)(fbase + (size_t)p1 * NC);
            uint2 u2 = *(const uint2*)(fbase + (size_t)p2 * NC);
            uint2 u3 = *(const uint2*)(fbase + (size_t)p3 * NC);
            float2 f;
            f = __half22float2(*(__half2*)&u0.x); a0 += f.x; a1 += f.y;
            f = __half22float2(*(__half2*)&u0.y); a2 += f.x; a3 += f.y;
            f = __half22float2(*(__half2*)&u1.x); c0 += f.x; c1 += f.y;
            f = __half22float2(*(__half2*)&u1.y); c2 += f.x; c3 += f.y;
            f = __half22float2(*(__half2*)&u2.x); a0 += f.x; a1 += f.y;
            f = __half22float2(*(__half2*)&u2.y); a2 += f.x; a3 += f.y;
            f = __half22float2(*(__half2*)&u3.x); c0 += f.x; c1 += f.y;
            f = __half22float2(*(__half2*)&u3.y); c2 += f.x; c3 += f.y;
        }
        for (; i < e; i++) {
            int p = idxS[i];
            uint2 u = *(const uint2*)(fbase + (size_t)p * NC);
            float2 f;
            f = __half22float2(*(__half2*)&u.x); a0 += f.x; a1 += f.y;
            f = __half22float2(*(__half2*)&u.y); a2 += f.x; a3 += f.y;
        }
        a0 += c0; a1 += c1; a2 += c2; a3 += c3;
        __half* dst = g_acc + ((size_t)(n * DIM + (lane << 2)) * 180 + a) * 180 + r;
        dst[0]              = __float2half_rn(a0);
        dst[AR]             = __float2half_rn(a1);
        dst[2 * AR]         = __float2half_rn(a2);
        dst[3 * (size_t)AR] = __float2half_rn(a3);
    }
}

// ---------------- conv3x3 + BN + ReLU: fp16 mma, double-buffered cp.async pipeline ----------
// 256 threads, 1 angle, 96 cols (grid 2x180x8). W and B double-buffered.
// smem half2: W[2][tap s1088][ci2 s136][co]  B[2][ci2 s312][ar s104][q(half2 of ci pair)]
#define WBUF_H2 9792                    /* per W buffer  */
#define BBUF_H2 2496                    /* per B buffer  */
#define WBUF_B  (WBUF_H2 * 4)
#define BBUF_B  (BBUF_H2 * 4)
#define C3_SMEM (2 * WBUF_B + 2 * BBUF_B + 1024)

template <int OUT_HALF>
__global__ __launch_bounds__(256) void conv3h_kernel(
    const __half* __restrict__ src, const __half2* __restrict__ wh,
    const float* __restrict__ b,  const float* __restrict__ g,
    const float* __restrict__ be, const float* __restrict__ m,
    const float* __restrict__ v,  void* __restrict__ dstv)
{
    extern __shared__ __align__(16) char smraw[];
    char*  Wb  = smraw;                       // 2 W buffers
    char*  Bb  = smraw + 2 * WBUF_B;          // 2 B buffers
    float* sS  = (float*)(smraw + 2 * WBUF_B + 2 * BBUF_B);
    float* tS  = sS + 128;
    uint32_t wsm = smem_u32(Wb);

    int t  = threadIdx.x;
    int r0 = blockIdx.x * 84;
    int a  = blockIdx.y;
    int n  = blockIdx.z;
    if (t < 128) {
        float sc = g[t] * rsqrtf(v[t] + 1e-5f);
        sS[t] = sc;
        tS[t] = (b[t] - m[t]) * sc + be[t];
    }

    int lane = t & 31, warp = t >> 5;
    int grp = lane >> 2, q4 = lane & 3;
    int co_base = warp * 16;
    int wci2 = t >> 5, wco4 = t & 31;    // W cp.async mapping

    float acc[12][4];
#pragma unroll
    for (int j = 0; j < 12; j++)
#pragma unroll
        for (int i = 0; i < 4; i++) acc[j][i] = 0.f;

    const __half* srcn = src + (size_t)n * DIM * AR;

    // ---- helpers as lambdas ----
    auto cpW = [&](int chunk, int buf) {
        uint32_t base = wsm + buf * WBUF_B;
#pragma unroll
        for (int i = 0; i < 9; i++) {
            uint32_t d = base + (uint32_t)(i * 4352 + wci2 * 544 + wco4 * 16);
            const __half2* s = wh + ((size_t)i * 64 + chunk * 8 + wci2) * 128 + wco4 * 4;
            CP_ASYNC16(d, s);
        }
        CP_COMMIT();
    };
    uint32_t pv[10];
    auto ldB = [&](int chunk) {
        int c0 = chunk * 16;
#pragma unroll
        for (int i = 0; i < 10; i++) {
            int e = t + i * 256;
            pv[i] = 0u;
            if (e < 2352) {
                int ci2 = e / 294;
                int rem = e - ci2 * 294;
                int ar  = rem / 98;
                int qq  = rem - ar * 98;
                int as  = a + ar - 1;
                int rs  = r0 - 1 + qq;
                if ((unsigned)as < 180u && (unsigned)rs < 180u) {
                    const __half* p = srcn + ((size_t)(c0 + 2 * ci2) * 180 + as) * 180 + rs;
                    unsigned short lo = *(const unsigned short*)p;
                    unsigned short hi = *(const unsigned short*)(p + AR);
                    pv[i] = (uint32_t)lo | ((uint32_t)hi << 16);
                }
            }
        }
    };
    auto stB = [&](int buf) {
        uint32_t* Bw = (uint32_t*)(Bb + buf * BBUF_B);
#pragma unroll
        for (int i = 0; i < 10; i++) {
            int e = t + i * 256;
            if (e < 2352) {
                int ci2 = e / 294;
                int rem = e - ci2 * 294;
                int ar  = rem / 98;
                int qq  = rem - ar * 98;
                Bw[ci2 * 312 + ar * 104 + qq] = pv[i];
            }
        }
    };

    // ---- prologue: chunk 0 ----
    cpW(0, 0);
    ldB(0);
    CP_WAIT0();
    stB(0);
    __syncthreads();

#pragma unroll 1
    for (int c = 0; c < 8; c++) {
        int buf = c & 1;
        if (c < 7) { cpW(c + 1, buf ^ 1); ldB(c + 1); }

        const __half2* Wh2 = (const __half2*)(Wb + buf * WBUF_B);
        const __half2* Bh2 = (const __half2*)(Bb + buf * BBUF_B);
#pragma unroll
        for (int tap = 0; tap < 9; tap++) {
            int ky = tap / 3, kx = tap - 3 * (tap / 3);
            const __half2* wA = Wh2 + tap * 1088;
            unsigned a0r = *(const unsigned*)(wA + q4 * 136 + co_base + grp);
            unsigned a1r = *(const unsigned*)(wA + q4 * 136 + co_base + grp + 8);
            unsigned a2r = *(const unsigned*)(wA + (q4 + 4) * 136 + co_base + grp);
            unsigned a3r = *(const unsigned*)(wA + (q4 + 4) * 136 + co_base + grp + 8);
            const __half2* bB = Bh2 + ky * 104 + kx + grp;
#pragma unroll
            for (int jn = 0; jn < 12; jn++) {
                unsigned b0r = *(const unsigned*)(bB + q4 * 312 + jn * 8);
                unsigned b1r = *(const unsigned*)(bB + (q4 + 4) * 312 + jn * 8);
                asm volatile(
                    "mma.sync.aligned.m16n8k16.row.col.f32.f16.f16.f32 "
                    "{%0,%1,%2,%3}, {%4,%5,%6,%7}, {%8,%9}, {%0,%1,%2,%3};"
                    : "+f"(acc[jn][0]), "+f"(acc[jn][1]),
                      "+f"(acc[jn][2]), "+f"(acc[jn][3])
                    : "r"(a0r), "r"(a1r), "r"(a2r), "r"(a3r),
                      "r"(b0r), "r"(b1r));
            }
        }

        if (c < 7) { CP_WAIT0(); stB(buf ^ 1); }
        __syncthreads();
    }

    // ---- epilogue: BN + ReLU ----
    int co0 = co_base + grp;
    int co1 = co0 + 8;
    float sc0 = sS[co0], tt0 = tS[co0];
    float sc1 = sS[co1], tt1 = tS[co1];
    size_t i0 = ((size_t)(n * DIM + co0) * 180 + a) * 180 + r0 + q4 * 2;
    size_t i1 = ((size_t)(n * DIM + co1) * 180 + a) * 180 + r0 + q4 * 2;
    if (OUT_HALF) {
        __half* dst = (__half*)dstv;
#pragma unroll
        for (int jn = 0; jn < 12; jn++) {
            float x0 = fmaxf(acc[jn][0] * sc0 + tt0, 0.f);
            float x1 = fmaxf(acc[jn][1] * sc0 + tt0, 0.f);
            float x2 = fmaxf(acc[jn][2] * sc1 + tt1, 0.f);
            float x3 = fmaxf(acc[jn][3] * sc1 + tt1, 0.f);
            *(__half2*)(dst + i0 + jn * 8) = __floats2half2_rn(x0, x1);
            *(__half2*)(dst + i1 + jn * 8) = __floats2half2_rn(x2, x3);
        }
    } else {
        float* dst = (float*)dstv;
#pragma unroll
        for (int jn = 0; jn < 12; jn++) {
            float2 o0, o1;
            o0.x = fmaxf(acc[jn][0] * sc0 + tt0, 0.f);
            o0.y = fmaxf(acc[jn][1] * sc0 + tt0, 0.f);
            o1.x = fmaxf(acc[jn][2] * sc1 + tt1, 0.f);
            o1.y = fmaxf(acc[jn][3] * sc1 + tt1, 0.f);
            *(float2*)(dst + i0 + jn * 8) = o0;
            *(float2*)(dst + i1 + jn * 8) = o1;
        }
    }
}

// ---------------- launch ----------------
extern "C" void kernel_launch(void* const* d_in, const int* in_sizes, int n_in,
                              void* d_out, int out_size) {
    const float* x   = (const float*)d_in[0];
    const float* w1  = (const float*)d_in[1];
    const float* b1  = (const float*)d_in[2];
    const float* g1  = (const float*)d_in[3];
    const float* be1 = (const float*)d_in[4];
    const float* m1  = (const float*)d_in[5];
    const float* v1  = (const float*)d_in[6];
    const float* w2  = (const float*)d_in[7];
    const float* b2  = (const float*)d_in[8];
    const float* g2  = (const float*)d_in[9];
    const float* be2 = (const float*)d_in[10];
    const float* m2  = (const float*)d_in[11];
    const float* v2  = (const float*)d_in[12];
    const float* w3  = (const float*)d_in[13];
    const float* b3  = (const float*)d_in[14];
    const float* g3  = (const float*)d_in[15];
    const float* be3 = (const float*)d_in[16];
    const float* m3  = (const float*)d_in[17];
    const float* v3  = (const float*)d_in[18];
    float* out = (float*)d_out;

    void *p_w2h, *p_w3h, *p_acc, *p_y2;
    cudaGetSymbolAddress(&p_w2h, g_w2h);
    cudaGetSymbolAddress(&p_w3h, g_w3h);
    cudaGetSymbolAddress(&p_acc, g_acc);
    cudaGetSymbolAddress(&p_y2,  g_y2);

    cudaFuncSetAttribute(conv3h_kernel<0>, cudaFuncAttributeMaxDynamicSharedMemorySize, C3_SMEM);
    cudaFuncSetAttribute(conv3h_kernel<1>, cudaFuncAttributeMaxDynamicSharedMemorySize, C3_SMEM);

    seg_kernel<<<dim3(A_ANG, HW / 256), 256>>>();
    conv1_kernel<<<(Nn * HW) / 64, 256>>>(x, w1, b1, g1, be1, m1, v1);
    csr_kernel<<<A_ANG, 128>>>();
    dhtg_kernel<<<dim3(A_ANG, Nn / 2), 256>>>();
    wpreph_kernel<<<(9 * 64 * 128 + 255) / 256, 256>>>(w2, (__half2*)p_w2h);
    wpreph_kernel<<<(9 * 64 * 128 + 255) / 256, 256>>>(w3, (__half2*)p_w3h);
    conv3h_kernel<1><<<dim3(2, A_ANG, Nn), 256, C3_SMEM>>>(
        (const __half*)p_acc, (const __half2*)p_w2h, b2, g2, be2, m2, v2, p_y2);
    conv3h_kernel<0><<<dim3(2, A_ANG, Nn), 256, C3_SMEM>>>(
        (const __half*)p_y2, (const __half2*)p_w3h, b3, g3, be3, m3, v3, out);
}

// round 11
// speedup vs baseline: 1.2191x; 1.0172x over previous
#include <cuda_runtime.h>
#include <cuda_fp16.h>
#include <cuda_bf16.h>
#include <math.h>
#include <stdint.h>

#define A_ANG 180
#define R_RHO 180
#define AR    32400
#define Hh    128
#define Ww    128
#define HW    16384
#define Nn    8
#define CI1   256
#define DIM   128
#define NC    1024      /* Nn*DIM */
#define CSTRIDE 17664   /* padded CSR row: >= 16384 + 180*7, mult of 8 */

// ---------------- static device scratch ----------------
__device__ unsigned char  g_seg[A_ANG * HW];
__device__ __half         g_ft[(size_t)(HW + 8) * NC];     // conv1 out + zero pad row (p=HW)
__device__ __half         g_acc[(size_t)Nn * DIM * AR];    // DHT out, NCHW, fp16
__device__ __half         g_y2 [(size_t)Nn * DIM * AR];    // conv2 out, fp16
__device__ __half2        g_w1h[128 * 128];                // conv1 weights [ci2][co]
__device__ __half2        g_w2h[9 * 64 * 128];             // conv3 weights [tap][ci2][co]
__device__ __half2        g_w3h[9 * 64 * 128];
__device__ unsigned short g_csr_idx[(size_t)A_ANG * CSTRIDE];
__device__ int            g_csr_ptr[A_ANG * 181];

__device__ __forceinline__ uint32_t smem_u32(const void* p) {
    uint32_t a;
    asm("{ .reg .u64 t; cvta.to.shared.u64 t, %1; cvt.u32.u64 %0, t; }" : "=r"(a) : "l"(p));
    return a;
}
#define CP_ASYNC16(dst_u32, src_ptr) \
    asm volatile("cp.async.ca.shared.global [%0], [%1], 16;" :: "r"(dst_u32), "l"(src_ptr))
#define CP_COMMIT()  asm volatile("cp.async.commit_group;")
#define CP_WAIT0()   asm volatile("cp.async.wait_group 0;" ::: "memory")

// ---------------- seg table: fp64, bit-matches numpy binning ----------------
__global__ void seg_kernel() {
    int a = blockIdx.x;
    int p = blockIdx.y * 256 + threadIdx.x;
    double irho = (double)((int)(sqrt((double)(Hh * Hh + Ww * Ww)) + 1.0)) / (double)(R_RHO - 1);
    double theta = (double)a * (3.141592653589793 / (double)A_ANG);
    double tc = cos(theta) / irho;
    double ts = sin(theta) / irho;
    int y = p >> 7, x = p & (Ww - 1);
    double val = __dadd_rn(__dmul_rn(tc, (double)(x - Ww / 2)),
                           __dmul_rn(ts, (double)(y - Hh / 2)));
    long long r = (long long)rint(val) + R_RHO / 2;
    if (r < 0) r = 0;
    if (r > R_RHO - 1) r = R_RHO - 1;
    g_seg[a * HW + p] = (unsigned char)r;
}

// ---------------- CSR build: bins padded to multiples of 8 (sentinel = HW) ----------------
__global__ __launch_bounds__(128) void csr_kernel() {
    __shared__ unsigned short hist[128][180];
    __shared__ int off[181];
    int a = blockIdx.x, t = threadIdx.x;

    for (int i = t; i < CSTRIDE; i += 128)
        g_csr_idx[(size_t)a * CSTRIDE + i] = (unsigned short)HW;   // pad -> zero row

    for (int r = 0; r < 180; r++) hist[t][r] = 0;
    const unsigned char* segrow = g_seg + a * HW + t * 128;
    for (int x = 0; x < 128; x++) hist[t][segrow[x]]++;
    __syncthreads();

    for (int r = t; r < 180; r += 128) {
        int run = 0;
        for (int q = 0; q < 128; q++) {
            int tmp = hist[q][r];
            hist[q][r] = (unsigned short)run;
            run += tmp;
        }
        off[r] = run;
    }
    __syncthreads();
    if (t == 0) {
        int run = 0;
        for (int r = 0; r < 180; r++) {
            int tot = off[r];
            off[r] = run;
            run += (tot + 7) & ~7;       // pad each bin to multiple of 8
        }
        off[180] = run;
    }
    __syncthreads();

    unsigned short* myh = hist[t];
    for (int x = 0; x < 128; x++) {
        int r = segrow[x];
        int pos = off[r] + myh[r];
        myh[r]++;
        g_csr_idx[(size_t)a * CSTRIDE + pos] = (unsigned short)(t * 128 + x);
    }
    for (int i = t; i < 181; i += 128) g_csr_ptr[a * 181 + i] = off[i];
}

// ---------------- weight preps ----------------
__global__ void wprep1_kernel(const float* __restrict__ w, __half2* __restrict__ wh) {
    int e = blockIdx.x * 256 + threadIdx.x;
    if (e < 128 * 128) {
        int ci2 = e >> 7;
        int co  = e & 127;
        wh[e] = __floats2half2_rn(w[co * CI1 + 2 * ci2], w[co * CI1 + 2 * ci2 + 1]);
    }
}
__global__ void wpreph_kernel(const float* __restrict__ w, __half2* __restrict__ wh) {
    int e = blockIdx.x * 256 + threadIdx.x;
    if (e < 9 * 64 * 128) {
        int tap = e >> 13;
        int ci2 = (e >> 7) & 63;
        int co  = e & 127;
        float lo = w[co * 1152 + (2 * ci2) * 9 + tap];
        float hi = w[co * 1152 + (2 * ci2 + 1) * 9 + tap];
        wh[e] = __floats2half2_rn(lo, hi);
    }
}

// ---------------- conv1: 1x1 conv + BN + ReLU via fp16 mma (128co x 64px, K=256) ----------
__global__ __launch_bounds__(256) void conv1h_kernel(
    const float* __restrict__ x, const __half2* __restrict__ wh,
    const float* __restrict__ b, const float* __restrict__ g,
    const float* __restrict__ be, const float* __restrict__ m,
    const float* __restrict__ v)
{
    __shared__ __half2 W1s[8 * 136];
    __shared__ __half2 Bs[8 * 136];
    __shared__ float sS[128], tS[128];
    int t = threadIdx.x;
    int px0 = blockIdx.x * 64;
    int n   = blockIdx.y;
    if (t < 128) {
        float sc = g[t] * rsqrtf(v[t] + 1e-5f);
        sS[t] = sc;
        tS[t] = (b[t] - m[t]) * sc + be[t];
    }
    int lane = t & 31, warp = t >> 5;
    int grp = lane >> 2, q4 = lane & 3;
    int co_base = warp * 16;

    float acc[8][4];
#pragma unroll
    for (int j = 0; j < 8; j++)
#pragma unroll
        for (int i = 0; i < 4; i++) acc[j][i] = 0.f;

    const float* xn = x + (size_t)n * CI1 * HW;

#pragma unroll 1
    for (int ch = 0; ch < 16; ch++) {
        int c8 = ch * 8;    // ci2 base
        __syncthreads();
#pragma unroll
        for (int i = 0; i < 4; i++) {
            int e = t + i * 256;
            int ci2 = e >> 7, co = e & 127;
            W1s[ci2 * 136 + co] = wh[(c8 + ci2) * 128 + co];
        }
#pragma unroll
        for (int i = 0; i < 2; i++) {
            int e = t + i * 256;
            int ci2 = e >> 6, p = e & 63;
            float lo = xn[(size_t)(2 * (c8 + ci2)) * HW + px0 + p];
            float hi = xn[(size_t)(2 * (c8 + ci2) + 1) * HW + px0 + p];
            Bs[ci2 * 136 + p] = __floats2half2_rn(lo, hi);
        }
        __syncthreads();

        unsigned a0r = *(const unsigned*)(W1s + q4 * 136 + co_base + grp);
        unsigned a1r = *(const unsigned*)(W1s + q4 * 136 + co_base + grp + 8);
        unsigned a2r = *(const unsigned*)(W1s + (q4 + 4) * 136 + co_base + grp);
        unsigned a3r = *(const unsigned*)(W1s + (q4 + 4) * 136 + co_base + grp + 8);
#pragma unroll
        for (int jn = 0; jn < 8; jn++) {
            unsigned b0r = *(const unsigned*)(Bs + q4 * 136 + jn * 8 + grp);
            unsigned b1r = *(const unsigned*)(Bs + (q4 + 4) * 136 + jn * 8 + grp);
            asm volatile(
                "mma.sync.aligned.m16n8k16.row.col.f32.f16.f16.f32 "
                "{%0,%1,%2,%3}, {%4,%5,%6,%7}, {%8,%9}, {%0,%1,%2,%3};"
                : "+f"(acc[jn][0]), "+f"(acc[jn][1]),
                  "+f"(acc[jn][2]), "+f"(acc[jn][3])
                : "r"(a0r), "r"(a1r), "r"(a2r), "r"(a3r),
                  "r"(b0r), "r"(b1r));
        }
    }

    int co0 = co_base + grp;
    int co1 = co0 + 8;
    float sc0 = sS[co0], tt0 = tS[co0];
    float sc1 = sS[co1], tt1 = tS[co1];
#pragma unroll
    for (int jn = 0; jn < 8; jn++) {
        int p = px0 + jn * 8 + q4 * 2;
        __half* d0 = g_ft + (size_t)p * NC + n * DIM;
        __half* d1 = g_ft + (size_t)(p + 1) * NC + n * DIM;
        d0[co0] = __float2half_rn(fmaxf(acc[jn][0] * sc0 + tt0, 0.f));
        d1[co0] = __float2half_rn(fmaxf(acc[jn][1] * sc0 + tt0, 0.f));
        d0[co1] = __float2half_rn(fmaxf(acc[jn][2] * sc1 + tt1, 0.f));
        d1[co1] = __float2half_rn(fmaxf(acc[jn][3] * sc1 + tt1, 0.f));
    }
}

// ---------------- DHT gather: block (a, n); 8 warps, uniform gmem idx, no idx smem --------
__global__ __launch_bounds__(256) void dhtg_kernel() {
    __shared__ int ptrS[181];
    int a = blockIdx.x, n = blockIdx.y, t = threadIdx.x;
    for (int i = t; i < 181; i += 256) ptrS[i] = g_csr_ptr[a * 181 + i];
    __syncthreads();

    int w = t >> 5, lane = t & 31;
    int total = ptrS[180];
    int th0 = (w * total) >> 3;
    int th1 = ((w + 1) * total) >> 3;
    int b0 = 0;
    while (b0 < 180 && ptrS[b0] < th0) b0++;
    int b1;
    if (w == 7) b1 = 180;
    else { b1 = 0; while (b1 < 180 && ptrS[b1] < th1) b1++; }

    const __half* fbase = g_ft + n * DIM + (lane << 2);
    const unsigned short* ibase = g_csr_idx + (size_t)a * CSTRIDE;

    for (int r = b0; r < b1; r++) {
        int s = ptrS[r], e = ptrS[r + 1];     // multiples of 8
        float a0 = 0.f, a1 = 0.f, a2 = 0.f, a3 = 0.f;
        float c0 = 0.f, c1 = 0.f, c2 = 0.f, c3 = 0.f;
        for (int i = s; i < e; i += 8) {
            uint4 I = *(const uint4*)(ibase + i);   // 8 idx, uniform across lanes
            int p0 = I.x & 0xFFFF, p1 = I.x >> 16;
            int p2 = I.y & 0xFFFF, p3 = I.y >> 16;
            int p4 = I.z & 0xFFFF, p5 = I.z >> 16;
            int p6 = I.w & 0xFFFF, p7 = I.w >> 16;
            uint2 u0 = *(const uint2*)(fbase + (size_t)p0 * NC);
            uint2 u1 = *(const uint2*)(fbase + (size_t)p1 * NC);
            uint2 u2 = *(const uint2*)(fbase + (size_t)p2 * NC);
            uint2 u3 = *(const uint2*)(fbase + (size_t)p3 * NC);
            uint2 u4 = *(const uint2*)(fbase + (size_t)p4 * NC);
            uint2 u5 = *(const uint2*)(fbase + (size_t)p5 * NC);
            uint2 u6 = *(const uint2*)(fbase + (size_t)p6 * NC);
            uint2 u7 = *(const uint2*)(fbase + (size_t)p7 * NC);
            float2 f;
            f = __half22float2(*(__half2*)&u0.x); a0 += f.x; a1 += f.y;
            f = __half22float2(*(__half2*)&u0.y); a2 += f.x; a3 += f.y;
            f = __half22float2(*(__half2*)&u1.x); c0 += f.x; c1 += f.y;
            f = __half22float2(*(__half2*)&u1.y); c2 += f.x; c3 += f.y;
            f = __half22float2(*(__half2*)&u2.x); a0 += f.x; a1 += f.y;
            f = __half22float2(*(__half2*)&u2.y); a2 += f.x; a3 += f.y;
            f = __half22float2(*(__half2*)&u3.x); c0 += f.x; c1 += f.y;
            f = __half22float2(*(__half2*)&u3.y); c2 += f.x; c3 += f.y;
            f = __half22float2(*(__half2*)&u4.x); a0 += f.x; a1 += f.y;
            f = __half22float2(*(__half2*)&u4.y); a2 += f.x; a3 += f.y;
            f = __half22float2(*(__half2*)&u5.x); c0 += f.x; c1 += f.y;
            f = __half22float2(*(__half2*)&u5.y); c2 += f.x; c3 += f.y;
            f = __half22float2(*(__half2*)&u6.x); a0 += f.x; a1 += f.y;
            f = __half22float2(*(__half2*)&u6.y); a2 += f.x; a3 += f.y;
            f = __half22float2(*(__half2*)&u7.x); c0 += f.x; c1 += f.y;
            f = __half22float2(*(__half2*)&u7.y); c2 += f.x; c3 += f.y;
        }
        a0 += c0; a1 += c1; a2 += c2; a3 += c3;
        __half* dst = g_acc + ((size_t)(n * DIM + (lane << 2)) * 180 + a) * 180 + r;
        dst[0]              = __float2half_rn(a0);
        dst[AR]             = __float2half_rn(a1);
        dst[2 * AR]         = __float2half_rn(a2);
        dst[3 * (size_t)AR] = __float2half_rn(a3);
    }
}

// ---------------- conv3x3 + BN + ReLU: fp16 mma, double-buffered cp.async (R10-proven) ----
#define WBUF_H2 9792
#define BBUF_H2 2496
#define WBUF_B  (WBUF_H2 * 4)
#define BBUF_B  (BBUF_H2 * 4)
#define C3_SMEM (2 * WBUF_B + 2 * BBUF_B + 1024)

template <int OUT_HALF>
__global__ __launch_bounds__(256) void conv3h_kernel(
    const __half* __restrict__ src, const __half2* __restrict__ wh,
    const float* __restrict__ b,  const float* __restrict__ g,
    const float* __restrict__ be, const float* __restrict__ m,
    const float* __restrict__ v,  void* __restrict__ dstv)
{
    extern __shared__ __align__(16) char smraw[];
    char*  Wb  = smraw;
    char*  Bb  = smraw + 2 * WBUF_B;
    float* sS  = (float*)(smraw + 2 * WBUF_B + 2 * BBUF_B);
    float* tS  = sS + 128;
    uint32_t wsm = smem_u32(Wb);

    int t  = threadIdx.x;
    int r0 = blockIdx.x * 84;
    int a  = blockIdx.y;
    int n  = blockIdx.z;
    if (t < 128) {
        float sc = g[t] * rsqrtf(v[t] + 1e-5f);
        sS[t] = sc;
        tS[t] = (b[t] - m[t]) * sc + be[t];
    }

    int lane = t & 31, warp = t >> 5;
    int grp = lane >> 2, q4 = lane & 3;
    int co_base = warp * 16;
    int wci2 = t >> 5, wco4 = t & 31;

    float acc[12][4];
#pragma unroll
    for (int j = 0; j < 12; j++)
#pragma unroll
        for (int i = 0; i < 4; i++) acc[j][i] = 0.f;

    const __half* srcn = src + (size_t)n * DIM * AR;

    auto cpW = [&](int chunk, int buf) {
        uint32_t base = wsm + buf * WBUF_B;
#pragma unroll
        for (int i = 0; i < 9; i++) {
            uint32_t d = base + (uint32_t)(i * 4352 + wci2 * 544 + wco4 * 16);
            const __half2* s = wh + ((size_t)i * 64 + chunk * 8 + wci2) * 128 + wco4 * 4;
            CP_ASYNC16(d, s);
        }
        CP_COMMIT();
    };
    uint32_t pv[10];
    auto ldB = [&](int chunk) {
        int c0 = chunk * 16;
#pragma unroll
        for (int i = 0; i < 10; i++) {
            int e = t + i * 256;
            pv[i] = 0u;
            if (e < 2352) {
                int ci2 = e / 294;
                int rem = e - ci2 * 294;
                int ar  = rem / 98;
                int qq  = rem - ar * 98;
                int as  = a + ar - 1;
                int rs  = r0 - 1 + qq;
                if ((unsigned)as < 180u && (unsigned)rs < 180u) {
                    const __half* p = srcn + ((size_t)(c0 + 2 * ci2) * 180 + as) * 180 + rs;
                    unsigned short lo = *(const unsigned short*)p;
                    unsigned short hi = *(const unsigned short*)(p + AR);
                    pv[i] = (uint32_t)lo | ((uint32_t)hi << 16);
                }
            }
        }
    };
    auto stB = [&](int buf) {
        uint32_t* Bw = (uint32_t*)(Bb + buf * BBUF_B);
#pragma unroll
        for (int i = 0; i < 10; i++) {
            int e = t + i * 256;
            if (e < 2352) {
                int ci2 = e / 294;
                int rem = e - ci2 * 294;
                int ar  = rem / 98;
                int qq  = rem - ar * 98;
                Bw[ci2 * 312 + ar * 104 + qq] = pv[i];
            }
        }
    };

    cpW(0, 0);
    ldB(0);
    CP_WAIT0();
    stB(0);
    __syncthreads();

#pragma unroll 1
    for (int c = 0; c < 8; c++) {
        int buf = c & 1;
        if (c < 7) { cpW(c + 1, buf ^ 1); ldB(c + 1); }

        const __half2* Wh2 = (const __half2*)(Wb + buf * WBUF_B);
        const __half2* Bh2 = (const __half2*)(Bb + buf * BBUF_B);
#pragma unroll
        for (int tap = 0; tap < 9; tap++) {
            int ky = tap / 3, kx = tap - 3 * (tap / 3);
            const __half2* wA = Wh2 + tap * 1088;
            unsigned a0r = *(const unsigned*)(wA + q4 * 136 + co_base + grp);
            unsigned a1r = *(const unsigned*)(wA + q4 * 136 + co_base + grp + 8);
            unsigned a2r = *(const unsigned*)(wA + (q4 + 4) * 136 + co_base + grp);
            unsigned a3r = *(const unsigned*)(wA + (q4 + 4) * 136 + co_base + grp + 8);
            const __half2* bB = Bh2 + ky * 104 + kx + grp;
#pragma unroll
            for (int jn = 0; jn < 12; jn++) {
                unsigned b0r = *(const unsigned*)(bB + q4 * 312 + jn * 8);
                unsigned b1r = *(const unsigned*)(bB + (q4 + 4) * 312 + jn * 8);
                asm volatile(
                    "mma.sync.aligned.m16n8k16.row.col.f32.f16.f16.f32 "
                    "{%0,%1,%2,%3}, {%4,%5,%6,%7}, {%8,%9}, {%0,%1,%2,%3};"
                    : "+f"(acc[jn][0]), "+f"(acc[jn][1]),
                      "+f"(acc[jn][2]), "+f"(acc[jn][3])
                    : "r"(a0r), "r"(a1r), "r"(a2r), "r"(a3r),
                      "r"(b0r), "r"(b1r));
            }
        }

        if (c < 7) { CP_WAIT0(); stB(buf ^ 1); }
        __syncthreads();
    }

    int co0 = co_base + grp;
    int co1 = co0 + 8;
    float sc0 = sS[co0], tt0 = tS[co0];
    float sc1 = sS[co1], tt1 = tS[co1];
    size_t i0 = ((size_t)(n * DIM + co0) * 180 + a) * 180 + r0 + q4 * 2;
    size_t i1 = ((size_t)(n * DIM + co1) * 180 + a) * 180 + r0 + q4 * 2;
    if (OUT_HALF) {
        __half* dst = (__half*)dstv;
#pragma unroll
        for (int jn = 0; jn < 12; jn++) {
            float x0 = fmaxf(acc[jn][0] * sc0 + tt0, 0.f);
            float x1 = fmaxf(acc[jn][1] * sc0 + tt0, 0.f);
            float x2 = fmaxf(acc[jn][2] * sc1 + tt1, 0.f);
            float x3 = fmaxf(acc[jn][3] * sc1 + tt1, 0.f);
            *(__half2*)(dst + i0 + jn * 8) = __floats2half2_rn(x0, x1);
            *(__half2*)(dst + i1 + jn * 8) = __floats2half2_rn(x2, x3);
        }
    } else {
        float* dst = (float*)dstv;
#pragma unroll
        for (int jn = 0; jn < 12; jn++) {
            float2 o0, o1;
            o0.x = fmaxf(acc[jn][0] * sc0 + tt0, 0.f);
            o0.y = fmaxf(acc[jn][1] * sc0 + tt0, 0.f);
            o1.x = fmaxf(acc[jn][2] * sc1 + tt1, 0.f);
            o1.y = fmaxf(acc[jn][3] * sc1 + tt1, 0.f);
            *(float2*)(dst + i0 + jn * 8) = o0;
            *(float2*)(dst + i1 + jn * 8) = o1;
        }
    }
}

// ---------------- launch ----------------
extern "C" void kernel_launch(void* const* d_in, const int* in_sizes, int n_in,
                              void* d_out, int out_size) {
    const float* x   = (const float*)d_in[0];
    const float* w1  = (const float*)d_in[1];
    const float* b1  = (const float*)d_in[2];
    const float* g1  = (const float*)d_in[3];
    const float* be1 = (const float*)d_in[4];
    const float* m1  = (const float*)d_in[5];
    const float* v1  = (const float*)d_in[6];
    const float* w2  = (const float*)d_in[7];
    const float* b2  = (const float*)d_in[8];
    const float* g2  = (const float*)d_in[9];
    const float* be2 = (const float*)d_in[10];
    const float* m2  = (const float*)d_in[11];
    const float* v2  = (const float*)d_in[12];
    const float* w3  = (const float*)d_in[13];
    const float* b3  = (const float*)d_in[14];
    const float* g3  = (const float*)d_in[15];
    const float* be3 = (const float*)d_in[16];
    const float* m3  = (const float*)d_in[17];
    const float* v3  = (const float*)d_in[18];
    float* out = (float*)d_out;

    void *p_w1h, *p_w2h, *p_w3h, *p_acc, *p_y2;
    cudaGetSymbolAddress(&p_w1h, g_w1h);
    cudaGetSymbolAddress(&p_w2h, g_w2h);
    cudaGetSymbolAddress(&p_w3h, g_w3h);
    cudaGetSymbolAddress(&p_acc, g_acc);
    cudaGetSymbolAddress(&p_y2,  g_y2);

    cudaFuncSetAttribute(conv3h_kernel<0>, cudaFuncAttributeMaxDynamicSharedMemorySize, C3_SMEM);
    cudaFuncSetAttribute(conv3h_kernel<1>, cudaFuncAttributeMaxDynamicSharedMemorySize, C3_SMEM);

    seg_kernel<<<dim3(A_ANG, HW / 256), 256>>>();                       // 0
    csr_kernel<<<A_ANG, 128>>>();                                       // 1
    wprep1_kernel<<<(128 * 128 + 255) / 256, 256>>>(w1, (__half2*)p_w1h); // 2
    conv1h_kernel<<<dim3(HW / 64, Nn), 256>>>(x, (const __half2*)p_w1h,  // 3 (profiled)
                                              b1, g1, be1, m1, v1);
    dhtg_kernel<<<dim3(A_ANG, Nn), 256>>>();                            // 4
    wpreph_kernel<<<(9 * 64 * 128 + 255) / 256, 256>>>(w2, (__half2*)p_w2h);
    wpreph_kernel<<<(9 * 64 * 128 + 255) / 256, 256>>>(w3, (__half2*)p_w3h);
    conv3h_kernel<1><<<dim3(2, A_ANG, Nn), 256, C3_SMEM>>>(
        (const __half*)p_acc, (const __half2*)p_w2h, b2, g2, be2, m2, v2, p_y2);
    conv3h_kernel<0><<<dim3(2, A_ANG, Nn), 256, C3_SMEM>>>(
        (const __half*)p_y2, (const __half2*)p_w3h, b3, g3, be3, m3, v3, out);
}

// round 12
// speedup vs baseline: 1.5844x; 1.2996x over previous
#include <cuda_runtime.h>
#include <cuda_fp16.h>
#include <cuda_bf16.h>
#include <math.h>
#include <stdint.h>

#define A_ANG 180
#define R_RHO 180
#define AR    32400
#define Hh    128
#define Ww    128
#define HW    16384
#define Nn    8
#define CI1   256
#define DIM   128
#define NC    1024      /* Nn*DIM */
#define CSTRIDE 17664   /* padded CSR row: >= 16384 + 180*7, mult of 8 */

// ---------------- static device scratch ----------------
__device__ __half         g_ft[(size_t)(HW + 8) * NC];     // conv1 out + zero pad row (p=HW)
__device__ unsigned char  g_seg[A_ANG * HW];
__device__ __half         g_acc[(size_t)Nn * DIM * AR];    // DHT out, NCHW, fp16
__device__ __half         g_y2 [(size_t)Nn * DIM * AR];    // conv2 out, fp16
__device__ __half2        g_w1h[128 * 128];                // conv1 weights [ci2][co]
__device__ __half2        g_w2h[9 * 64 * 128];             // conv3 weights [tap][ci2][co]
__device__ __half2        g_w3h[9 * 64 * 128];
__device__ unsigned short g_csr_idx[(size_t)A_ANG * CSTRIDE];
__device__ int            g_csr_ptr[A_ANG * 181];

__device__ __forceinline__ uint32_t smem_u32(const void* p) {
    uint32_t a;
    asm("{ .reg .u64 t; cvta.to.shared.u64 t, %1; cvt.u32.u64 %0, t; }" : "=r"(a) : "l"(p));
    return a;
}
#define CP_ASYNC16(dst_u32, src_ptr) \
    asm volatile("cp.async.ca.shared.global [%0], [%1], 16;" :: "r"(dst_u32), "l"(src_ptr))
#define CP_COMMIT()  asm volatile("cp.async.commit_group;")
#define CP_WAIT0()   asm volatile("cp.async.wait_group 0;" ::: "memory")

// ---------------- fused prep: seg table + all weight preps in one launch ----------------
#define SEG_N   (A_ANG * HW)             /* 2949120 */
#define W1_N    (128 * 128)              /* 16384   */
#define WH_N    (9 * 64 * 128)           /* 73728   */
#define PREP_N  (SEG_N + W1_N + 2 * WH_N)

__global__ void prep_kernel(const float* __restrict__ w1,
                            const float* __restrict__ w2,
                            const float* __restrict__ w3) {
    int e = blockIdx.x * 256 + threadIdx.x;
    if (e < SEG_N) {
        int a = e >> 14, p = e & (HW - 1);
        double irho = (double)((int)(sqrt((double)(Hh * Hh + Ww * Ww)) + 1.0)) / (double)(R_RHO - 1);
        double theta = (double)a * (3.141592653589793 / (double)A_ANG);
        double tc = cos(theta) / irho;
        double ts = sin(theta) / irho;
        int y = p >> 7, x = p & (Ww - 1);
        double val = __dadd_rn(__dmul_rn(tc, (double)(x - Ww / 2)),
                               __dmul_rn(ts, (double)(y - Hh / 2)));
        long long r = (long long)rint(val) + R_RHO / 2;   // round-half-even = np.round
        if (r < 0) r = 0;
        if (r > R_RHO - 1) r = R_RHO - 1;
        g_seg[a * HW + p] = (unsigned char)r;
    } else if (e < SEG_N + W1_N) {
        int q = e - SEG_N;
        int ci2 = q >> 7, co = q & 127;
        g_w1h[q] = __floats2half2_rn(w1[co * CI1 + 2 * ci2], w1[co * CI1 + 2 * ci2 + 1]);
    } else if (e < SEG_N + W1_N + 2 * WH_N) {
        int q = e - SEG_N - W1_N;
        const float* w = (q < WH_N) ? w2 : w3;
        __half2* wh    = (q < WH_N) ? g_w2h : g_w3h;
        q = (q < WH_N) ? q : q - WH_N;
        int tap = q >> 13;
        int ci2 = (q >> 7) & 63;
        int co  = q & 127;
        wh[q] = __floats2half2_rn(w[co * 1152 + (2 * ci2) * 9 + tap],
                                  w[co * 1152 + (2 * ci2 + 1) * 9 + tap]);
    }
}

// ---------------- conv1: 1x1 conv + BN + ReLU via fp16 mma (128co x 64px, K=256) ----------
__global__ __launch_bounds__(256) void conv1h_kernel(
    const float* __restrict__ x, const __half2* __restrict__ wh,
    const float* __restrict__ b, const float* __restrict__ g,
    const float* __restrict__ be, const float* __restrict__ m,
    const float* __restrict__ v)
{
    __shared__ __half2 W1s[8 * 136];
    __shared__ __half2 Bs[8 * 136];
    __shared__ float sS[128], tS[128];
    int t = threadIdx.x;
    int px0 = blockIdx.x * 64;
    int n   = blockIdx.y;
    if (t < 128) {
        float sc = g[t] * rsqrtf(v[t] + 1e-5f);
        sS[t] = sc;
        tS[t] = (b[t] - m[t]) * sc + be[t];
    }
    int lane = t & 31, warp = t >> 5;
    int grp = lane >> 2, q4 = lane & 3;
    int co_base = warp * 16;

    float acc[8][4];
#pragma unroll
    for (int j = 0; j < 8; j++)
#pragma unroll
        for (int i = 0; i < 4; i++) acc[j][i] = 0.f;

    const float* xn = x + (size_t)n * CI1 * HW;

#pragma unroll 1
    for (int ch = 0; ch < 16; ch++) {
        int c8 = ch * 8;
        __syncthreads();
#pragma unroll
        for (int i = 0; i < 4; i++) {
            int e = t + i * 256;
            int ci2 = e >> 7, co = e & 127;
            W1s[ci2 * 136 + co] = wh[(c8 + ci2) * 128 + co];
        }
#pragma unroll
        for (int i = 0; i < 2; i++) {
            int e = t + i * 256;
            int ci2 = e >> 6, p = e & 63;
            float lo = xn[(size_t)(2 * (c8 + ci2)) * HW + px0 + p];
            float hi = xn[(size_t)(2 * (c8 + ci2) + 1) * HW + px0 + p];
            Bs[ci2 * 136 + p] = __floats2half2_rn(lo, hi);
        }
        __syncthreads();

        unsigned a0r = *(const unsigned*)(W1s + q4 * 136 + co_base + grp);
        unsigned a1r = *(const unsigned*)(W1s + q4 * 136 + co_base + grp + 8);
        unsigned a2r = *(const unsigned*)(W1s + (q4 + 4) * 136 + co_base + grp);
        unsigned a3r = *(const unsigned*)(W1s + (q4 + 4) * 136 + co_base + grp + 8);
#pragma unroll
        for (int jn = 0; jn < 8; jn++) {
            unsigned b0r = *(const unsigned*)(Bs + q4 * 136 + jn * 8 + grp);
            unsigned b1r = *(const unsigned*)(Bs + (q4 + 4) * 136 + jn * 8 + grp);
            asm volatile(
                "mma.sync.aligned.m16n8k16.row.col.f32.f16.f16.f32 "
                "{%0,%1,%2,%3}, {%4,%5,%6,%7}, {%8,%9}, {%0,%1,%2,%3};"
                : "+f"(acc[jn][0]), "+f"(acc[jn][1]),
                  "+f"(acc[jn][2]), "+f"(acc[jn][3])
                : "r"(a0r), "r"(a1r), "r"(a2r), "r"(a3r),
                  "r"(b0r), "r"(b1r));
        }
    }

    int co0 = co_base + grp;
    int co1 = co0 + 8;
    float sc0 = sS[co0], tt0 = tS[co0];
    float sc1 = sS[co1], tt1 = tS[co1];
#pragma unroll
    for (int jn = 0; jn < 8; jn++) {
        int p = px0 + jn * 8 + q4 * 2;
        __half* d0 = g_ft + (size_t)p * NC + n * DIM;
        __half* d1 = g_ft + (size_t)(p + 1) * NC + n * DIM;
        d0[co0] = __float2half_rn(fmaxf(acc[jn][0] * sc0 + tt0, 0.f));
        d1[co0] = __float2half_rn(fmaxf(acc[jn][1] * sc0 + tt0, 0.f));
        d0[co1] = __float2half_rn(fmaxf(acc[jn][2] * sc1 + tt1, 0.f));
        d1[co1] = __float2half_rn(fmaxf(acc[jn][3] * sc1 + tt1, 0.f));
    }
}

// ---------------- CSR build: bins padded to multiples of 8 (sentinel = HW) ----------------
__global__ __launch_bounds__(128) void csr_kernel() {
    __shared__ unsigned short hist[128][180];
    __shared__ int off[181];
    int a = blockIdx.x, t = threadIdx.x;

    for (int i = t; i < CSTRIDE; i += 128)
        g_csr_idx[(size_t)a * CSTRIDE + i] = (unsigned short)HW;   // pad -> zero row

    for (int r = 0; r < 180; r++) hist[t][r] = 0;
    const unsigned char* segrow = g_seg + a * HW + t * 128;
    for (int x = 0; x < 128; x++) hist[t][segrow[x]]++;
    __syncthreads();

    for (int r = t; r < 180; r += 128) {
        int run = 0;
        for (int q = 0; q < 128; q++) {
            int tmp = hist[q][r];
            hist[q][r] = (unsigned short)run;
            run += tmp;
        }
        off[r] = run;
    }
    __syncthreads();
    if (t == 0) {
        int run = 0;
        for (int r = 0; r < 180; r++) {
            int tot = off[r];
            off[r] = run;
            run += (tot + 7) & ~7;       // pad each bin to multiple of 8
        }
        off[180] = run;
    }
    __syncthreads();

    unsigned short* myh = hist[t];
    for (int x = 0; x < 128; x++) {
        int r = segrow[x];
        int pos = off[r] + myh[r];
        myh[r]++;
        g_csr_idx[(size_t)a * CSTRIDE + pos] = (unsigned short)(t * 128 + x);
    }
    for (int i = t; i < 181; i += 128) g_csr_ptr[a * 181 + i] = off[i];
}

// ---------------- DHT gather: block (a, n); prefetched uniform idx stream ----------------
__global__ __launch_bounds__(256) void dhtg_kernel() {
    __shared__ int ptrS[181];
    int a = blockIdx.x, n = blockIdx.y, t = threadIdx.x;
    for (int i = t; i < 181; i += 256) ptrS[i] = g_csr_ptr[a * 181 + i];
    __syncthreads();

    int w = t >> 5, lane = t & 31;
    int total = ptrS[180];
    int th0 = (w * total) >> 3;
    int th1 = ((w + 1) * total) >> 3;
    int b0 = 0;
    while (b0 < 180 && ptrS[b0] < th0) b0++;
    int b1;
    if (w == 7) b1 = 180;
    else { b1 = 0; while (b1 < 180 && ptrS[b1] < th1) b1++; }

    const __half* fbase = g_ft + n * DIM + (lane << 2);
    const unsigned short* ibase = g_csr_idx + (size_t)a * CSTRIDE;

    // prefetch pipeline: bins are contiguous, so the stream rolls across bins
    uint4 I = *(const uint4*)(ibase + ptrS[b0]);

    for (int r = b0; r < b1; r++) {
        int s = ptrS[r], e = ptrS[r + 1];     // multiples of 8
        float a0 = 0.f, a1 = 0.f, a2 = 0.f, a3 = 0.f;
        float c0 = 0.f, c1 = 0.f, c2 = 0.f, c3 = 0.f;
        for (int i = s; i < e; i += 8) {
            uint4 In = *(const uint4*)(ibase + i + 8);   // next group (pad-safe)
            int p0 = I.x & 0xFFFF, p1 = I.x >> 16;
            int p2 = I.y & 0xFFFF, p3 = I.y >> 16;
            int p4 = I.z & 0xFFFF, p5 = I.z >> 16;
            int p6 = I.w & 0xFFFF, p7 = I.w >> 16;
            uint2 u0 = *(const uint2*)(fbase + (size_t)p0 * NC);
            uint2 u1 = *(const uint2*)(fbase + (size_t)p1 * NC);
            uint2 u2 = *(const uint2*)(fbase + (size_t)p2 * NC);
            uint2 u3 = *(const uint2*)(fbase + (size_t)p3 * NC);
            uint2 u4 = *(const uint2*)(fbase + (size_t)p4 * NC);
            uint2 u5 = *(const uint2*)(fbase + (size_t)p5 * NC);
            uint2 u6 = *(const uint2*)(fbase + (size_t)p6 * NC);
            uint2 u7 = *(const uint2*)(fbase + (size_t)p7 * NC);
            float2 f;
            f = __half22float2(*(__half2*)&u0.x); a0 += f.x; a1 += f.y;
            f = __half22float2(*(__half2*)&u0.y); a2 += f.x; a3 += f.y;
            f = __half22float2(*(__half2*)&u1.x); c0 += f.x; c1 += f.y;
            f = __half22float2(*(__half2*)&u1.y); c2 += f.x; c3 += f.y;
            f = __half22float2(*(__half2*)&u2.x); a0 += f.x; a1 += f.y;
            f = __half22float2(*(__half2*)&u2.y); a2 += f.x; a3 += f.y;
            f = __half22float2(*(__half2*)&u3.x); c0 += f.x; c1 += f.y;
            f = __half22float2(*(__half2*)&u3.y); c2 += f.x; c3 += f.y;
            f = __half22float2(*(__half2*)&u4.x); a0 += f.x; a1 += f.y;
            f = __half22float2(*(__half2*)&u4.y); a2 += f.x; a3 += f.y;
            f = __half22float2(*(__half2*)&u5.x); c0 += f.x; c1 += f.y;
            f = __half22float2(*(__half2*)&u5.y); c2 += f.x; c3 += f.y;
            f = __half22float2(*(__half2*)&u6.x); a0 += f.x; a1 += f.y;
            f = __half22float2(*(__half2*)&u6.y); a2 += f.x; a3 += f.y;
            f = __half22float2(*(__half2*)&u7.x); c0 += f.x; c1 += f.y;
            f = __half22float2(*(__half2*)&u7.y); c2 += f.x; c3 += f.y;
            I = In;
        }
        a0 += c0; a1 += c1; a2 += c2; a3 += c3;
        __half* dst = g_acc + ((size_t)(n * DIM + (lane << 2)) * 180 + a) * 180 + r;
        dst[0]              = __float2half_rn(a0);
        dst[AR]             = __float2half_rn(a1);
        dst[2 * AR]         = __float2half_rn(a2);
        dst[3 * (size_t)AR] = __float2half_rn(a3);
    }
}

// ---------------- conv3x3 + BN + ReLU: fp16 mma, double-buffered cp.async ----------------
#define WBUF_H2 9792
#define BBUF_H2 2496
#define WBUF_B  (WBUF_H2 * 4)
#define BBUF_B  (BBUF_H2 * 4)
#define C3_SMEM (2 * WBUF_B + 2 * BBUF_B + 1024)

template <int OUT_HALF>
__global__ __launch_bounds__(256, 2) void conv3h_kernel(
    const __half* __restrict__ src, const __half2* __restrict__ wh,
    const float* __restrict__ b,  const float* __restrict__ g,
    const float* __restrict__ be, const float* __restrict__ m,
    const float* __restrict__ v,  void* __restrict__ dstv)
{
    extern __shared__ __align__(16) char smraw[];
    char*  Wb  = smraw;
    char*  Bb  = smraw + 2 * WBUF_B;
    float* sS  = (float*)(smraw + 2 * WBUF_B + 2 * BBUF_B);
    float* tS  = sS + 128;
    uint32_t wsm = smem_u32(Wb);

    int t  = threadIdx.x;
    int r0 = blockIdx.x * 84;
    int a  = blockIdx.y;
    int n  = blockIdx.z;
    if (t < 128) {
        float sc = g[t] * rsqrtf(v[t] + 1e-5f);
        sS[t] = sc;
        tS[t] = (b[t] - m[t]) * sc + be[t];
    }

    int lane = t & 31, warp = t >> 5;
    int grp = lane >> 2, q4 = lane & 3;
    int co_base = warp * 16;
    int wci2 = t >> 5, wco4 = t & 31;

    float acc[12][4];
#pragma unroll
    for (int j = 0; j < 12; j++)
#pragma unroll
        for (int i = 0; i < 4; i++) acc[j][i] = 0.f;

    const __half* srcn = src + (size_t)n * DIM * AR;

    auto cpW = [&](int chunk, int buf) {
        uint32_t base = wsm + buf * WBUF_B;
#pragma unroll
        for (int i = 0; i < 9; i++) {
            uint32_t d = base + (uint32_t)(i * 4352 + wci2 * 544 + wco4 * 16);
            const __half2* s = wh + ((size_t)i * 64 + chunk * 8 + wci2) * 128 + wco4 * 4;
            CP_ASYNC16(d, s);
        }
        CP_COMMIT();
    };
    uint32_t pv[10];
    auto ldB = [&](int chunk) {
        int c0 = chunk * 16;
#pragma unroll
        for (int i = 0; i < 10; i++) {
            int e = t + i * 256;
            pv[i] = 0u;
            if (e < 2352) {
                int ci2 = e / 294;
                int rem = e - ci2 * 294;
                int ar  = rem / 98;
                int qq  = rem - ar * 98;
                int as  = a + ar - 1;
                int rs  = r0 - 1 + qq;
                if ((unsigned)as < 180u && (unsigned)rs < 180u) {
                    const __half* p = srcn + ((size_t)(c0 + 2 * ci2) * 180 + as) * 180 + rs;
                    unsigned short lo = *(const unsigned short*)p;
                    unsigned short hi = *(const unsigned short*)(p + AR);
                    pv[i] = (uint32_t)lo | ((uint32_t)hi << 16);
                }
            }
        }
    };
    auto stB = [&](int buf) {
        uint32_t* Bw = (uint32_t*)(Bb + buf * BBUF_B);
#pragma unroll
        for (int i = 0; i < 10; i++) {
            int e = t + i * 256;
            if (e < 2352) {
                int ci2 = e / 294;
                int rem = e - ci2 * 294;
                int ar  = rem / 98;
                int qq  = rem - ar * 98;
                Bw[ci2 * 312 + ar * 104 + qq] = pv[i];
            }
        }
    };

    cpW(0, 0);
    ldB(0);
    CP_WAIT0();
    stB(0);
    __syncthreads();

#pragma unroll 1
    for (int c = 0; c < 8; c++) {
        int buf = c & 1;
        if (c < 7) { cpW(c + 1, buf ^ 1); ldB(c + 1); }

        const __half2* Wh2 = (const __half2*)(Wb + buf * WBUF_B);
        const __half2* Bh2 = (const __half2*)(Bb + buf * BBUF_B);
#pragma unroll
        for (int tap = 0; tap < 9; tap++) {
            int ky = tap / 3, kx = tap - 3 * (tap / 3);
            const __half2* wA = Wh2 + tap * 1088;
            unsigned a0r = *(const unsigned*)(wA + q4 * 136 + co_base + grp);
            unsigned a1r = *(const unsigned*)(wA + q4 * 136 + co_base + grp + 8);
            unsigned a2r = *(const unsigned*)(wA + (q4 + 4) * 136 + co_base + grp);
            unsigned a3r = *(const unsigned*)(wA + (q4 + 4) * 136 + co_base + grp + 8);
            const __half2* bB = Bh2 + ky * 104 + kx + grp;
#pragma unroll
            for (int jn = 0; jn < 12; jn++) {
                unsigned b0r = *(const unsigned*)(bB + q4 * 312 + jn * 8);
                unsigned b1r = *(const unsigned*)(bB + (q4 + 4) * 312 + jn * 8);
                asm volatile(
                    "mma.sync.aligned.m16n8k16.row.col.f32.f16.f16.f32 "
                    "{%0,%1,%2,%3}, {%4,%5,%6,%7}, {%8,%9}, {%0,%1,%2,%3};"
                    : "+f"(acc[jn][0]), "+f"(acc[jn][1]),
                      "+f"(acc[jn][2]), "+f"(acc[jn][3])
                    : "r"(a0r), "r"(a1r), "r"(a2r), "r"(a3r),
                      "r"(b0r), "r"(b1r));
            }
        }

        if (c < 7) { CP_WAIT0(); stB(buf ^ 1); }
        __syncthreads();
    }

    int co0 = co_base + grp;
    int co1 = co0 + 8;
    float sc0 = sS[co0], tt0 = tS[co0];
    float sc1 = sS[co1], tt1 = tS[co1];
    size_t i0 = ((size_t)(n * DIM + co0) * 180 + a) * 180 + r0 + q4 * 2;
    size_t i1 = ((size_t)(n * DIM + co1) * 180 + a) * 180 + r0 + q4 * 2;
    if (OUT_HALF) {
        __half* dst = (__half*)dstv;
#pragma unroll
        for (int jn = 0; jn < 12; jn++) {
            float x0 = fmaxf(acc[jn][0] * sc0 + tt0, 0.f);
            float x1 = fmaxf(acc[jn][1] * sc0 + tt0, 0.f);
            float x2 = fmaxf(acc[jn][2] * sc1 + tt1, 0.f);
            float x3 = fmaxf(acc[jn][3] * sc1 + tt1, 0.f);
            *(__half2*)(dst + i0 + jn * 8) = __floats2half2_rn(x0, x1);
            *(__half2*)(dst + i1 + jn * 8) = __floats2half2_rn(x2, x3);
        }
    } else {
        float* dst = (float*)dstv;
#pragma unroll
        for (int jn = 0; jn < 12; jn++) {
            float2 o0, o1;
            o0.x = fmaxf(acc[jn][0] * sc0 + tt0, 0.f);
            o0.y = fmaxf(acc[jn][1] * sc0 + tt0, 0.f);
            o1.x = fmaxf(acc[jn][2] * sc1 + tt1, 0.f);
            o1.y = fmaxf(acc[jn][3] * sc1 + tt1, 0.f);
            *(float2*)(dst + i0 + jn * 8) = o0;
            *(float2*)(dst + i1 + jn * 8) = o1;
        }
    }
}

// ---------------- launch ----------------
extern "C" void kernel_launch(void* const* d_in, const int* in_sizes, int n_in,
                              void* d_out, int out_size) {
    const float* x   = (const float*)d_in[0];
    const float* w1  = (const float*)d_in[1];
    const float* b1  = (const float*)d_in[2];
    const float* g1  = (const float*)d_in[3];
    const float* be1 = (const float*)d_in[4];
    const float* m1  = (const float*)d_in[5];
    const float* v1  = (const float*)d_in[6];
    const float* w2  = (const float*)d_in[7];
    const float* b2  = (const float*)d_in[8];
    const float* g2  = (const float*)d_in[9];
    const float* be2 = (const float*)d_in[10];
    const float* m2  = (const float*)d_in[11];
    const float* v2  = (const float*)d_in[12];
    const float* w3  = (const float*)d_in[13];
    const float* b3  = (const float*)d_in[14];
    const float* g3  = (const float*)d_in[15];
    const float* be3 = (const float*)d_in[16];
    const float* m3  = (const float*)d_in[17];
    const float* v3  = (const float*)d_in[18];
    float* out = (float*)d_out;

    void *p_w1h, *p_w2h, *p_w3h, *p_acc, *p_y2;
    cudaGetSymbolAddress(&p_w1h, g_w1h);
    cudaGetSymbolAddress(&p_w2h, g_w2h);
    cudaGetSymbolAddress(&p_w3h, g_w3h);
    cudaGetSymbolAddress(&p_acc, g_acc);
    cudaGetSymbolAddress(&p_y2,  g_y2);

    cudaFuncSetAttribute(conv3h_kernel<0>, cudaFuncAttributeMaxDynamicSharedMemorySize, C3_SMEM);
    cudaFuncSetAttribute(conv3h_kernel<1>, cudaFuncAttributeMaxDynamicSharedMemorySize, C3_SMEM);

    prep_kernel<<<(PREP_N + 255) / 256, 256>>>(w1, w2, w3);              // 1
    conv1h_kernel<<<dim3(HW / 64, Nn), 256>>>(x, (const __half2*)p_w1h,  // 2
                                              b1, g1, be1, m1, v1);
    csr_kernel<<<A_ANG, 128>>>();                                        // 3
    dhtg_kernel<<<dim3(A_ANG, Nn), 256>>>();                             // 4 (profiled)
    conv3h_kernel<1><<<dim3(2, A_ANG, Nn), 256, C3_SMEM>>>(
        (const __half*)p_acc, (const __half2*)p_w2h, b2, g2, be2, m2, v2, p_y2);
    conv3h_kernel<0><<<dim3(2, A_ANG, Nn), 256, C3_SMEM>>>(
        (const __half*)p_y2, (const __half2*)p_w3h, b3, g3, be3, m3, v3, out);
}

// round 13
// speedup vs baseline: 1.8622x; 1.1754x over previous
#include <cuda_runtime.h>
#include <cuda_fp16.h>
#include <cuda_bf16.h>
#include <math.h>
#include <stdint.h>

#define A_ANG 180
#define R_RHO 180
#define AR    32400
#define Hh    128
#define Ww    128
#define HW    16384
#define Nn    8
#define CI1   256
#define DIM   128
#define NC    1024      /* Nn*DIM */
#define CSTRIDE 17664   /* padded CSR row: >= 16384 + 180*7, mult of 8 */

// ---------------- static device scratch ----------------
__device__ __half         g_ft[(size_t)(HW + 8) * NC];     // conv1 out + zero pad row (p=HW)
__device__ unsigned char  g_seg[A_ANG * HW];
__device__ unsigned       g_acc[(size_t)Nn * 64 * AR];     // DHT out, packed half2 [n][ci2][a][r]
__device__ unsigned       g_y2 [(size_t)Nn * 64 * AR];     // conv2 out, packed half2
__device__ __half2        g_w1h[128 * 128];                // conv1 weights [ci2][co]
__device__ __half2        g_w2h[9 * 64 * 128];             // conv3 weights [tap][ci2][co]
__device__ __half2        g_w3h[9 * 64 * 128];
__device__ unsigned short g_csr_idx[(size_t)A_ANG * CSTRIDE];
__device__ int            g_csr_ptr[A_ANG * 181];

__device__ __forceinline__ uint32_t smem_u32(const void* p) {
    uint32_t a;
    asm("{ .reg .u64 t; cvta.to.shared.u64 t, %1; cvt.u32.u64 %0, t; }" : "=r"(a) : "l"(p));
    return a;
}
#define CP_ASYNC16(dst_u32, src_ptr) \
    asm volatile("cp.async.ca.shared.global [%0], [%1], 16;" :: "r"(dst_u32), "l"(src_ptr))
#define CP_COMMIT()  asm volatile("cp.async.commit_group;")
#define CP_WAIT0()   asm volatile("cp.async.wait_group 0;" ::: "memory")

// ---------------- fused prep: seg table + all weight preps ----------------
#define SEG_N   (A_ANG * HW)
#define W1_N    (128 * 128)
#define WH_N    (9 * 64 * 128)
#define PREP_N  (SEG_N + W1_N + 2 * WH_N)

__global__ void prep_kernel(const float* __restrict__ w1,
                            const float* __restrict__ w2,
                            const float* __restrict__ w3) {
    int e = blockIdx.x * 256 + threadIdx.x;
    if (e < SEG_N) {
        int a = e >> 14, p = e & (HW - 1);
        double irho = (double)((int)(sqrt((double)(Hh * Hh + Ww * Ww)) + 1.0)) / (double)(R_RHO - 1);
        double theta = (double)a * (3.141592653589793 / (double)A_ANG);
        double tc = cos(theta) / irho;
        double ts = sin(theta) / irho;
        int y = p >> 7, x = p & (Ww - 1);
        double val = __dadd_rn(__dmul_rn(tc, (double)(x - Ww / 2)),
                               __dmul_rn(ts, (double)(y - Hh / 2)));
        long long r = (long long)rint(val) + R_RHO / 2;
        if (r < 0) r = 0;
        if (r > R_RHO - 1) r = R_RHO - 1;
        g_seg[a * HW + p] = (unsigned char)r;
    } else if (e < SEG_N + W1_N) {
        int q = e - SEG_N;
        int ci2 = q >> 7, co = q & 127;
        g_w1h[q] = __floats2half2_rn(w1[co * CI1 + 2 * ci2], w1[co * CI1 + 2 * ci2 + 1]);
    } else if (e < SEG_N + W1_N + 2 * WH_N) {
        int q = e - SEG_N - W1_N;
        const float* w = (q < WH_N) ? w2 : w3;
        __half2* wh    = (q < WH_N) ? g_w2h : g_w3h;
        q = (q < WH_N) ? q : q - WH_N;
        int tap = q >> 13;
        int ci2 = (q >> 7) & 63;
        int co  = q & 127;
        wh[q] = __floats2half2_rn(w[co * 1152 + (2 * ci2) * 9 + tap],
                                  w[co * 1152 + (2 * ci2 + 1) * 9 + tap]);
    }
}

// ---------------- conv1: 1x1 conv + BN + ReLU via fp16 mma (HBM-floor, R11-proven) --------
__global__ __launch_bounds__(256) void conv1h_kernel(
    const float* __restrict__ x, const __half2* __restrict__ wh,
    const float* __restrict__ b, const float* __restrict__ g,
    const float* __restrict__ be, const float* __restrict__ m,
    const float* __restrict__ v)
{
    __shared__ __half2 W1s[8 * 136];
    __shared__ __half2 Bs[8 * 136];
    __shared__ float sS[128], tS[128];
    int t = threadIdx.x;
    int px0 = blockIdx.x * 64;
    int n   = blockIdx.y;
    if (t < 128) {
        float sc = g[t] * rsqrtf(v[t] + 1e-5f);
        sS[t] = sc;
        tS[t] = (b[t] - m[t]) * sc + be[t];
    }
    int lane = t & 31, warp = t >> 5;
    int grp = lane >> 2, q4 = lane & 3;
    int co_base = warp * 16;

    float acc[8][4];
#pragma unroll
    for (int j = 0; j < 8; j++)
#pragma unroll
        for (int i = 0; i < 4; i++) acc[j][i] = 0.f;

    const float* xn = x + (size_t)n * CI1 * HW;

#pragma unroll 1
    for (int ch = 0; ch < 16; ch++) {
        int c8 = ch * 8;
        __syncthreads();
#pragma unroll
        for (int i = 0; i < 4; i++) {
            int e = t + i * 256;
            int ci2 = e >> 7, co = e & 127;
            W1s[ci2 * 136 + co] = wh[(c8 + ci2) * 128 + co];
        }
#pragma unroll
        for (int i = 0; i < 2; i++) {
            int e = t + i * 256;
            int ci2 = e >> 6, p = e & 63;
            float lo = xn[(size_t)(2 * (c8 + ci2)) * HW + px0 + p];
            float hi = xn[(size_t)(2 * (c8 + ci2) + 1) * HW + px0 + p];
            Bs[ci2 * 136 + p] = __floats2half2_rn(lo, hi);
        }
        __syncthreads();

        unsigned a0r = *(const unsigned*)(W1s + q4 * 136 + co_base + grp);
        unsigned a1r = *(const unsigned*)(W1s + q4 * 136 + co_base + grp + 8);
        unsigned a2r = *(const unsigned*)(W1s + (q4 + 4) * 136 + co_base + grp);
        unsigned a3r = *(const unsigned*)(W1s + (q4 + 4) * 136 + co_base + grp + 8);
#pragma unroll
        for (int jn = 0; jn < 8; jn++) {
            unsigned b0r = *(const unsigned*)(Bs + q4 * 136 + jn * 8 + grp);
            unsigned b1r = *(const unsigned*)(Bs + (q4 + 4) * 136 + jn * 8 + grp);
            asm volatile(
                "mma.sync.aligned.m16n8k16.row.col.f32.f16.f16.f32 "
                "{%0,%1,%2,%3}, {%4,%5,%6,%7}, {%8,%9}, {%0,%1,%2,%3};"
                : "+f"(acc[jn][0]), "+f"(acc[jn][1]),
                  "+f"(acc[jn][2]), "+f"(acc[jn][3])
                : "r"(a0r), "r"(a1r), "r"(a2r), "r"(a3r),
                  "r"(b0r), "r"(b1r));
        }
    }

    int co0 = co_base + grp;
    int co1 = co0 + 8;
    float sc0 = sS[co0], tt0 = tS[co0];
    float sc1 = sS[co1], tt1 = tS[co1];
#pragma unroll
    for (int jn = 0; jn < 8; jn++) {
        int p = px0 + jn * 8 + q4 * 2;
        __half* d0 = g_ft + (size_t)p * NC + n * DIM;
        __half* d1 = g_ft + (size_t)(p + 1) * NC + n * DIM;
        d0[co0] = __float2half_rn(fmaxf(acc[jn][0] * sc0 + tt0, 0.f));
        d1[co0] = __float2half_rn(fmaxf(acc[jn][1] * sc0 + tt0, 0.f));
        d0[co1] = __float2half_rn(fmaxf(acc[jn][2] * sc1 + tt1, 0.f));
        d1[co1] = __float2half_rn(fmaxf(acc[jn][3] * sc1 + tt1, 0.f));
    }
}

// ---------------- CSR build: bins padded to multiples of 8 (sentinel = HW) ----------------
__global__ __launch_bounds__(128) void csr_kernel() {
    __shared__ unsigned short hist[128][180];
    __shared__ int off[181];
    int a = blockIdx.x, t = threadIdx.x;

    for (int i = t; i < CSTRIDE; i += 128)
        g_csr_idx[(size_t)a * CSTRIDE + i] = (unsigned short)HW;

    for (int r = 0; r < 180; r++) hist[t][r] = 0;
    const unsigned char* segrow = g_seg + a * HW + t * 128;
    for (int x = 0; x < 128; x++) hist[t][segrow[x]]++;
    __syncthreads();

    for (int r = t; r < 180; r += 128) {
        int run = 0;
        for (int q = 0; q < 128; q++) {
            int tmp = hist[q][r];
            hist[q][r] = (unsigned short)run;
            run += tmp;
        }
        off[r] = run;
    }
    __syncthreads();
    if (t == 0) {
        int run = 0;
        for (int r = 0; r < 180; r++) {
            int tot = off[r];
            off[r] = run;
            run += (tot + 7) & ~7;
        }
        off[180] = run;
    }
    __syncthreads();

    unsigned short* myh = hist[t];
    for (int x = 0; x < 128; x++) {
        int r = segrow[x];
        int pos = off[r] + myh[r];
        myh[r]++;
        g_csr_idx[(size_t)a * CSTRIDE + pos] = (unsigned short)(t * 128 + x);
    }
    for (int i = t; i < 181; i += 128) g_csr_ptr[a * 181 + i] = off[i];
}

// ---------------- DHT gather: prefetched idx stream + pairwise HADD2 + packed output ------
__global__ __launch_bounds__(256) void dhtg_kernel() {
    __shared__ int ptrS[181];
    int a = blockIdx.x, n = blockIdx.y, t = threadIdx.x;
    for (int i = t; i < 181; i += 256) ptrS[i] = g_csr_ptr[a * 181 + i];
    __syncthreads();

    int w = t >> 5, lane = t & 31;
    int total = ptrS[180];
    int th0 = (w * total) >> 3;
    int th1 = ((w + 1) * total) >> 3;
    int b0 = 0;
    while (b0 < 180 && ptrS[b0] < th0) b0++;
    int b1;
    if (w == 7) b1 = 180;
    else { b1 = 0; while (b1 < 180 && ptrS[b1] < th1) b1++; }

    const __half* fbase = g_ft + n * DIM + (lane << 2);
    const unsigned short* ibase = g_csr_idx + (size_t)a * CSTRIDE;

    uint4 I = *(const uint4*)(ibase + ptrS[b0]);

    for (int r = b0; r < b1; r++) {
        int s = ptrS[r], e = ptrS[r + 1];     // multiples of 8
        float a0 = 0.f, a1 = 0.f, a2 = 0.f, a3 = 0.f;
        float c0 = 0.f, c1 = 0.f, c2 = 0.f, c3 = 0.f;
        for (int i = s; i < e; i += 8) {
            uint4 In = *(const uint4*)(ibase + i + 8);   // next group (pad-safe)
            int p0 = I.x & 0xFFFF, p1 = I.x >> 16;
            int p2 = I.y & 0xFFFF, p3 = I.y >> 16;
            int p4 = I.z & 0xFFFF, p5 = I.z >> 16;
            int p6 = I.w & 0xFFFF, p7 = I.w >> 16;
            uint2 u0 = *(const uint2*)(fbase + (size_t)p0 * NC);
            uint2 u1 = *(const uint2*)(fbase + (size_t)p1 * NC);
            uint2 u2 = *(const uint2*)(fbase + (size_t)p2 * NC);
            uint2 u3 = *(const uint2*)(fbase + (size_t)p3 * NC);
            uint2 u4 = *(const uint2*)(fbase + (size_t)p4 * NC);
            uint2 u5 = *(const uint2*)(fbase + (size_t)p5 * NC);
            uint2 u6 = *(const uint2*)(fbase + (size_t)p6 * NC);
            uint2 u7 = *(const uint2*)(fbase + (size_t)p7 * NC);
            // level-1: pairwise fp16 adds across pixel pairs (per-channel)
            __half2 h0x = __hadd2(*(__half2*)&u0.x, *(__half2*)&u1.x);
            __half2 h0y = __hadd2(*(__half2*)&u0.y, *(__half2*)&u1.y);
            __half2 h1x = __hadd2(*(__half2*)&u2.x, *(__half2*)&u3.x);
            __half2 h1y = __hadd2(*(__half2*)&u2.y, *(__half2*)&u3.y);
            __half2 h2x = __hadd2(*(__half2*)&u4.x, *(__half2*)&u5.x);
            __half2 h2y = __hadd2(*(__half2*)&u4.y, *(__half2*)&u5.y);
            __half2 h3x = __hadd2(*(__half2*)&u6.x, *(__half2*)&u7.x);
            __half2 h3y = __hadd2(*(__half2*)&u6.y, *(__half2*)&u7.y);
            float2 f;
            f = __half22float2(h0x); a0 += f.x; a1 += f.y;
            f = __half22float2(h0y); a2 += f.x; a3 += f.y;
            f = __half22float2(h1x); c0 += f.x; c1 += f.y;
            f = __half22float2(h1y); c2 += f.x; c3 += f.y;
            f = __half22float2(h2x); a0 += f.x; a1 += f.y;
            f = __half22float2(h2y); a2 += f.x; a3 += f.y;
            f = __half22float2(h3x); c0 += f.x; c1 += f.y;
            f = __half22float2(h3y); c2 += f.x; c3 += f.y;
            I = In;
        }
        a0 += c0; a1 += c1; a2 += c2; a3 += c3;
        // packed output: word = half2(channel 2*ci2, 2*ci2+1); ci2 = lane*2, lane*2+1
        size_t wb = ((size_t)(n * 64 + lane * 2)) * AR + a * 180 + r;
        __half2 o01 = __floats2half2_rn(a0, a1);
        __half2 o23 = __floats2half2_rn(a2, a3);
        g_acc[wb]      = *(unsigned*)&o01;
        g_acc[wb + AR] = *(unsigned*)&o23;
    }
}

// ---------------- conv3x3 + BN + ReLU: fp16 mma, double-buffered, packed input ------------
#define WBUF_H2 9792
#define BBUF_H2 2496
#define WBUF_B  (WBUF_H2 * 4)
#define BBUF_B  (BBUF_H2 * 4)
#define C3_SMEM (2 * WBUF_B + 2 * BBUF_B + 1024)

template <int OUT_HALF>
__global__ __launch_bounds__(256, 2) void conv3h_kernel(
    const unsigned* __restrict__ src, const __half2* __restrict__ wh,
    const float* __restrict__ b,  const float* __restrict__ g,
    const float* __restrict__ be, const float* __restrict__ m,
    const float* __restrict__ v,  void* __restrict__ dstv)
{
    extern __shared__ __align__(16) char smraw[];
    char*  Wb  = smraw;
    char*  Bb  = smraw + 2 * WBUF_B;
    float* sS  = (float*)(smraw + 2 * WBUF_B + 2 * BBUF_B);
    float* tS  = sS + 128;
    uint32_t wsm = smem_u32(Wb);

    int t  = threadIdx.x;
    int r0 = blockIdx.x * 84;
    int a  = blockIdx.y;
    int n  = blockIdx.z;
    if (t < 128) {
        float sc = g[t] * rsqrtf(v[t] + 1e-5f);
        sS[t] = sc;
        tS[t] = (b[t] - m[t]) * sc + be[t];
    }

    int lane = t & 31, warp = t >> 5;
    int grp = lane >> 2, q4 = lane & 3;
    int co_base = warp * 16;
    int wci2 = t >> 5, wco4 = t & 31;

    float acc[12][4];
#pragma unroll
    for (int j = 0; j < 12; j++)
#pragma unroll
        for (int i = 0; i < 4; i++) acc[j][i] = 0.f;

    const unsigned* srcn = src + (size_t)n * 64 * AR;

    auto cpW = [&](int chunk, int buf) {
        uint32_t base = wsm + buf * WBUF_B;
#pragma unroll
        for (int i = 0; i < 9; i++) {
            uint32_t d = base + (uint32_t)(i * 4352 + wci2 * 544 + wco4 * 16);
            const __half2* s = wh + ((size_t)i * 64 + chunk * 8 + wci2) * 128 + wco4 * 4;
            CP_ASYNC16(d, s);
        }
        CP_COMMIT();
    };
    uint32_t pv[10];
    auto ldB = [&](int chunk) {
#pragma unroll
        for (int i = 0; i < 10; i++) {
            int e = t + i * 256;
            pv[i] = 0u;
            if (e < 2352) {
                int ci2 = e / 294;
                int rem = e - ci2 * 294;
                int ar  = rem / 98;
                int qq  = rem - ar * 98;
                int as  = a + ar - 1;
                int rs  = r0 - 1 + qq;
                if ((unsigned)as < 180u && (unsigned)rs < 180u)
                    pv[i] = srcn[((size_t)(chunk * 8 + ci2)) * AR + as * 180 + rs];
            }
        }
    };
    auto stB = [&](int buf) {
        uint32_t* Bw = (uint32_t*)(Bb + buf * BBUF_B);
#pragma unroll
        for (int i = 0; i < 10; i++) {
            int e = t + i * 256;
            if (e < 2352) {
                int ci2 = e / 294;
                int rem = e - ci2 * 294;
                int ar  = rem / 98;
                int qq  = rem - ar * 98;
                Bw[ci2 * 312 + ar * 104 + qq] = pv[i];
            }
        }
    };

    cpW(0, 0);
    ldB(0);
    CP_WAIT0();
    stB(0);
    __syncthreads();

#pragma unroll 1
    for (int c = 0; c < 8; c++) {
        int buf = c & 1;
        if (c < 7) { cpW(c + 1, buf ^ 1); ldB(c + 1); }

        const __half2* Wh2 = (const __half2*)(Wb + buf * WBUF_B);
        const __half2* Bh2 = (const __half2*)(Bb + buf * BBUF_B);
#pragma unroll
        for (int tap = 0; tap < 9; tap++) {
            int ky = tap / 3, kx = tap - 3 * (tap / 3);
            const __half2* wA = Wh2 + tap * 1088;
            unsigned a0r = *(const unsigned*)(wA + q4 * 136 + co_base + grp);
            unsigned a1r = *(const unsigned*)(wA + q4 * 136 + co_base + grp + 8);
            unsigned a2r = *(const unsigned*)(wA + (q4 + 4) * 136 + co_base + grp);
            unsigned a3r = *(const unsigned*)(wA + (q4 + 4) * 136 + co_base + grp + 8);
            const __half2* bB = Bh2 + ky * 104 + kx + grp;
#pragma unroll
            for (int jn = 0; jn < 12; jn++) {
                unsigned b0r = *(const unsigned*)(bB + q4 * 312 + jn * 8);
                unsigned b1r = *(const unsigned*)(bB + (q4 + 4) * 312 + jn * 8);
                asm volatile(
                    "mma.sync.aligned.m16n8k16.row.col.f32.f16.f16.f32 "
                    "{%0,%1,%2,%3}, {%4,%5,%6,%7}, {%8,%9}, {%0,%1,%2,%3};"
                    : "+f"(acc[jn][0]), "+f"(acc[jn][1]),
                      "+f"(acc[jn][2]), "+f"(acc[jn][3])
                    : "r"(a0r), "r"(a1r), "r"(a2r), "r"(a3r),
                      "r"(b0r), "r"(b1r));
            }
        }

        if (c < 7) { CP_WAIT0(); stB(buf ^ 1); }
        __syncthreads();
    }

    int co0 = co_base + grp;
    int co1 = co0 + 8;
    float sc0 = sS[co0], tt0 = tS[co0];
    float sc1 = sS[co1], tt1 = tS[co1];
    if (OUT_HALF) {
        // packed half2 layout [n][ci2][a][r]; half index = 2*word + (co&1)
        __half* dst = (__half*)dstv;
        size_t w0 = ((size_t)(n * 64 + (co0 >> 1))) * AR + a * 180 + r0;
        size_t w1 = ((size_t)(n * 64 + (co1 >> 1))) * AR + a * 180 + r0;
        int par = co0 & 1;   // co1 has same parity (co1 = co0+8)
#pragma unroll
        for (int jn = 0; jn < 12; jn++) {
            int col = q4 * 2 + jn * 8;
            dst[2 * (w0 + col)     + par] = __float2half_rn(fmaxf(acc[jn][0] * sc0 + tt0, 0.f));
            dst[2 * (w0 + col + 1) + par] = __float2half_rn(fmaxf(acc[jn][1] * sc0 + tt0, 0.f));
            dst[2 * (w1 + col)     + par] = __float2half_rn(fmaxf(acc[jn][2] * sc1 + tt1, 0.f));
            dst[2 * (w1 + col + 1) + par] = __float2half_rn(fmaxf(acc[jn][3] * sc1 + tt1, 0.f));
        }
    } else {
        float* dst = (float*)dstv;
        size_t i0 = ((size_t)(n * DIM + co0) * 180 + a) * 180 + r0 + q4 * 2;
        size_t i1 = ((size_t)(n * DIM + co1) * 180 + a) * 180 + r0 + q4 * 2;
#pragma unroll
        for (int jn = 0; jn < 12; jn++) {
            float2 o0, o1;
            o0.x = fmaxf(acc[jn][0] * sc0 + tt0, 0.f);
            o0.y = fmaxf(acc[jn][1] * sc0 + tt0, 0.f);
            o1.x = fmaxf(acc[jn][2] * sc1 + tt1, 0.f);
            o1.y = fmaxf(acc[jn][3] * sc1 + tt1, 0.f);
            *(float2*)(dst + i0 + jn * 8) = o0;
            *(float2*)(dst + i1 + jn * 8) = o1;
        }
    }
}

// ---------------- launch ----------------
extern "C" void kernel_launch(void* const* d_in, const int* in_sizes, int n_in,
                              void* d_out, int out_size) {
    const float* x   = (const float*)d_in[0];
    const float* w1  = (const float*)d_in[1];
    const float* b1  = (const float*)d_in[2];
    const float* g1  = (const float*)d_in[3];
    const float* be1 = (const float*)d_in[4];
    const float* m1  = (const float*)d_in[5];
    const float* v1  = (const float*)d_in[6];
    const float* w2  = (const float*)d_in[7];
    const float* b2  = (const float*)d_in[8];
    const float* g2  = (const float*)d_in[9];
    const float* be2 = (const float*)d_in[10];
    const float* m2  = (const float*)d_in[11];
    const float* v2  = (const float*)d_in[12];
    const float* w3  = (const float*)d_in[13];
    const float* b3  = (const float*)d_in[14];
    const float* g3  = (const float*)d_in[15];
    const float* be3 = (const float*)d_in[16];
    const float* m3  = (const float*)d_in[17];
    const float* v3  = (const float*)d_in[18];
    float* out = (float*)d_out;

    void *p_w1h, *p_w2h, *p_w3h, *p_acc, *p_y2;
    cudaGetSymbolAddress(&p_w1h, g_w1h);
    cudaGetSymbolAddress(&p_w2h, g_w2h);
    cudaGetSymbolAddress(&p_w3h, g_w3h);
    cudaGetSymbolAddress(&p_acc, g_acc);
    cudaGetSymbolAddress(&p_y2,  g_y2);

    cudaFuncSetAttribute(conv3h_kernel<0>, cudaFuncAttributeMaxDynamicSharedMemorySize, C3_SMEM);
    cudaFuncSetAttribute(conv3h_kernel<1>, cudaFuncAttributeMaxDynamicSharedMemorySize, C3_SMEM);

    prep_kernel<<<(PREP_N + 255) / 256, 256>>>(w1, w2, w3);
    conv1h_kernel<<<dim3(HW / 64, Nn), 256>>>(x, (const __half2*)p_w1h,
                                              b1, g1, be1, m1, v1);
    csr_kernel<<<A_ANG, 128>>>();
    dhtg_kernel<<<dim3(A_ANG, Nn), 256>>>();                             // profiled slot
    conv3h_kernel<1><<<dim3(2, A_ANG, Nn), 256, C3_SMEM>>>(
        (const unsigned*)p_acc, (const __half2*)p_w2h, b2, g2, be2, m2, v2, p_y2);
    conv3h_kernel<0><<<dim3(2, A_ANG, Nn), 256, C3_SMEM>>>(
        (const unsigned*)p_y2, (const __half2*)p_w3h, b3, g3, be3, m3, v3, out);
}

// round 14
// speedup vs baseline: 2.3248x; 1.2484x over previous
#include <cuda_runtime.h>
#include <cuda_fp16.h>
#include <cuda_bf16.h>
#include <math.h>
#include <stdint.h>

#define A_ANG 180
#define R_RHO 180
#define AR    32400
#define Hh    128
#define Ww    128
#define HW    16384
#define Nn    8
#define CI1   256
#define DIM   128
#define NC    1024      /* Nn*DIM */
#define CSTRIDE 17664   /* padded CSR row: >= 16384 + 180*7, mult of 8 */

// ---------------- static device scratch ----------------
__device__ __half         g_ft[(size_t)(HW + 8) * NC];     // conv1 out + zero pad row (p=HW)
__device__ unsigned       g_acc[(size_t)Nn * 64 * AR];     // DHT out, packed half2 [n][ci2][a][r]
__device__ unsigned       g_y2 [(size_t)Nn * 64 * AR];     // conv2 out, packed half2
__device__ __half2        g_w1h[128 * 128];                // conv1 weights [ci2][co]
__device__ __half2        g_w2h[9 * 64 * 128];             // conv3 weights [tap][ci2][co]
__device__ __half2        g_w3h[9 * 64 * 128];
__device__ unsigned short g_csr_idx[(size_t)A_ANG * CSTRIDE];
__device__ int            g_csr_ptr[A_ANG * 181];

#define W1_N    (128 * 128)
#define WH_N    (9 * 64 * 128)

__device__ __forceinline__ uint32_t smem_u32(const void* p) {
    uint32_t a;
    asm("{ .reg .u64 t; cvta.to.shared.u64 t, %1; cvt.u32.u64 %0, t; }" : "=r"(a) : "l"(p));
    return a;
}
#define CP_ASYNC16(dst_u32, src_ptr) \
    asm volatile("cp.async.ca.shared.global [%0], [%1], 16;" :: "r"(dst_u32), "l"(src_ptr))
#define CP_COMMIT()  asm volatile("cp.async.commit_group;")
#define CP_WAIT0()   asm volatile("cp.async.wait_group 0;" ::: "memory")

// seg bin for (a, x, y) — fp64, bit-matches numpy round-half-even binning
__device__ __forceinline__ int seg_bin(double tc, double ts, int x, int y) {
    double val = __dadd_rn(__dmul_rn(tc, (double)(x - Ww / 2)),
                           __dmul_rn(ts, (double)(y - Hh / 2)));
    long long r = (long long)rint(val) + R_RHO / 2;
    if (r < 0) r = 0;
    if (r > R_RHO - 1) r = R_RHO - 1;
    return (int)r;
}

// ---------------- CSR build (seg inline, fp64 recompute) + weight prep piggyback ----------
__global__ __launch_bounds__(128) void csr_kernel(const float* __restrict__ w1,
                                                  const float* __restrict__ w2,
                                                  const float* __restrict__ w3) {
    __shared__ unsigned short hist[128][180];
    __shared__ int off[181];
    int a = blockIdx.x, t = threadIdx.x;

    // piggyback: weight prep (grid-stride over all blocks)
    for (int i = a * 128 + t; i < W1_N + 2 * WH_N; i += A_ANG * 128) {
        if (i < W1_N) {
            int ci2 = i >> 7, co = i & 127;
            g_w1h[i] = __floats2half2_rn(w1[co * CI1 + 2 * ci2], w1[co * CI1 + 2 * ci2 + 1]);
        } else {
            int q = i - W1_N;
            const float* w = (q < WH_N) ? w2 : w3;
            __half2* wh    = (q < WH_N) ? g_w2h : g_w3h;
            q = (q < WH_N) ? q : q - WH_N;
            int tap = q >> 13, ci2 = (q >> 7) & 63, co = q & 127;
            wh[q] = __floats2half2_rn(w[co * 1152 + (2 * ci2) * 9 + tap],
                                      w[co * 1152 + (2 * ci2 + 1) * 9 + tap]);
        }
    }

    for (int i = t; i < CSTRIDE; i += 128)
        g_csr_idx[(size_t)a * CSTRIDE + i] = (unsigned short)HW;   // pad -> zero row

    double irho = (double)((int)(sqrt((double)(Hh * Hh + Ww * Ww)) + 1.0)) / (double)(R_RHO - 1);
    double theta = (double)a * (3.141592653589793 / (double)A_ANG);
    double tc = cos(theta) / irho;
    double ts = sin(theta) / irho;
    int y = t;   // thread owns image row y = t

    for (int r = 0; r < 180; r++) hist[t][r] = 0;
    for (int x = 0; x < 128; x++) hist[t][seg_bin(tc, ts, x, y)]++;
    __syncthreads();

    for (int r = t; r < 180; r += 128) {
        int run = 0;
        for (int q = 0; q < 128; q++) {
            int tmp = hist[q][r];
            hist[q][r] = (unsigned short)run;
            run += tmp;
        }
        off[r] = run;
    }
    __syncthreads();
    if (t == 0) {
        int run = 0;
        for (int r = 0; r < 180; r++) {
            int tot = off[r];
            off[r] = run;
            run += (tot + 7) & ~7;       // pad each bin to multiple of 8
        }
        off[180] = run;
    }
    __syncthreads();

    unsigned short* myh = hist[t];
    for (int x = 0; x < 128; x++) {
        int r = seg_bin(tc, ts, x, y);
        int pos = off[r] + myh[r];
        myh[r]++;
        g_csr_idx[(size_t)a * CSTRIDE + pos] = (unsigned short)(t * 128 + x);
    }
    for (int i = t; i < 181; i += 128) g_csr_ptr[a * 181 + i] = off[i];
}

// ---------------- conv1: 1x1 conv + BN + ReLU via fp16 mma (R11-proven) ----------------
__global__ __launch_bounds__(256) void conv1h_kernel(
    const float* __restrict__ x, const __half2* __restrict__ wh,
    const float* __restrict__ b, const float* __restrict__ g,
    const float* __restrict__ be, const float* __restrict__ m,
    const float* __restrict__ v)
{
    __shared__ __half2 W1s[8 * 136];
    __shared__ __half2 Bs[8 * 136];
    __shared__ float sS[128], tS[128];
    int t = threadIdx.x;
    int px0 = blockIdx.x * 64;
    int n   = blockIdx.y;
    if (t < 128) {
        float sc = g[t] * rsqrtf(v[t] + 1e-5f);
        sS[t] = sc;
        tS[t] = (b[t] - m[t]) * sc + be[t];
    }
    int lane = t & 31, warp = t >> 5;
    int grp = lane >> 2, q4 = lane & 3;
    int co_base = warp * 16;

    float acc[8][4];
#pragma unroll
    for (int j = 0; j < 8; j++)
#pragma unroll
        for (int i = 0; i < 4; i++) acc[j][i] = 0.f;

    const float* xn = x + (size_t)n * CI1 * HW;

#pragma unroll 1
    for (int ch = 0; ch < 16; ch++) {
        int c8 = ch * 8;
        __syncthreads();
#pragma unroll
        for (int i = 0; i < 4; i++) {
            int e = t + i * 256;
            int ci2 = e >> 7, co = e & 127;
            W1s[ci2 * 136 + co] = wh[(c8 + ci2) * 128 + co];
        }
#pragma unroll
        for (int i = 0; i < 2; i++) {
            int e = t + i * 256;
            int ci2 = e >> 6, p = e & 63;
            float lo = xn[(size_t)(2 * (c8 + ci2)) * HW + px0 + p];
            float hi = xn[(size_t)(2 * (c8 + ci2) + 1) * HW + px0 + p];
            Bs[ci2 * 136 + p] = __floats2half2_rn(lo, hi);
        }
        __syncthreads();

        unsigned a0r = *(const unsigned*)(W1s + q4 * 136 + co_base + grp);
        unsigned a1r = *(const unsigned*)(W1s + q4 * 136 + co_base + grp + 8);
        unsigned a2r = *(const unsigned*)(W1s + (q4 + 4) * 136 + co_base + grp);
        unsigned a3r = *(const unsigned*)(W1s + (q4 + 4) * 136 + co_base + grp + 8);
#pragma unroll
        for (int jn = 0; jn < 8; jn++) {
            unsigned b0r = *(const unsigned*)(Bs + q4 * 136 + jn * 8 + grp);
            unsigned b1r = *(const unsigned*)(Bs + (q4 + 4) * 136 + jn * 8 + grp);
            asm volatile(
                "mma.sync.aligned.m16n8k16.row.col.f32.f16.f16.f32 "
                "{%0,%1,%2,%3}, {%4,%5,%6,%7}, {%8,%9}, {%0,%1,%2,%3};"
                : "+f"(acc[jn][0]), "+f"(acc[jn][1]),
                  "+f"(acc[jn][2]), "+f"(acc[jn][3])
                : "r"(a0r), "r"(a1r), "r"(a2r), "r"(a3r),
                  "r"(b0r), "r"(b1r));
        }
    }

    int co0 = co_base + grp;
    int co1 = co0 + 8;
    float sc0 = sS[co0], tt0 = tS[co0];
    float sc1 = sS[co1], tt1 = tS[co1];
#pragma unroll
    for (int jn = 0; jn < 8; jn++) {
        int p = px0 + jn * 8 + q4 * 2;
        __half* d0 = g_ft + (size_t)p * NC + n * DIM;
        __half* d1 = g_ft + (size_t)(p + 1) * NC + n * DIM;
        d0[co0] = __float2half_rn(fmaxf(acc[jn][0] * sc0 + tt0, 0.f));
        d1[co0] = __float2half_rn(fmaxf(acc[jn][1] * sc0 + tt0, 0.f));
        d0[co1] = __float2half_rn(fmaxf(acc[jn][2] * sc1 + tt1, 0.f));
        d1[co1] = __float2half_rn(fmaxf(acc[jn][3] * sc1 + tt1, 0.f));
    }
}

// ---------------- DHT gather (R13-proven): prefetch + HADD2 + packed output ----------------
__global__ __launch_bounds__(256) void dhtg_kernel() {
    __shared__ int ptrS[181];
    int a = blockIdx.x, n = blockIdx.y, t = threadIdx.x;
    for (int i = t; i < 181; i += 256) ptrS[i] = g_csr_ptr[a * 181 + i];
    __syncthreads();

    int w = t >> 5, lane = t & 31;
    int total = ptrS[180];
    int th0 = (w * total) >> 3;
    int th1 = ((w + 1) * total) >> 3;
    int b0 = 0;
    while (b0 < 180 && ptrS[b0] < th0) b0++;
    int b1;
    if (w == 7) b1 = 180;
    else { b1 = 0; while (b1 < 180 && ptrS[b1] < th1) b1++; }

    const __half* fbase = g_ft + n * DIM + (lane << 2);
    const unsigned short* ibase = g_csr_idx + (size_t)a * CSTRIDE;

    uint4 I = *(const uint4*)(ibase + ptrS[b0]);

    for (int r = b0; r < b1; r++) {
        int s = ptrS[r], e = ptrS[r + 1];     // multiples of 8
        float a0 = 0.f, a1 = 0.f, a2 = 0.f, a3 = 0.f;
        float c0 = 0.f, c1 = 0.f, c2 = 0.f, c3 = 0.f;
        for (int i = s; i < e; i += 8) {
            uint4 In = *(const uint4*)(ibase + i + 8);   // next group (pad-safe)
            int p0 = I.x & 0xFFFF, p1 = I.x >> 16;
            int p2 = I.y & 0xFFFF, p3 = I.y >> 16;
            int p4 = I.z & 0xFFFF, p5 = I.z >> 16;
            int p6 = I.w & 0xFFFF, p7 = I.w >> 16;
            uint2 u0 = *(const uint2*)(fbase + (size_t)p0 * NC);
            uint2 u1 = *(const uint2*)(fbase + (size_t)p1 * NC);
            uint2 u2 = *(const uint2*)(fbase + (size_t)p2 * NC);
            uint2 u3 = *(const uint2*)(fbase + (size_t)p3 * NC);
            uint2 u4 = *(const uint2*)(fbase + (size_t)p4 * NC);
            uint2 u5 = *(const uint2*)(fbase + (size_t)p5 * NC);
            uint2 u6 = *(const uint2*)(fbase + (size_t)p6 * NC);
            uint2 u7 = *(const uint2*)(fbase + (size_t)p7 * NC);
            __half2 h0x = __hadd2(*(__half2*)&u0.x, *(__half2*)&u1.x);
            __half2 h0y = __hadd2(*(__half2*)&u0.y, *(__half2*)&u1.y);
            __half2 h1x = __hadd2(*(__half2*)&u2.x, *(__half2*)&u3.x);
            __half2 h1y = __hadd2(*(__half2*)&u2.y, *(__half2*)&u3.y);
            __half2 h2x = __hadd2(*(__half2*)&u4.x, *(__half2*)&u5.x);
            __half2 h2y = __hadd2(*(__half2*)&u4.y, *(__half2*)&u5.y);
            __half2 h3x = __hadd2(*(__half2*)&u6.x, *(__half2*)&u7.x);
            __half2 h3y = __hadd2(*(__half2*)&u6.y, *(__half2*)&u7.y);
            float2 f;
            f = __half22float2(h0x); a0 += f.x; a1 += f.y;
            f = __half22float2(h0y); a2 += f.x; a3 += f.y;
            f = __half22float2(h1x); c0 += f.x; c1 += f.y;
            f = __half22float2(h1y); c2 += f.x; c3 += f.y;
            f = __half22float2(h2x); a0 += f.x; a1 += f.y;
            f = __half22float2(h2y); a2 += f.x; a3 += f.y;
            f = __half22float2(h3x); c0 += f.x; c1 += f.y;
            f = __half22float2(h3y); c2 += f.x; c3 += f.y;
            I = In;
        }
        a0 += c0; a1 += c1; a2 += c2; a3 += c3;
        size_t wb = ((size_t)(n * 64 + lane * 2)) * AR + a * 180 + r;
        __half2 o01 = __floats2half2_rn(a0, a1);
        __half2 o23 = __floats2half2_rn(a2, a3);
        g_acc[wb]      = *(unsigned*)&o01;
        g_acc[wb + AR] = *(unsigned*)&o23;
    }
}

// ---------------- conv3x3 + BN + ReLU: fp16 mma, double-buffered, B-frag preload ----------
#define WBUF_H2 9792
#define BBUF_H2 2496
#define WBUF_B  (WBUF_H2 * 4)
#define BBUF_B  (BBUF_H2 * 4)
#define C3_SMEM (2 * WBUF_B + 2 * BBUF_B + 1024)

template <int OUT_HALF>
__global__ __launch_bounds__(256, 2) void conv3h_kernel(
    const unsigned* __restrict__ src, const __half2* __restrict__ wh,
    const float* __restrict__ b,  const float* __restrict__ g,
    const float* __restrict__ be, const float* __restrict__ m,
    const float* __restrict__ v,  void* __restrict__ dstv)
{
    extern __shared__ __align__(16) char smraw[];
    char*  Wb  = smraw;
    char*  Bb  = smraw + 2 * WBUF_B;
    float* sS  = (float*)(smraw + 2 * WBUF_B + 2 * BBUF_B);
    float* tS  = sS + 128;
    uint32_t wsm = smem_u32(Wb);

    int t  = threadIdx.x;
    int r0 = blockIdx.x * 84;
    int a  = blockIdx.y;
    int n  = blockIdx.z;
    if (t < 128) {
        float sc = g[t] * rsqrtf(v[t] + 1e-5f);
        sS[t] = sc;
        tS[t] = (b[t] - m[t]) * sc + be[t];
    }

    int lane = t & 31, warp = t >> 5;
    int grp = lane >> 2, q4 = lane & 3;
    int co_base = warp * 16;
    int wci2 = t >> 5, wco4 = t & 31;

    float acc[12][4];
#pragma unroll
    for (int j = 0; j < 12; j++)
#pragma unroll
        for (int i = 0; i < 4; i++) acc[j][i] = 0.f;

    const unsigned* srcn = src + (size_t)n * 64 * AR;

    auto cpW = [&](int chunk, int buf) {
        uint32_t base = wsm + buf * WBUF_B;
#pragma unroll
        for (int i = 0; i < 9; i++) {
            uint32_t d = base + (uint32_t)(i * 4352 + wci2 * 544 + wco4 * 16);
            const __half2* s = wh + ((size_t)i * 64 + chunk * 8 + wci2) * 128 + wco4 * 4;
            CP_ASYNC16(d, s);
        }
        CP_COMMIT();
    };
    uint32_t pv[10];
    auto ldB = [&](int chunk) {
#pragma unroll
        for (int i = 0; i < 10; i++) {
            int e = t + i * 256;
            pv[i] = 0u;
            if (e < 2352) {
                int ci2 = e / 294;
                int rem = e - ci2 * 294;
                int ar  = rem / 98;
                int qq  = rem - ar * 98;
                int as  = a + ar - 1;
                int rs  = r0 - 1 + qq;
                if ((unsigned)as < 180u && (unsigned)rs < 180u)
                    pv[i] = srcn[((size_t)(chunk * 8 + ci2)) * AR + as * 180 + rs];
            }
        }
    };
    auto stB = [&](int buf) {
        uint32_t* Bw = (uint32_t*)(Bb + buf * BBUF_B);
#pragma unroll
        for (int i = 0; i < 10; i++) {
            int e = t + i * 256;
            if (e < 2352) {
                int ci2 = e / 294;
                int rem = e - ci2 * 294;
                int ar  = rem / 98;
                int qq  = rem - ar * 98;
                Bw[ci2 * 312 + ar * 104 + qq] = pv[i];
            }
        }
    };

    cpW(0, 0);
    ldB(0);
    CP_WAIT0();
    stB(0);
    __syncthreads();

#pragma unroll 1
    for (int c = 0; c < 8; c++) {
        int buf = c & 1;
        if (c < 7) { cpW(c + 1, buf ^ 1); ldB(c + 1); }

        const __half2* Wh2 = (const __half2*)(Wb + buf * WBUF_B);
        const __half2* Bh2 = (const __half2*)(Bb + buf * BBUF_B);
#pragma unroll
        for (int tap = 0; tap < 9; tap++) {
            int ky = tap / 3, kx = tap - 3 * (tap / 3);
            const __half2* wA = Wh2 + tap * 1088;
            unsigned a0r = *(const unsigned*)(wA + q4 * 136 + co_base + grp);
            unsigned a1r = *(const unsigned*)(wA + q4 * 136 + co_base + grp + 8);
            unsigned a2r = *(const unsigned*)(wA + (q4 + 4) * 136 + co_base + grp);
            unsigned a3r = *(const unsigned*)(wA + (q4 + 4) * 136 + co_base + grp + 8);
            const __half2* bB = Bh2 + ky * 104 + kx + grp;
            // preload all B frags for this tap (ILP: 24 independent LDS)
            unsigned bf[12][2];
#pragma unroll
            for (int jn = 0; jn < 12; jn++) {
                bf[jn][0] = *(const unsigned*)(bB + q4 * 312 + jn * 8);
                bf[jn][1] = *(const unsigned*)(bB + (q4 + 4) * 312 + jn * 8);
            }
#pragma unroll
            for (int jn = 0; jn < 12; jn++) {
                asm volatile(
                    "mma.sync.aligned.m16n8k16.row.col.f32.f16.f16.f32 "
                    "{%0,%1,%2,%3}, {%4,%5,%6,%7}, {%8,%9}, {%0,%1,%2,%3};"
                    : "+f"(acc[jn][0]), "+f"(acc[jn][1]),
                      "+f"(acc[jn][2]), "+f"(acc[jn][3])
                    : "r"(a0r), "r"(a1r), "r"(a2r), "r"(a3r),
                      "r"(bf[jn][0]), "r"(bf[jn][1]));
            }
        }

        if (c < 7) { CP_WAIT0(); stB(buf ^ 1); }
        __syncthreads();
    }

    int co0 = co_base + grp;
    int co1 = co0 + 8;
    float sc0 = sS[co0], tt0 = tS[co0];
    float sc1 = sS[co1], tt1 = tS[co1];
    if (OUT_HALF) {
        __half* dst = (__half*)dstv;
        size_t w0 = ((size_t)(n * 64 + (co0 >> 1))) * AR + a * 180 + r0;
        size_t w1 = ((size_t)(n * 64 + (co1 >> 1))) * AR + a * 180 + r0;
        int par = co0 & 1;
#pragma unroll
        for (int jn = 0; jn < 12; jn++) {
            int col = q4 * 2 + jn * 8;
            dst[2 * (w0 + col)     + par] = __float2half_rn(fmaxf(acc[jn][0] * sc0 + tt0, 0.f));
            dst[2 * (w0 + col + 1) + par] = __float2half_rn(fmaxf(acc[jn][1] * sc0 + tt0, 0.f));
            dst[2 * (w1 + col)     + par] = __float2half_rn(fmaxf(acc[jn][2] * sc1 + tt1, 0.f));
            dst[2 * (w1 + col + 1) + par] = __float2half_rn(fmaxf(acc[jn][3] * sc1 + tt1, 0.f));
        }
    } else {
        float* dst = (float*)dstv;
        size_t i0 = ((size_t)(n * DIM + co0) * 180 + a) * 180 + r0 + q4 * 2;
        size_t i1 = ((size_t)(n * DIM + co1) * 180 + a) * 180 + r0 + q4 * 2;
#pragma unroll
        for (int jn = 0; jn < 12; jn++) {
            float2 o0, o1;
            o0.x = fmaxf(acc[jn][0] * sc0 + tt0, 0.f);
            o0.y = fmaxf(acc[jn][1] * sc0 + tt0, 0.f);
            o1.x = fmaxf(acc[jn][2] * sc1 + tt1, 0.f);
            o1.y = fmaxf(acc[jn][3] * sc1 + tt1, 0.f);
            *(float2*)(dst + i0 + jn * 8) = o0;
            *(float2*)(dst + i1 + jn * 8) = o1;
        }
    }
}

// ---------------- launch ----------------
extern "C" void kernel_launch(void* const* d_in, const int* in_sizes, int n_in,
                              void* d_out, int out_size) {
    const float* x   = (const float*)d_in[0];
    const float* w1  = (const float*)d_in[1];
    const float* b1  = (const float*)d_in[2];
    const float* g1  = (const float*)d_in[3];
    const float* be1 = (const float*)d_in[4];
    const float* m1  = (const float*)d_in[5];
    const float* v1  = (const float*)d_in[6];
    const float* w2  = (const float*)d_in[7];
    const float* b2  = (const float*)d_in[8];
    const float* g2  = (const float*)d_in[9];
    const float* be2 = (const float*)d_in[10];
    const float* m2  = (const float*)d_in[11];
    const float* v2  = (const float*)d_in[12];
    const float* w3  = (const float*)d_in[13];
    const float* b3  = (const float*)d_in[14];
    const float* g3  = (const float*)d_in[15];
    const float* be3 = (const float*)d_in[16];
    const float* m3  = (const float*)d_in[17];
    const float* v3  = (const float*)d_in[18];
    float* out = (float*)d_out;

    void *p_w1h, *p_w2h, *p_w3h, *p_acc, *p_y2;
    cudaGetSymbolAddress(&p_w1h, g_w1h);
    cudaGetSymbolAddress(&p_w2h, g_w2h);
    cudaGetSymbolAddress(&p_w3h, g_w3h);
    cudaGetSymbolAddress(&p_acc, g_acc);
    cudaGetSymbolAddress(&p_y2,  g_y2);

    cudaFuncSetAttribute(conv3h_kernel<0>, cudaFuncAttributeMaxDynamicSharedMemorySize, C3_SMEM);
    cudaFuncSetAttribute(conv3h_kernel<1>, cudaFuncAttributeMaxDynamicSharedMemorySize, C3_SMEM);

    csr_kernel<<<A_ANG, 128>>>(w1, w2, w3);                              // 0
    conv1h_kernel<<<dim3(HW / 64, Nn), 256>>>(x, (const __half2*)p_w1h,  // 1
                                              b1, g1, be1, m1, v1);
    dhtg_kernel<<<dim3(A_ANG, Nn), 256>>>();                             // 2
    conv3h_kernel<1><<<dim3(2, A_ANG, Nn), 256, C3_SMEM>>>(              // 3 (profiled)
        (const unsigned*)p_acc, (const __half2*)p_w2h, b2, g2, be2, m2, v2, p_y2);
    conv3h_kernel<0><<<dim3(2, A_ANG, Nn), 256, C3_SMEM>>>(
        (const unsigned*)p_y2, (const __half2*)p_w3h, b3, g3, be3, m3, v3, out);
}

// round 15
// speedup vs baseline: 2.4727x; 1.0636x over previous
#include <cuda_runtime.h>
#include <cuda_fp16.h>
#include <cuda_bf16.h>
#include <math.h>
#include <stdint.h>

#define A_ANG 180
#define R_RHO 180
#define AR    32400
#define Hh    128
#define Ww    128
#define HW    16384
#define Nn    8
#define CI1   256
#define DIM   128
#define NC    1024      /* Nn*DIM */
#define CSTRIDE 17664   /* padded CSR row: >= 16384 + 180*7, mult of 8 */

// ---------------- static device scratch ----------------
__device__ __half         g_ft[(size_t)(HW + 8) * NC];     // conv1 out + zero pad row (p=HW)
__device__ unsigned       g_acc[(size_t)Nn * 64 * AR];     // DHT out, packed half2 [n][ci2][a][r]
__device__ unsigned       g_y2 [(size_t)Nn * 64 * AR];     // conv2 out, packed half2
__device__ __half2        g_w1h[128 * 128];                // conv1 weights [ci2][co]
__device__ __half2        g_w2h[9 * 64 * 128];             // conv3 weights [tap][ci2][co]
__device__ __half2        g_w3h[9 * 64 * 128];
__device__ unsigned short g_csr_idx[(size_t)A_ANG * CSTRIDE];
__device__ int            g_csr_ptr[A_ANG * 181];

#define W1_N    (128 * 128)
#define WH_N    (9 * 64 * 128)

__device__ __forceinline__ uint32_t smem_u32(const void* p) {
    uint32_t a;
    asm("{ .reg .u64 t; cvta.to.shared.u64 t, %1; cvt.u32.u64 %0, t; }" : "=r"(a) : "l"(p));
    return a;
}
#define CP_ASYNC16(dst_u32, src_ptr) \
    asm volatile("cp.async.ca.shared.global [%0], [%1], 16;" :: "r"(dst_u32), "l"(src_ptr))
#define CP_COMMIT()  asm volatile("cp.async.commit_group;")
#define CP_WAIT0()   asm volatile("cp.async.wait_group 0;" ::: "memory")

// seg bin for (a, x, y) — fp64, bit-matches numpy round-half-even binning
__device__ __forceinline__ int seg_bin(double tc, double ts, int x, int y) {
    double val = __dadd_rn(__dmul_rn(tc, (double)(x - Ww / 2)),
                           __dmul_rn(ts, (double)(y - Hh / 2)));
    long long r = (long long)rint(val) + R_RHO / 2;
    if (r < 0) r = 0;
    if (r > R_RHO - 1) r = R_RHO - 1;
    return (int)r;
}

// ---------------- CSR build (seg inline) + weight prep piggyback ----------
__global__ __launch_bounds__(128) void csr_kernel(const float* __restrict__ w1,
                                                  const float* __restrict__ w2,
                                                  const float* __restrict__ w3) {
    __shared__ unsigned short hist[128][180];
    __shared__ int off[181];
    int a = blockIdx.x, t = threadIdx.x;

    for (int i = a * 128 + t; i < W1_N + 2 * WH_N; i += A_ANG * 128) {
        if (i < W1_N) {
            int ci2 = i >> 7, co = i & 127;
            g_w1h[i] = __floats2half2_rn(w1[co * CI1 + 2 * ci2], w1[co * CI1 + 2 * ci2 + 1]);
        } else {
            int q = i - W1_N;
            const float* w = (q < WH_N) ? w2 : w3;
            __half2* wh    = (q < WH_N) ? g_w2h : g_w3h;
            q = (q < WH_N) ? q : q - WH_N;
            int tap = q >> 13, ci2 = (q >> 7) & 63, co = q & 127;
            wh[q] = __floats2half2_rn(w[co * 1152 + (2 * ci2) * 9 + tap],
                                      w[co * 1152 + (2 * ci2 + 1) * 9 + tap]);
        }
    }

    for (int i = t; i < CSTRIDE; i += 128)
        g_csr_idx[(size_t)a * CSTRIDE + i] = (unsigned short)HW;

    double irho = (double)((int)(sqrt((double)(Hh * Hh + Ww * Ww)) + 1.0)) / (double)(R_RHO - 1);
    double theta = (double)a * (3.141592653589793 / (double)A_ANG);
    double tc = cos(theta) / irho;
    double ts = sin(theta) / irho;
    int y = t;

    for (int r = 0; r < 180; r++) hist[t][r] = 0;
    for (int x = 0; x < 128; x++) hist[t][seg_bin(tc, ts, x, y)]++;
    __syncthreads();

    for (int r = t; r < 180; r += 128) {
        int run = 0;
        for (int q = 0; q < 128; q++) {
            int tmp = hist[q][r];
            hist[q][r] = (unsigned short)run;
            run += tmp;
        }
        off[r] = run;
    }
    __syncthreads();
    if (t == 0) {
        int run = 0;
        for (int r = 0; r < 180; r++) {
            int tot = off[r];
            off[r] = run;
            run += (tot + 7) & ~7;
        }
        off[180] = run;
    }
    __syncthreads();

    unsigned short* myh = hist[t];
    for (int x = 0; x < 128; x++) {
        int r = seg_bin(tc, ts, x, y);
        int pos = off[r] + myh[r];
        myh[r]++;
        g_csr_idx[(size_t)a * CSTRIDE + pos] = (unsigned short)(t * 128 + x);
    }
    for (int i = t; i < 181; i += 128) g_csr_ptr[a * 181 + i] = off[i];
}

// ---------------- conv1: 1x1 conv + BN + ReLU via fp16 mma (R11-proven) ----------------
__global__ __launch_bounds__(256) void conv1h_kernel(
    const float* __restrict__ x, const __half2* __restrict__ wh,
    const float* __restrict__ b, const float* __restrict__ g,
    const float* __restrict__ be, const float* __restrict__ m,
    const float* __restrict__ v)
{
    __shared__ __half2 W1s[8 * 136];
    __shared__ __half2 Bs[8 * 136];
    __shared__ float sS[128], tS[128];
    int t = threadIdx.x;
    int px0 = blockIdx.x * 64;
    int n   = blockIdx.y;
    if (t < 128) {
        float sc = g[t] * rsqrtf(v[t] + 1e-5f);
        sS[t] = sc;
        tS[t] = (b[t] - m[t]) * sc + be[t];
    }
    int lane = t & 31, warp = t >> 5;
    int grp = lane >> 2, q4 = lane & 3;
    int co_base = warp * 16;

    float acc[8][4];
#pragma unroll
    for (int j = 0; j < 8; j++)
#pragma unroll
        for (int i = 0; i < 4; i++) acc[j][i] = 0.f;

    const float* xn = x + (size_t)n * CI1 * HW;

#pragma unroll 1
    for (int ch = 0; ch < 16; ch++) {
        int c8 = ch * 8;
        __syncthreads();
#pragma unroll
        for (int i = 0; i < 4; i++) {
            int e = t + i * 256;
            int ci2 = e >> 7, co = e & 127;
            W1s[ci2 * 136 + co] = wh[(c8 + ci2) * 128 + co];
        }
#pragma unroll
        for (int i = 0; i < 2; i++) {
            int e = t + i * 256;
            int ci2 = e >> 6, p = e & 63;
            float lo = xn[(size_t)(2 * (c8 + ci2)) * HW + px0 + p];
            float hi = xn[(size_t)(2 * (c8 + ci2) + 1) * HW + px0 + p];
            Bs[ci2 * 136 + p] = __floats2half2_rn(lo, hi);
        }
        __syncthreads();

        unsigned a0r = *(const unsigned*)(W1s + q4 * 136 + co_base + grp);
        unsigned a1r = *(const unsigned*)(W1s + q4 * 136 + co_base + grp + 8);
        unsigned a2r = *(const unsigned*)(W1s + (q4 + 4) * 136 + co_base + grp);
        unsigned a3r = *(const unsigned*)(W1s + (q4 + 4) * 136 + co_base + grp + 8);
#pragma unroll
        for (int jn = 0; jn < 8; jn++) {
            unsigned b0r = *(const unsigned*)(Bs + q4 * 136 + jn * 8 + grp);
            unsigned b1r = *(const unsigned*)(Bs + (q4 + 4) * 136 + jn * 8 + grp);
            asm volatile(
                "mma.sync.aligned.m16n8k16.row.col.f32.f16.f16.f32 "
                "{%0,%1,%2,%3}, {%4,%5,%6,%7}, {%8,%9}, {%0,%1,%2,%3};"
                : "+f"(acc[jn][0]), "+f"(acc[jn][1]),
                  "+f"(acc[jn][2]), "+f"(acc[jn][3])
                : "r"(a0r), "r"(a1r), "r"(a2r), "r"(a3r),
                  "r"(b0r), "r"(b1r));
        }
    }

    int co0 = co_base + grp;
    int co1 = co0 + 8;
    float sc0 = sS[co0], tt0 = tS[co0];
    float sc1 = sS[co1], tt1 = tS[co1];
#pragma unroll
    for (int jn = 0; jn < 8; jn++) {
        int p = px0 + jn * 8 + q4 * 2;
        __half* d0 = g_ft + (size_t)p * NC + n * DIM;
        __half* d1 = g_ft + (size_t)(p + 1) * NC + n * DIM;
        d0[co0] = __float2half_rn(fmaxf(acc[jn][0] * sc0 + tt0, 0.f));
        d1[co0] = __float2half_rn(fmaxf(acc[jn][1] * sc0 + tt0, 0.f));
        d0[co1] = __float2half_rn(fmaxf(acc[jn][2] * sc1 + tt1, 0.f));
        d1[co1] = __float2half_rn(fmaxf(acc[jn][3] * sc1 + tt1, 0.f));
    }
}

// ---------------- DHT gather (R13-proven): prefetch + HADD2 + packed output ----------------
__global__ __launch_bounds__(256) void dhtg_kernel() {
    __shared__ int ptrS[181];
    int a = blockIdx.x, n = blockIdx.y, t = threadIdx.x;
    for (int i = t; i < 181; i += 256) ptrS[i] = g_csr_ptr[a * 181 + i];
    __syncthreads();

    int w = t >> 5, lane = t & 31;
    int total = ptrS[180];
    int th0 = (w * total) >> 3;
    int th1 = ((w + 1) * total) >> 3;
    int b0 = 0;
    while (b0 < 180 && ptrS[b0] < th0) b0++;
    int b1;
    if (w == 7) b1 = 180;
    else { b1 = 0; while (b1 < 180 && ptrS[b1] < th1) b1++; }

    const __half* fbase = g_ft + n * DIM + (lane << 2);
    const unsigned short* ibase = g_csr_idx + (size_t)a * CSTRIDE;

    uint4 I = *(const uint4*)(ibase + ptrS[b0]);

    for (int r = b0; r < b1; r++) {
        int s = ptrS[r], e = ptrS[r + 1];
        float a0 = 0.f, a1 = 0.f, a2 = 0.f, a3 = 0.f;
        float c0 = 0.f, c1 = 0.f, c2 = 0.f, c3 = 0.f;
        for (int i = s; i < e; i += 8) {
            uint4 In = *(const uint4*)(ibase + i + 8);
            int p0 = I.x & 0xFFFF, p1 = I.x >> 16;
            int p2 = I.y & 0xFFFF, p3 = I.y >> 16;
            int p4 = I.z & 0xFFFF, p5 = I.z >> 16;
            int p6 = I.w & 0xFFFF, p7 = I.w >> 16;
            uint2 u0 = *(const uint2*)(fbase + (size_t)p0 * NC);
            uint2 u1 = *(const uint2*)(fbase + (size_t)p1 * NC);
            uint2 u2 = *(const uint2*)(fbase + (size_t)p2 * NC);
            uint2 u3 = *(const uint2*)(fbase + (size_t)p3 * NC);
            uint2 u4 = *(const uint2*)(fbase + (size_t)p4 * NC);
            uint2 u5 = *(const uint2*)(fbase + (size_t)p5 * NC);
            uint2 u6 = *(const uint2*)(fbase + (size_t)p6 * NC);
            uint2 u7 = *(const uint2*)(fbase + (size_t)p7 * NC);
            __half2 h0x = __hadd2(*(__half2*)&u0.x, *(__half2*)&u1.x);
            __half2 h0y = __hadd2(*(__half2*)&u0.y, *(__half2*)&u1.y);
            __half2 h1x = __hadd2(*(__half2*)&u2.x, *(__half2*)&u3.x);
            __half2 h1y = __hadd2(*(__half2*)&u2.y, *(__half2*)&u3.y);
            __half2 h2x = __hadd2(*(__half2*)&u4.x, *(__half2*)&u5.x);
            __half2 h2y = __hadd2(*(__half2*)&u4.y, *(__half2*)&u5.y);
            __half2 h3x = __hadd2(*(__half2*)&u6.x, *(__half2*)&u7.x);
            __half2 h3y = __hadd2(*(__half2*)&u6.y, *(__half2*)&u7.y);
            float2 f;
            f = __half22float2(h0x); a0 += f.x; a1 += f.y;
            f = __half22float2(h0y); a2 += f.x; a3 += f.y;
            f = __half22float2(h1x); c0 += f.x; c1 += f.y;
            f = __half22float2(h1y); c2 += f.x; c3 += f.y;
            f = __half22float2(h2x); a0 += f.x; a1 += f.y;
            f = __half22float2(h2y); a2 += f.x; a3 += f.y;
            f = __half22float2(h3x); c0 += f.x; c1 += f.y;
            f = __half22float2(h3y); c2 += f.x; c3 += f.y;
            I = In;
        }
        a0 += c0; a1 += c1; a2 += c2; a3 += c3;
        size_t wb = ((size_t)(n * 64 + lane * 2)) * AR + a * 180 + r;
        __half2 o01 = __floats2half2_rn(a0, a1);
        __half2 o23 = __floats2half2_rn(a2, a3);
        g_acc[wb]      = *(unsigned*)&o01;
        g_acc[wb + AR] = *(unsigned*)&o23;
    }
}

// ---------------- conv3x3 + BN + ReLU: fp16 mma, CO32xCOL48 warp tile -------------------
#define WBUF_H2 9792
#define BBUF_H2 2496
#define WBUF_B  (WBUF_H2 * 4)
#define BBUF_B  (BBUF_H2 * 4)
#define C3_SMEM (2 * WBUF_B + 2 * BBUF_B + 1024)

template <int OUT_HALF>
__global__ __launch_bounds__(256, 2) void conv3h_kernel(
    const unsigned* __restrict__ src, const __half2* __restrict__ wh,
    const float* __restrict__ b,  const float* __restrict__ g,
    const float* __restrict__ be, const float* __restrict__ m,
    const float* __restrict__ v,  void* __restrict__ dstv)
{
    extern __shared__ __align__(16) char smraw[];
    char*  Wb  = smraw;
    char*  Bb  = smraw + 2 * WBUF_B;
    float* sS  = (float*)(smraw + 2 * WBUF_B + 2 * BBUF_B);
    float* tS  = sS + 128;
    uint32_t wsm = smem_u32(Wb);

    int t  = threadIdx.x;
    int r0 = blockIdx.x * 84;
    int a  = blockIdx.y;
    int n  = blockIdx.z;
    if (t < 128) {
        float sc = g[t] * rsqrtf(v[t] + 1e-5f);
        sS[t] = sc;
        tS[t] = (b[t] - m[t]) * sc + be[t];
    }

    int lane = t & 31, warp = t >> 5;
    int grp = lane >> 2, q4 = lane & 3;
    int co_base  = (warp & 3) * 32;       // 2 m16 tiles: co_base, co_base+16
    int colbase  = (warp >> 2) * 48;      // 6 n8 tiles
    int wci2 = t >> 5, wco4 = t & 31;

    float acc[2][6][4];
#pragma unroll
    for (int u = 0; u < 2; u++)
#pragma unroll
        for (int j = 0; j < 6; j++)
#pragma unroll
            for (int i = 0; i < 4; i++) acc[u][j][i] = 0.f;

    const unsigned* srcn = src + (size_t)n * 64 * AR;

    auto cpW = [&](int chunk, int buf) {
        uint32_t base = wsm + buf * WBUF_B;
#pragma unroll
        for (int i = 0; i < 9; i++) {
            uint32_t d = base + (uint32_t)(i * 4352 + wci2 * 544 + wco4 * 16);
            const __half2* s = wh + ((size_t)i * 64 + chunk * 8 + wci2) * 128 + wco4 * 4;
            CP_ASYNC16(d, s);
        }
        CP_COMMIT();
    };
    uint32_t pv[10];
    auto ldB = [&](int chunk) {
#pragma unroll
        for (int i = 0; i < 10; i++) {
            int e = t + i * 256;
            pv[i] = 0u;
            if (e < 2352) {
                int ci2 = e / 294;
                int rem = e - ci2 * 294;
                int ar  = rem / 98;
                int qq  = rem - ar * 98;
                int as  = a + ar - 1;
                int rs  = r0 - 1 + qq;
                if ((unsigned)as < 180u && (unsigned)rs < 180u)
                    pv[i] = srcn[((size_t)(chunk * 8 + ci2)) * AR + as * 180 + rs];
            }
        }
    };
    auto stB = [&](int buf) {
        uint32_t* Bw = (uint32_t*)(Bb + buf * BBUF_B);
#pragma unroll
        for (int i = 0; i < 10; i++) {
            int e = t + i * 256;
            if (e < 2352) {
                int ci2 = e / 294;
                int rem = e - ci2 * 294;
                int ar  = rem / 98;
                int qq  = rem - ar * 98;
                Bw[ci2 * 312 + ar * 104 + qq] = pv[i];
            }
        }
    };

    cpW(0, 0);
    ldB(0);
    CP_WAIT0();
    stB(0);
    __syncthreads();

#pragma unroll 1
    for (int c = 0; c < 8; c++) {
        int buf = c & 1;
        if (c < 7) { cpW(c + 1, buf ^ 1); ldB(c + 1); }

        const __half2* Wh2 = (const __half2*)(Wb + buf * WBUF_B);
        const __half2* Bh2 = (const __half2*)(Bb + buf * BBUF_B);
#pragma unroll
        for (int tap = 0; tap < 9; tap++) {
            int ky = tap / 3, kx = tap - 3 * (tap / 3);
            const __half2* wA = Wh2 + tap * 1088;
            // A frags: two m16 co-tiles
            unsigned af[2][4];
#pragma unroll
            for (int u = 0; u < 2; u++) {
                int cb = co_base + u * 16 + grp;
                af[u][0] = *(const unsigned*)(wA + q4 * 136 + cb);
                af[u][1] = *(const unsigned*)(wA + q4 * 136 + cb + 8);
                af[u][2] = *(const unsigned*)(wA + (q4 + 4) * 136 + cb);
                af[u][3] = *(const unsigned*)(wA + (q4 + 4) * 136 + cb + 8);
            }
            const __half2* bB = Bh2 + ky * 104 + kx + grp + colbase;
            // B frags: 6 n8 tiles (preloaded, ILP)
            unsigned bf[6][2];
#pragma unroll
            for (int jn = 0; jn < 6; jn++) {
                bf[jn][0] = *(const unsigned*)(bB + q4 * 312 + jn * 8);
                bf[jn][1] = *(const unsigned*)(bB + (q4 + 4) * 312 + jn * 8);
            }
#pragma unroll
            for (int u = 0; u < 2; u++)
#pragma unroll
                for (int jn = 0; jn < 6; jn++) {
                    asm volatile(
                        "mma.sync.aligned.m16n8k16.row.col.f32.f16.f16.f32 "
                        "{%0,%1,%2,%3}, {%4,%5,%6,%7}, {%8,%9}, {%0,%1,%2,%3};"
                        : "+f"(acc[u][jn][0]), "+f"(acc[u][jn][1]),
                          "+f"(acc[u][jn][2]), "+f"(acc[u][jn][3])
                        : "r"(af[u][0]), "r"(af[u][1]), "r"(af[u][2]), "r"(af[u][3]),
                          "r"(bf[jn][0]), "r"(bf[jn][1]));
                }
        }

        if (c < 7) { CP_WAIT0(); stB(buf ^ 1); }
        __syncthreads();
    }

    // epilogue: 2 co-tiles x 6 col-tiles
#pragma unroll
    for (int u = 0; u < 2; u++) {
        int co0 = co_base + u * 16 + grp;
        int co1 = co0 + 8;
        float sc0 = sS[co0], tt0 = tS[co0];
        float sc1 = sS[co1], tt1 = tS[co1];
        if (OUT_HALF) {
            __half* dst = (__half*)dstv;
            size_t w0 = ((size_t)(n * 64 + (co0 >> 1))) * AR + a * 180 + r0 + colbase;
            size_t w1 = ((size_t)(n * 64 + (co1 >> 1))) * AR + a * 180 + r0 + colbase;
            int par = co0 & 1;
#pragma unroll
            for (int jn = 0; jn < 6; jn++) {
                int col = q4 * 2 + jn * 8;
                dst[2 * (w0 + col)     + par] = __float2half_rn(fmaxf(acc[u][jn][0] * sc0 + tt0, 0.f));
                dst[2 * (w0 + col + 1) + par] = __float2half_rn(fmaxf(acc[u][jn][1] * sc0 + tt0, 0.f));
                dst[2 * (w1 + col)     + par] = __float2half_rn(fmaxf(acc[u][jn][2] * sc1 + tt1, 0.f));
                dst[2 * (w1 + col + 1) + par] = __float2half_rn(fmaxf(acc[u][jn][3] * sc1 + tt1, 0.f));
            }
        } else {
            float* dst = (float*)dstv;
            size_t i0 = ((size_t)(n * DIM + co0) * 180 + a) * 180 + r0 + colbase + q4 * 2;
            size_t i1 = ((size_t)(n * DIM + co1) * 180 + a) * 180 + r0 + colbase + q4 * 2;
#pragma unroll
            for (int jn = 0; jn < 6; jn++) {
                float2 o0, o1;
                o0.x = fmaxf(acc[u][jn][0] * sc0 + tt0, 0.f);
                o0.y = fmaxf(acc[u][jn][1] * sc0 + tt0, 0.f);
                o1.x = fmaxf(acc[u][jn][2] * sc1 + tt1, 0.f);
                o1.y = fmaxf(acc[u][jn][3] * sc1 + tt1, 0.f);
                *(float2*)(dst + i0 + jn * 8) = o0;
                *(float2*)(dst + i1 + jn * 8) = o1;
            }
        }
    }
}

// ---------------- launch ----------------
extern "C" void kernel_launch(void* const* d_in, const int* in_sizes, int n_in,
                              void* d_out, int out_size) {
    const float* x   = (const float*)d_in[0];
    const float* w1  = (const float*)d_in[1];
    const float* b1  = (const float*)d_in[2];
    const float* g1  = (const float*)d_in[3];
    const float* be1 = (const float*)d_in[4];
    const float* m1  = (const float*)d_in[5];
    const float* v1  = (const float*)d_in[6];
    const float* w2  = (const float*)d_in[7];
    const float* b2  = (const float*)d_in[8];
    const float* g2  = (const float*)d_in[9];
    const float* be2 = (const float*)d_in[10];
    const float* m2  = (const float*)d_in[11];
    const float* v2  = (const float*)d_in[12];
    const float* w3  = (const float*)d_in[13];
    const float* b3  = (const float*)d_in[14];
    const float* g3  = (const float*)d_in[15];
    const float* be3 = (const float*)d_in[16];
    const float* m3  = (const float*)d_in[17];
    const float* v3  = (const float*)d_in[18];
    float* out = (float*)d_out;

    void *p_w1h, *p_w2h, *p_w3h, *p_acc, *p_y2;
    cudaGetSymbolAddress(&p_w1h, g_w1h);
    cudaGetSymbolAddress(&p_w2h, g_w2h);
    cudaGetSymbolAddress(&p_w3h, g_w3h);
    cudaGetSymbolAddress(&p_acc, g_acc);
    cudaGetSymbolAddress(&p_y2,  g_y2);

    cudaFuncSetAttribute(conv3h_kernel<0>, cudaFuncAttributeMaxDynamicSharedMemorySize, C3_SMEM);
    cudaFuncSetAttribute(conv3h_kernel<1>, cudaFuncAttributeMaxDynamicSharedMemorySize, C3_SMEM);

    csr_kernel<<<A_ANG, 128>>>(w1, w2, w3);
    conv1h_kernel<<<dim3(HW / 64, Nn), 256>>>(x, (const __half2*)p_w1h,
                                              b1, g1, be1, m1, v1);
    dhtg_kernel<<<dim3(A_ANG, Nn), 256>>>();
    conv3h_kernel<1><<<dim3(2, A_ANG, Nn), 256, C3_SMEM>>>(              // profiled
        (const unsigned*)p_acc, (const __half2*)p_w2h, b2, g2, be2, m2, v2, p_y2);
    conv3h_kernel<0><<<dim3(2, A_ANG, Nn), 256, C3_SMEM>>>(
        (const unsigned*)p_y2, (const __half2*)p_w3h, b3, g3, be3, m3, v3, out);
}

// round 16
// speedup vs baseline: 2.5456x; 1.0295x over previous
#include <cuda_runtime.h>
#include <cuda_fp16.h>
#include <cuda_bf16.h>
#include <math.h>
#include <stdint.h>

#define A_ANG 180
#define R_RHO 180
#define AR    32400
#define Hh    128
#define Ww    128
#define HW    16384
#define Nn    8
#define CI1   256
#define DIM   128
#define NC    1024      /* Nn*DIM */
#define CSTRIDE 17664   /* padded CSR row: >= 16384 + 180*7, mult of 8 */

// ---------------- static device scratch ----------------
__device__ __half         g_ft[(size_t)(HW + 8) * NC];     // conv1 out + zero pad row (p=HW)
__device__ unsigned       g_acc[(size_t)Nn * 64 * AR];     // DHT out, packed half2 [n][ci2][a][r]
__device__ unsigned       g_y2 [(size_t)Nn * 64 * AR];     // conv2 out, packed half2
__device__ __half2        g_w1h[128 * 128];                // conv1 weights [ci2][co]
__device__ __half2        g_w2h[9 * 64 * 128];             // conv3 weights [tap][ci2][co]
__device__ __half2        g_w3h[9 * 64 * 128];
__device__ unsigned short g_csr_idx[(size_t)A_ANG * CSTRIDE];
__device__ int            g_csr_ptr[A_ANG * 181];

#define W1_N    (128 * 128)
#define WH_N    (9 * 64 * 128)

__device__ __forceinline__ uint32_t smem_u32(const void* p) {
    uint32_t a;
    asm("{ .reg .u64 t; cvta.to.shared.u64 t, %1; cvt.u32.u64 %0, t; }" : "=r"(a) : "l"(p));
    return a;
}
#define CP_ASYNC16(dst_u32, src_ptr) \
    asm volatile("cp.async.ca.shared.global [%0], [%1], 16;" :: "r"(dst_u32), "l"(src_ptr))
#define CP_COMMIT()  asm volatile("cp.async.commit_group;")
#define CP_WAIT0()   asm volatile("cp.async.wait_group 0;" ::: "memory")

// seg bin for (a, x, y) — fp64, bit-matches numpy round-half-even binning
__device__ __forceinline__ int seg_bin(double tc, double ts, int x, int y) {
    double val = __dadd_rn(__dmul_rn(tc, (double)(x - Ww / 2)),
                           __dmul_rn(ts, (double)(y - Hh / 2)));
    long long r = (long long)rint(val) + R_RHO / 2;
    if (r < 0) r = 0;
    if (r > R_RHO - 1) r = R_RHO - 1;
    return (int)r;
}

// ---------------- CSR build (seg inline) + weight prep piggyback ----------
__global__ __launch_bounds__(128) void csr_kernel(const float* __restrict__ w1,
                                                  const float* __restrict__ w2,
                                                  const float* __restrict__ w3) {
    __shared__ unsigned short hist[128][180];
    __shared__ int off[181];
    int a = blockIdx.x, t = threadIdx.x;

    for (int i = a * 128 + t; i < W1_N + 2 * WH_N; i += A_ANG * 128) {
        if (i < W1_N) {
            int ci2 = i >> 7, co = i & 127;
            g_w1h[i] = __floats2half2_rn(w1[co * CI1 + 2 * ci2], w1[co * CI1 + 2 * ci2 + 1]);
        } else {
            int q = i - W1_N;
            const float* w = (q < WH_N) ? w2 : w3;
            __half2* wh    = (q < WH_N) ? g_w2h : g_w3h;
            q = (q < WH_N) ? q : q - WH_N;
            int tap = q >> 13, ci2 = (q >> 7) & 63, co = q & 127;
            wh[q] = __floats2half2_rn(w[co * 1152 + (2 * ci2) * 9 + tap],
                                      w[co * 1152 + (2 * ci2 + 1) * 9 + tap]);
        }
    }

    for (int i = t; i < CSTRIDE; i += 128)
        g_csr_idx[(size_t)a * CSTRIDE + i] = (unsigned short)HW;

    double irho = (double)((int)(sqrt((double)(Hh * Hh + Ww * Ww)) + 1.0)) / (double)(R_RHO - 1);
    double theta = (double)a * (3.141592653589793 / (double)A_ANG);
    double tc = cos(theta) / irho;
    double ts = sin(theta) / irho;
    int y = t;

    for (int r = 0; r < 180; r++) hist[t][r] = 0;
    for (int x = 0; x < 128; x++) hist[t][seg_bin(tc, ts, x, y)]++;
    __syncthreads();

    for (int r = t; r < 180; r += 128) {
        int run = 0;
        for (int q = 0; q < 128; q++) {
            int tmp = hist[q][r];
            hist[q][r] = (unsigned short)run;
            run += tmp;
        }
        off[r] = run;
    }
    __syncthreads();
    if (t == 0) {
        int run = 0;
        for (int r = 0; r < 180; r++) {
            int tot = off[r];
            off[r] = run;
            run += (tot + 7) & ~7;
        }
        off[180] = run;
    }
    __syncthreads();

    unsigned short* myh = hist[t];
    for (int x = 0; x < 128; x++) {
        int r = seg_bin(tc, ts, x, y);
        int pos = off[r] + myh[r];
        myh[r]++;
        g_csr_idx[(size_t)a * CSTRIDE + pos] = (unsigned short)(t * 128 + x);
    }
    for (int i = t; i < 181; i += 128) g_csr_ptr[a * 181 + i] = off[i];
}

// ---------------- conv1: 1x1 conv + BN + ReLU via fp16 mma (R11-proven) ----------------
__global__ __launch_bounds__(256) void conv1h_kernel(
    const float* __restrict__ x, const __half2* __restrict__ wh,
    const float* __restrict__ b, const float* __restrict__ g,
    const float* __restrict__ be, const float* __restrict__ m,
    const float* __restrict__ v)
{
    __shared__ __half2 W1s[8 * 136];
    __shared__ __half2 Bs[8 * 136];
    __shared__ float sS[128], tS[128];
    int t = threadIdx.x;
    int px0 = blockIdx.x * 64;
    int n   = blockIdx.y;
    if (t < 128) {
        float sc = g[t] * rsqrtf(v[t] + 1e-5f);
        sS[t] = sc;
        tS[t] = (b[t] - m[t]) * sc + be[t];
    }
    int lane = t & 31, warp = t >> 5;
    int grp = lane >> 2, q4 = lane & 3;
    int co_base = warp * 16;

    float acc[8][4];
#pragma unroll
    for (int j = 0; j < 8; j++)
#pragma unroll
        for (int i = 0; i < 4; i++) acc[j][i] = 0.f;

    const float* xn = x + (size_t)n * CI1 * HW;

#pragma unroll 1
    for (int ch = 0; ch < 16; ch++) {
        int c8 = ch * 8;
        __syncthreads();
#pragma unroll
        for (int i = 0; i < 4; i++) {
            int e = t + i * 256;
            int ci2 = e >> 7, co = e & 127;
            W1s[ci2 * 136 + co] = wh[(c8 + ci2) * 128 + co];
        }
#pragma unroll
        for (int i = 0; i < 2; i++) {
            int e = t + i * 256;
            int ci2 = e >> 6, p = e & 63;
            float lo = xn[(size_t)(2 * (c8 + ci2)) * HW + px0 + p];
            float hi = xn[(size_t)(2 * (c8 + ci2) + 1) * HW + px0 + p];
            Bs[ci2 * 136 + p] = __floats2half2_rn(lo, hi);
        }
        __syncthreads();

        unsigned a0r = *(const unsigned*)(W1s + q4 * 136 + co_base + grp);
        unsigned a1r = *(const unsigned*)(W1s + q4 * 136 + co_base + grp + 8);
        unsigned a2r = *(const unsigned*)(W1s + (q4 + 4) * 136 + co_base + grp);
        unsigned a3r = *(const unsigned*)(W1s + (q4 + 4) * 136 + co_base + grp + 8);
#pragma unroll
        for (int jn = 0; jn < 8; jn++) {
            unsigned b0r = *(const unsigned*)(Bs + q4 * 136 + jn * 8 + grp);
            unsigned b1r = *(const unsigned*)(Bs + (q4 + 4) * 136 + jn * 8 + grp);
            asm volatile(
                "mma.sync.aligned.m16n8k16.row.col.f32.f16.f16.f32 "
                "{%0,%1,%2,%3}, {%4,%5,%6,%7}, {%8,%9}, {%0,%1,%2,%3};"
                : "+f"(acc[jn][0]), "+f"(acc[jn][1]),
                  "+f"(acc[jn][2]), "+f"(acc[jn][3])
                : "r"(a0r), "r"(a1r), "r"(a2r), "r"(a3r),
                  "r"(b0r), "r"(b1r));
        }
    }

    int co0 = co_base + grp;
    int co1 = co0 + 8;
    float sc0 = sS[co0], tt0 = tS[co0];
    float sc1 = sS[co1], tt1 = tS[co1];
#pragma unroll
    for (int jn = 0; jn < 8; jn++) {
        int p = px0 + jn * 8 + q4 * 2;
        __half* d0 = g_ft + (size_t)p * NC + n * DIM;
        __half* d1 = g_ft + (size_t)(p + 1) * NC + n * DIM;
        d0[co0] = __float2half_rn(fmaxf(acc[jn][0] * sc0 + tt0, 0.f));
        d1[co0] = __float2half_rn(fmaxf(acc[jn][1] * sc0 + tt0, 0.f));
        d0[co1] = __float2half_rn(fmaxf(acc[jn][2] * sc1 + tt1, 0.f));
        d1[co1] = __float2half_rn(fmaxf(acc[jn][3] * sc1 + tt1, 0.f));
    }
}

// ---------------- DHT gather v3: uint4 loads, half-warp pixel split, level-2 tree ----------
__global__ __launch_bounds__(256) void dhtg_kernel() {
    __shared__ int ptrS[181];
    int a = blockIdx.x, n = blockIdx.y, t = threadIdx.x;
    for (int i = t; i < 181; i += 256) ptrS[i] = g_csr_ptr[a * 181 + i];
    __syncthreads();

    int w = t >> 5, lane = t & 31;
    int hw = lane >> 4;        // 0: pixels 0-3 of group, 1: pixels 4-7
    int cl = lane & 15;        // channel block: channels 8*cl .. 8*cl+7
    int total = ptrS[180];
    int th0 = (w * total) >> 3;
    int th1 = ((w + 1) * total) >> 3;
    int b0 = 0;
    while (b0 < 180 && ptrS[b0] < th0) b0++;
    int b1;
    if (w == 7) b1 = 180;
    else { b1 = 0; while (b1 < 180 && ptrS[b1] < th1) b1++; }

    const uint4* fb = (const uint4*)(g_ft + n * DIM + cl * 8);   // pixel stride: NC/8 = 128 uint4
    const unsigned short* ibase = g_csr_idx + (size_t)a * CSTRIDE;

    uint4 I = *(const uint4*)(ibase + ptrS[b0]);

    for (int r = b0; r < b1; r++) {
        int s = ptrS[r], e = ptrS[r + 1];     // multiples of 8
        float f0 = 0.f, f1 = 0.f, f2 = 0.f, f3 = 0.f;
        float f4 = 0.f, f5 = 0.f, f6 = 0.f, f7 = 0.f;
        for (int i = s; i < e; i += 8) {
            uint4 In = *(const uint4*)(ibase + i + 8);   // next group (pad-safe)
            int p0 = I.x & 0xFFFF, p1 = I.x >> 16;
            int p2 = I.y & 0xFFFF, p3 = I.y >> 16;
            int p4 = I.z & 0xFFFF, p5 = I.z >> 16;
            int p6 = I.w & 0xFFFF, p7 = I.w >> 16;
            int q0 = hw ? p4 : p0;
            int q1 = hw ? p5 : p1;
            int q2 = hw ? p6 : p2;
            int q3 = hw ? p7 : p3;
            uint4 u0 = fb[(size_t)q0 * 128];
            uint4 u1 = fb[(size_t)q1 * 128];
            uint4 u2 = fb[(size_t)q2 * 128];
            uint4 u3 = fb[(size_t)q3 * 128];
            // level-1 + level-2 fp16 tree over the 4 pixels, per channel pair
            __half2 ax = __hadd2(__hadd2(*(__half2*)&u0.x, *(__half2*)&u1.x),
                                 __hadd2(*(__half2*)&u2.x, *(__half2*)&u3.x));
            __half2 ay = __hadd2(__hadd2(*(__half2*)&u0.y, *(__half2*)&u1.y),
                                 __hadd2(*(__half2*)&u2.y, *(__half2*)&u3.y));
            __half2 az = __hadd2(__hadd2(*(__half2*)&u0.z, *(__half2*)&u1.z),
                                 __hadd2(*(__half2*)&u2.z, *(__half2*)&u3.z));
            __half2 aw = __hadd2(__hadd2(*(__half2*)&u0.w, *(__half2*)&u1.w),
                                 __hadd2(*(__half2*)&u2.w, *(__half2*)&u3.w));
            float2 f;
            f = __half22float2(ax); f0 += f.x; f1 += f.y;
            f = __half22float2(ay); f2 += f.x; f3 += f.y;
            f = __half22float2(az); f4 += f.x; f5 += f.y;
            f = __half22float2(aw); f6 += f.x; f7 += f.y;
            I = In;
        }
        // combine half-warps (lane L += lane L+16), then lanes 0-15 write
        f0 += __shfl_down_sync(0xFFFFFFFFu, f0, 16);
        f1 += __shfl_down_sync(0xFFFFFFFFu, f1, 16);
        f2 += __shfl_down_sync(0xFFFFFFFFu, f2, 16);
        f3 += __shfl_down_sync(0xFFFFFFFFu, f3, 16);
        f4 += __shfl_down_sync(0xFFFFFFFFu, f4, 16);
        f5 += __shfl_down_sync(0xFFFFFFFFu, f5, 16);
        f6 += __shfl_down_sync(0xFFFFFFFFu, f6, 16);
        f7 += __shfl_down_sync(0xFFFFFFFFu, f7, 16);
        if (hw == 0) {
            size_t wb = ((size_t)(n * 64 + cl * 4)) * AR + a * 180 + r;
            __half2 o01 = __floats2half2_rn(f0, f1);
            __half2 o23 = __floats2half2_rn(f2, f3);
            __half2 o45 = __floats2half2_rn(f4, f5);
            __half2 o67 = __floats2half2_rn(f6, f7);
            g_acc[wb]          = *(unsigned*)&o01;
            g_acc[wb + AR]     = *(unsigned*)&o23;
            g_acc[wb + 2 * AR] = *(unsigned*)&o45;
            g_acc[wb + 3 * (size_t)AR] = *(unsigned*)&o67;
        }
    }
}

// ---------------- conv3x3 + BN + ReLU: fp16 mma, CO32xCOL48 warp tile (R15-proven) --------
#define WBUF_H2 9792
#define BBUF_H2 2496
#define WBUF_B  (WBUF_H2 * 4)
#define BBUF_B  (BBUF_H2 * 4)
#define C3_SMEM (2 * WBUF_B + 2 * BBUF_B + 1024)

template <int OUT_HALF>
__global__ __launch_bounds__(256, 2) void conv3h_kernel(
    const unsigned* __restrict__ src, const __half2* __restrict__ wh,
    const float* __restrict__ b,  const float* __restrict__ g,
    const float* __restrict__ be, const float* __restrict__ m,
    const float* __restrict__ v,  void* __restrict__ dstv)
{
    extern __shared__ __align__(16) char smraw[];
    char*  Wb  = smraw;
    char*  Bb  = smraw + 2 * WBUF_B;
    float* sS  = (float*)(smraw + 2 * WBUF_B + 2 * BBUF_B);
    float* tS  = sS + 128;
    uint32_t wsm = smem_u32(Wb);

    int t  = threadIdx.x;
    int r0 = blockIdx.x * 84;
    int a  = blockIdx.y;
    int n  = blockIdx.z;
    if (t < 128) {
        float sc = g[t] * rsqrtf(v[t] + 1e-5f);
        sS[t] = sc;
        tS[t] = (b[t] - m[t]) * sc + be[t];
    }

    int lane = t & 31, warp = t >> 5;
    int grp = lane >> 2, q4 = lane & 3;
    int co_base  = (warp & 3) * 32;
    int colbase  = (warp >> 2) * 48;
    int wci2 = t >> 5, wco4 = t & 31;

    float acc[2][6][4];
#pragma unroll
    for (int u = 0; u < 2; u++)
#pragma unroll
        for (int j = 0; j < 6; j++)
#pragma unroll
            for (int i = 0; i < 4; i++) acc[u][j][i] = 0.f;

    const unsigned* srcn = src + (size_t)n * 64 * AR;

    auto cpW = [&](int chunk, int buf) {
        uint32_t base = wsm + buf * WBUF_B;
#pragma unroll
        for (int i = 0; i < 9; i++) {
            uint32_t d = base + (uint32_t)(i * 4352 + wci2 * 544 + wco4 * 16);
            const __half2* s = wh + ((size_t)i * 64 + chunk * 8 + wci2) * 128 + wco4 * 4;
            CP_ASYNC16(d, s);
        }
        CP_COMMIT();
    };
    uint32_t pv[10];
    auto ldB = [&](int chunk) {
#pragma unroll
        for (int i = 0; i < 10; i++) {
            int e = t + i * 256;
            pv[i] = 0u;
            if (e < 2352) {
                int ci2 = e / 294;
                int rem = e - ci2 * 294;
                int ar  = rem / 98;
                int qq  = rem - ar * 98;
                int as  = a + ar - 1;
                int rs  = r0 - 1 + qq;
                if ((unsigned)as < 180u && (unsigned)rs < 180u)
                    pv[i] = srcn[((size_t)(chunk * 8 + ci2)) * AR + as * 180 + rs];
            }
        }
    };
    auto stB = [&](int buf) {
        uint32_t* Bw = (uint32_t*)(Bb + buf * BBUF_B);
#pragma unroll
        for (int i = 0; i < 10; i++) {
            int e = t + i * 256;
            if (e < 2352) {
                int ci2 = e / 294;
                int rem = e - ci2 * 294;
                int ar  = rem / 98;
                int qq  = rem - ar * 98;
                Bw[ci2 * 312 + ar * 104 + qq] = pv[i];
            }
        }
    };

    cpW(0, 0);
    ldB(0);
    CP_WAIT0();
    stB(0);
    __syncthreads();

#pragma unroll 1
    for (int c = 0; c < 8; c++) {
        int buf = c & 1;
        if (c < 7) { cpW(c + 1, buf ^ 1); ldB(c + 1); }

        const __half2* Wh2 = (const __half2*)(Wb + buf * WBUF_B);
        const __half2* Bh2 = (const __half2*)(Bb + buf * BBUF_B);
#pragma unroll
        for (int tap = 0; tap < 9; tap++) {
            int ky = tap / 3, kx = tap - 3 * (tap / 3);
            const __half2* wA = Wh2 + tap * 1088;
            unsigned af[2][4];
#pragma unroll
            for (int u = 0; u < 2; u++) {
                int cb = co_base + u * 16 + grp;
                af[u][0] = *(const unsigned*)(wA + q4 * 136 + cb);
                af[u][1] = *(const unsigned*)(wA + q4 * 136 + cb + 8);
                af[u][2] = *(const unsigned*)(wA + (q4 + 4) * 136 + cb);
                af[u][3] = *(const unsigned*)(wA + (q4 + 4) * 136 + cb + 8);
            }
            const __half2* bB = Bh2 + ky * 104 + kx + grp + colbase;
            unsigned bf[6][2];
#pragma unroll
            for (int jn = 0; jn < 6; jn++) {
                bf[jn][0] = *(const unsigned*)(bB + q4 * 312 + jn * 8);
                bf[jn][1] = *(const unsigned*)(bB + (q4 + 4) * 312 + jn * 8);
            }
#pragma unroll
            for (int u = 0; u < 2; u++)
#pragma unroll
                for (int jn = 0; jn < 6; jn++) {
                    asm volatile(
                        "mma.sync.aligned.m16n8k16.row.col.f32.f16.f16.f32 "
                        "{%0,%1,%2,%3}, {%4,%5,%6,%7}, {%8,%9}, {%0,%1,%2,%3};"
                        : "+f"(acc[u][jn][0]), "+f"(acc[u][jn][1]),
                          "+f"(acc[u][jn][2]), "+f"(acc[u][jn][3])
                        : "r"(af[u][0]), "r"(af[u][1]), "r"(af[u][2]), "r"(af[u][3]),
                          "r"(bf[jn][0]), "r"(bf[jn][1]));
                }
        }

        if (c < 7) { CP_WAIT0(); stB(buf ^ 1); }
        __syncthreads();
    }

#pragma unroll
    for (int u = 0; u < 2; u++) {
        int co0 = co_base + u * 16 + grp;
        int co1 = co0 + 8;
        float sc0 = sS[co0], tt0 = tS[co0];
        float sc1 = sS[co1], tt1 = tS[co1];
        if (OUT_HALF) {
            __half* dst = (__half*)dstv;
            size_t w0 = ((size_t)(n * 64 + (co0 >> 1))) * AR + a * 180 + r0 + colbase;
            size_t w1 = ((size_t)(n * 64 + (co1 >> 1))) * AR + a * 180 + r0 + colbase;
            int par = co0 & 1;
#pragma unroll
            for (int jn = 0; jn < 6; jn++) {
                int col = q4 * 2 + jn * 8;
                dst[2 * (w0 + col)     + par] = __float2half_rn(fmaxf(acc[u][jn][0] * sc0 + tt0, 0.f));
                dst[2 * (w0 + col + 1) + par] = __float2half_rn(fmaxf(acc[u][jn][1] * sc0 + tt0, 0.f));
                dst[2 * (w1 + col)     + par] = __float2half_rn(fmaxf(acc[u][jn][2] * sc1 + tt1, 0.f));
                dst[2 * (w1 + col + 1) + par] = __float2half_rn(fmaxf(acc[u][jn][3] * sc1 + tt1, 0.f));
            }
        } else {
            float* dst = (float*)dstv;
            size_t i0 = ((size_t)(n * DIM + co0) * 180 + a) * 180 + r0 + colbase + q4 * 2;
            size_t i1 = ((size_t)(n * DIM + co1) * 180 + a) * 180 + r0 + colbase + q4 * 2;
#pragma unroll
            for (int jn = 0; jn < 6; jn++) {
                float2 o0, o1;
                o0.x = fmaxf(acc[u][jn][0] * sc0 + tt0, 0.f);
                o0.y = fmaxf(acc[u][jn][1] * sc0 + tt0, 0.f);
                o1.x = fmaxf(acc[u][jn][2] * sc1 + tt1, 0.f);
                o1.y = fmaxf(acc[u][jn][3] * sc1 + tt1, 0.f);
                *(float2*)(dst + i0 + jn * 8) = o0;
                *(float2*)(dst + i1 + jn * 8) = o1;
            }
        }
    }
}

// ---------------- launch ----------------
extern "C" void kernel_launch(void* const* d_in, const int* in_sizes, int n_in,
                              void* d_out, int out_size) {
    const float* x   = (const float*)d_in[0];
    const float* w1  = (const float*)d_in[1];
    const float* b1  = (const float*)d_in[2];
    const float* g1  = (const float*)d_in[3];
    const float* be1 = (const float*)d_in[4];
    const float* m1  = (const float*)d_in[5];
    const float* v1  = (const float*)d_in[6];
    const float* w2  = (const float*)d_in[7];
    const float* b2  = (const float*)d_in[8];
    const float* g2  = (const float*)d_in[9];
    const float* be2 = (const float*)d_in[10];
    const float* m2  = (const float*)d_in[11];
    const float* v2  = (const float*)d_in[12];
    const float* w3  = (const float*)d_in[13];
    const float* b3  = (const float*)d_in[14];
    const float* g3  = (const float*)d_in[15];
    const float* be3 = (const float*)d_in[16];
    const float* m3  = (const float*)d_in[17];
    const float* v3  = (const float*)d_in[18];
    float* out = (float*)d_out;

    void *p_w1h, *p_w2h, *p_w3h, *p_acc, *p_y2;
    cudaGetSymbolAddress(&p_w1h, g_w1h);
    cudaGetSymbolAddress(&p_w2h, g_w2h);
    cudaGetSymbolAddress(&p_w3h, g_w3h);
    cudaGetSymbolAddress(&p_acc, g_acc);
    cudaGetSymbolAddress(&p_y2,  g_y2);

    cudaFuncSetAttribute(conv3h_kernel<0>, cudaFuncAttributeMaxDynamicSharedMemorySize, C3_SMEM);
    cudaFuncSetAttribute(conv3h_kernel<1>, cudaFuncAttributeMaxDynamicSharedMemorySize, C3_SMEM);

    csr_kernel<<<A_ANG, 128>>>(w1, w2, w3);
    conv1h_kernel<<<dim3(HW / 64, Nn), 256>>>(x, (const __half2*)p_w1h,
                                              b1, g1, be1, m1, v1);
    dhtg_kernel<<<dim3(A_ANG, Nn), 256>>>();
    conv3h_kernel<1><<<dim3(2, A_ANG, Nn), 256, C3_SMEM>>>(              // profiled
        (const unsigned*)p_acc, (const __half2*)p_w2h, b2, g2, be2, m2, v2, p_y2);
    conv3h_kernel<0><<<dim3(2, A_ANG, Nn), 256, C3_SMEM>>>(
        (const unsigned*)p_y2, (const __half2*)p_w3h, b3, g3, be3, m3, v3, out);
}

// round 17
// speedup vs baseline: 2.5496x; 1.0016x over previous
#include <cuda_runtime.h>
#include <cuda_fp16.h>
#include <cuda_bf16.h>
#include <math.h>
#include <stdint.h>

#define A_ANG 180
#define R_RHO 180
#define AR    32400
#define Hh    128
#define Ww    128
#define HW    16384
#define Nn    8
#define CI1   256
#define DIM   128
#define NC    1024      /* Nn*DIM */
#define CSTRIDE 17664   /* padded CSR row: >= 16384 + 180*7, mult of 8 */

// ---------------- static device scratch ----------------
__device__ __half         g_ft[(size_t)(HW + 8) * NC];     // conv1 out + zero pad row (p=HW)
__device__ unsigned       g_acc[(size_t)Nn * 64 * AR];     // DHT out, packed half2 [n][ci2][a][r]
__device__ unsigned       g_y2 [(size_t)Nn * 64 * AR];     // conv2 out, packed half2
__device__ __half2        g_w1h[128 * 128];                // conv1 weights [ci2][co]
__device__ __half2        g_w2h[9 * 64 * 128];             // conv3 weights [tap][ci2][co]
__device__ __half2        g_w3h[9 * 64 * 128];
__device__ unsigned short g_csr_idx[(size_t)A_ANG * CSTRIDE];
__device__ int            g_csr_ptr[A_ANG * 181];

#define W1_N    (128 * 128)
#define WH_N    (9 * 64 * 128)

__device__ __forceinline__ uint32_t smem_u32(const void* p) {
    uint32_t a;
    asm("{ .reg .u64 t; cvta.to.shared.u64 t, %1; cvt.u32.u64 %0, t; }" : "=r"(a) : "l"(p));
    return a;
}
#define CP_ASYNC16(dst_u32, src_ptr) \
    asm volatile("cp.async.ca.shared.global [%0], [%1], 16;" :: "r"(dst_u32), "l"(src_ptr))
#define CP_COMMIT()  asm volatile("cp.async.commit_group;")
#define CP_WAIT0()   asm volatile("cp.async.wait_group 0;" ::: "memory")

// seg bin for (a, x, y) — fp64, bit-matches numpy round-half-even binning
__device__ __forceinline__ int seg_bin(double tc, double ts, int x, int y) {
    double val = __dadd_rn(__dmul_rn(tc, (double)(x - Ww / 2)),
                           __dmul_rn(ts, (double)(y - Hh / 2)));
    long long r = (long long)rint(val) + R_RHO / 2;
    if (r < 0) r = 0;
    if (r > R_RHO - 1) r = R_RHO - 1;
    return (int)r;
}

// ---------------- CSR build (seg inline) + weight prep piggyback ----------
__global__ __launch_bounds__(128) void csr_kernel(const float* __restrict__ w1,
                                                  const float* __restrict__ w2,
                                                  const float* __restrict__ w3) {
    __shared__ unsigned short hist[128][180];
    __shared__ int off[181];
    int a = blockIdx.x, t = threadIdx.x;

    for (int i = a * 128 + t; i < W1_N + 2 * WH_N; i += A_ANG * 128) {
        if (i < W1_N) {
            int ci2 = i >> 7, co = i & 127;
            g_w1h[i] = __floats2half2_rn(w1[co * CI1 + 2 * ci2], w1[co * CI1 + 2 * ci2 + 1]);
        } else {
            int q = i - W1_N;
            const float* w = (q < WH_N) ? w2 : w3;
            __half2* wh    = (q < WH_N) ? g_w2h : g_w3h;
            q = (q < WH_N) ? q : q - WH_N;
            int tap = q >> 13, ci2 = (q >> 7) & 63, co = q & 127;
            wh[q] = __floats2half2_rn(w[co * 1152 + (2 * ci2) * 9 + tap],
                                      w[co * 1152 + (2 * ci2 + 1) * 9 + tap]);
        }
    }

    for (int i = t; i < CSTRIDE; i += 128)
        g_csr_idx[(size_t)a * CSTRIDE + i] = (unsigned short)HW;

    double irho = (double)((int)(sqrt((double)(Hh * Hh + Ww * Ww)) + 1.0)) / (double)(R_RHO - 1);
    double theta = (double)a * (3.141592653589793 / (double)A_ANG);
    double tc = cos(theta) / irho;
    double ts = sin(theta) / irho;
    int y = t;

    for (int r = 0; r < 180; r++) hist[t][r] = 0;
    for (int x = 0; x < 128; x++) hist[t][seg_bin(tc, ts, x, y)]++;
    __syncthreads();

    for (int r = t; r < 180; r += 128) {
        int run = 0;
        for (int q = 0; q < 128; q++) {
            int tmp = hist[q][r];
            hist[q][r] = (unsigned short)run;
            run += tmp;
        }
        off[r] = run;
    }
    __syncthreads();
    if (t == 0) {
        int run = 0;
        for (int r = 0; r < 180; r++) {
            int tot = off[r];
            off[r] = run;
            run += (tot + 7) & ~7;
        }
        off[180] = run;
    }
    __syncthreads();

    unsigned short* myh = hist[t];
    for (int x = 0; x < 128; x++) {
        int r = seg_bin(tc, ts, x, y);
        int pos = off[r] + myh[r];
        myh[r]++;
        g_csr_idx[(size_t)a * CSTRIDE + pos] = (unsigned short)(t * 128 + x);
    }
    for (int i = t; i < 181; i += 128) g_csr_ptr[a * 181 + i] = off[i];
}

// ---------------- conv1: 1x1 conv + BN + ReLU via fp16 mma, double-buffered --------------
__global__ __launch_bounds__(256) void conv1h_kernel(
    const float* __restrict__ x, const __half2* __restrict__ wh,
    const float* __restrict__ b, const float* __restrict__ g,
    const float* __restrict__ be, const float* __restrict__ m,
    const float* __restrict__ v)
{
    __shared__ __half2 W1s[2][8 * 136];
    __shared__ __half2 Bs[2][8 * 136];
    __shared__ float sS[128], tS[128];
    int t = threadIdx.x;
    int px0 = blockIdx.x * 64;
    int n   = blockIdx.y;
    if (t < 128) {
        float sc = g[t] * rsqrtf(v[t] + 1e-5f);
        sS[t] = sc;
        tS[t] = (b[t] - m[t]) * sc + be[t];
    }
    int lane = t & 31, warp = t >> 5;
    int grp = lane >> 2, q4 = lane & 3;
    int co_base = warp * 16;

    float acc[8][4];
#pragma unroll
    for (int j = 0; j < 8; j++)
#pragma unroll
        for (int i = 0; i < 4; i++) acc[j][i] = 0.f;

    const float* xn = x + (size_t)n * CI1 * HW;

    __half2 wv[4];
    float xlo[2], xhi[2];
    auto ldW = [&](int ch) {
#pragma unroll
        for (int i = 0; i < 4; i++) {
            int e = t + i * 256;
            wv[i] = wh[(ch * 8 + (e >> 7)) * 128 + (e & 127)];
        }
    };
    auto ldX = [&](int ch) {
#pragma unroll
        for (int i = 0; i < 2; i++) {
            int e = t + i * 256;
            int ci2 = e >> 6, p = e & 63;
            xlo[i] = xn[(size_t)(2 * (ch * 8 + ci2)) * HW + px0 + p];
            xhi[i] = xn[(size_t)(2 * (ch * 8 + ci2) + 1) * HW + px0 + p];
        }
    };
    auto stW = [&](int buf) {
#pragma unroll
        for (int i = 0; i < 4; i++) {
            int e = t + i * 256;
            W1s[buf][(e >> 7) * 136 + (e & 127)] = wv[i];
        }
    };
    auto stX = [&](int buf) {
#pragma unroll
        for (int i = 0; i < 2; i++) {
            int e = t + i * 256;
            Bs[buf][(e >> 6) * 136 + (e & 63)] = __floats2half2_rn(xlo[i], xhi[i]);
        }
    };

    ldW(0); ldX(0);
    stW(0); stX(0);
    __syncthreads();

#pragma unroll 1
    for (int ch = 0; ch < 16; ch++) {
        int buf = ch & 1;
        if (ch < 15) { ldW(ch + 1); ldX(ch + 1); }

        unsigned a0r = *(const unsigned*)(W1s[buf] + q4 * 136 + co_base + grp);
        unsigned a1r = *(const unsigned*)(W1s[buf] + q4 * 136 + co_base + grp + 8);
        unsigned a2r = *(const unsigned*)(W1s[buf] + (q4 + 4) * 136 + co_base + grp);
        unsigned a3r = *(const unsigned*)(W1s[buf] + (q4 + 4) * 136 + co_base + grp + 8);
#pragma unroll
        for (int jn = 0; jn < 8; jn++) {
            unsigned b0r = *(const unsigned*)(Bs[buf] + q4 * 136 + jn * 8 + grp);
            unsigned b1r = *(const unsigned*)(Bs[buf] + (q4 + 4) * 136 + jn * 8 + grp);
            asm volatile(
                "mma.sync.aligned.m16n8k16.row.col.f32.f16.f16.f32 "
                "{%0,%1,%2,%3}, {%4,%5,%6,%7}, {%8,%9}, {%0,%1,%2,%3};"
                : "+f"(acc[jn][0]), "+f"(acc[jn][1]),
                  "+f"(acc[jn][2]), "+f"(acc[jn][3])
                : "r"(a0r), "r"(a1r), "r"(a2r), "r"(a3r),
                  "r"(b0r), "r"(b1r));
        }

        if (ch < 15) { stW(buf ^ 1); stX(buf ^ 1); }
        __syncthreads();
    }

    int co0 = co_base + grp;
    int co1 = co0 + 8;
    float sc0 = sS[co0], tt0 = tS[co0];
    float sc1 = sS[co1], tt1 = tS[co1];
#pragma unroll
    for (int jn = 0; jn < 8; jn++) {
        int p = px0 + jn * 8 + q4 * 2;
        __half* d0 = g_ft + (size_t)p * NC + n * DIM;
        __half* d1 = g_ft + (size_t)(p + 1) * NC + n * DIM;
        d0[co0] = __float2half_rn(fmaxf(acc[jn][0] * sc0 + tt0, 0.f));
        d1[co0] = __float2half_rn(fmaxf(acc[jn][1] * sc0 + tt0, 0.f));
        d0[co1] = __float2half_rn(fmaxf(acc[jn][2] * sc1 + tt1, 0.f));
        d1[co1] = __float2half_rn(fmaxf(acc[jn][3] * sc1 + tt1, 0.f));
    }
}

// ---------------- DHT gather v4: 2 blocks per (a,n) — finer wave packing ------------------
__global__ __launch_bounds__(256) void dhtg_kernel() {
    __shared__ int ptrS[181];
    int a = blockIdx.x, n = blockIdx.y, t = threadIdx.x;
    for (int i = t; i < 181; i += 256) ptrS[i] = g_csr_ptr[a * 181 + i];
    __syncthreads();

    int w16 = blockIdx.z * 8 + (t >> 5);   // 1/16 pixel-mass slice
    int lane = t & 31;
    int hw = lane >> 4;
    int cl = lane & 15;
    int total = ptrS[180];
    int th0 = (w16 * total) >> 4;
    int th1 = ((w16 + 1) * total) >> 4;
    int b0 = 0;
    while (b0 < 180 && ptrS[b0] < th0) b0++;
    int b1;
    if (w16 == 15) b1 = 180;
    else { b1 = 0; while (b1 < 180 && ptrS[b1] < th1) b1++; }
    if (b0 >= b1) return;

    const uint4* fb = (const uint4*)(g_ft + n * DIM + cl * 8);
    const unsigned short* ibase = g_csr_idx + (size_t)a * CSTRIDE;

    uint4 I = *(const uint4*)(ibase + ptrS[b0]);

    for (int r = b0; r < b1; r++) {
        int s = ptrS[r], e = ptrS[r + 1];
        float f0 = 0.f, f1 = 0.f, f2 = 0.f, f3 = 0.f;
        float f4 = 0.f, f5 = 0.f, f6 = 0.f, f7 = 0.f;
        for (int i = s; i < e; i += 8) {
            uint4 In = *(const uint4*)(ibase + i + 8);
            int p0 = I.x & 0xFFFF, p1 = I.x >> 16;
            int p2 = I.y & 0xFFFF, p3 = I.y >> 16;
            int p4 = I.z & 0xFFFF, p5 = I.z >> 16;
            int p6 = I.w & 0xFFFF, p7 = I.w >> 16;
            int q0 = hw ? p4 : p0;
            int q1 = hw ? p5 : p1;
            int q2 = hw ? p6 : p2;
            int q3 = hw ? p7 : p3;
            uint4 u0 = fb[(size_t)q0 * 128];
            uint4 u1 = fb[(size_t)q1 * 128];
            uint4 u2 = fb[(size_t)q2 * 128];
            uint4 u3 = fb[(size_t)q3 * 128];
            __half2 ax = __hadd2(__hadd2(*(__half2*)&u0.x, *(__half2*)&u1.x),
                                 __hadd2(*(__half2*)&u2.x, *(__half2*)&u3.x));
            __half2 ay = __hadd2(__hadd2(*(__half2*)&u0.y, *(__half2*)&u1.y),
                                 __hadd2(*(__half2*)&u2.y, *(__half2*)&u3.y));
            __half2 az = __hadd2(__hadd2(*(__half2*)&u0.z, *(__half2*)&u1.z),
                                 __hadd2(*(__half2*)&u2.z, *(__half2*)&u3.z));
            __half2 aw = __hadd2(__hadd2(*(__half2*)&u0.w, *(__half2*)&u1.w),
                                 __hadd2(*(__half2*)&u2.w, *(__half2*)&u3.w));
            float2 f;
            f = __half22float2(ax); f0 += f.x; f1 += f.y;
            f = __half22float2(ay); f2 += f.x; f3 += f.y;
            f = __half22float2(az); f4 += f.x; f5 += f.y;
            f = __half22float2(aw); f6 += f.x; f7 += f.y;
            I = In;
        }
        f0 += __shfl_down_sync(0xFFFFFFFFu, f0, 16);
        f1 += __shfl_down_sync(0xFFFFFFFFu, f1, 16);
        f2 += __shfl_down_sync(0xFFFFFFFFu, f2, 16);
        f3 += __shfl_down_sync(0xFFFFFFFFu, f3, 16);
        f4 += __shfl_down_sync(0xFFFFFFFFu, f4, 16);
        f5 += __shfl_down_sync(0xFFFFFFFFu, f5, 16);
        f6 += __shfl_down_sync(0xFFFFFFFFu, f6, 16);
        f7 += __shfl_down_sync(0xFFFFFFFFu, f7, 16);
        if (hw == 0) {
            size_t wb = ((size_t)(n * 64 + cl * 4)) * AR + a * 180 + r;
            __half2 o01 = __floats2half2_rn(f0, f1);
            __half2 o23 = __floats2half2_rn(f2, f3);
            __half2 o45 = __floats2half2_rn(f4, f5);
            __half2 o67 = __floats2half2_rn(f6, f7);
            g_acc[wb]          = *(unsigned*)&o01;
            g_acc[wb + AR]     = *(unsigned*)&o23;
            g_acc[wb + 2 * AR] = *(unsigned*)&o45;
            g_acc[wb + 3 * (size_t)AR] = *(unsigned*)&o67;
        }
    }
}

// ---------------- conv3x3 + BN + ReLU: fp16 mma, CO32xCOL48 warp tile (R15-proven) --------
#define WBUF_H2 9792
#define BBUF_H2 2496
#define WBUF_B  (WBUF_H2 * 4)
#define BBUF_B  (BBUF_H2 * 4)
#define C3_SMEM (2 * WBUF_B + 2 * BBUF_B + 1024)

template <int OUT_HALF>
__global__ __launch_bounds__(256, 2) void conv3h_kernel(
    const unsigned* __restrict__ src, const __half2* __restrict__ wh,
    const float* __restrict__ b,  const float* __restrict__ g,
    const float* __restrict__ be, const float* __restrict__ m,
    const float* __restrict__ v,  void* __restrict__ dstv)
{
    extern __shared__ __align__(16) char smraw[];
    char*  Wb  = smraw;
    char*  Bb  = smraw + 2 * WBUF_B;
    float* sS  = (float*)(smraw + 2 * WBUF_B + 2 * BBUF_B);
    float* tS  = sS + 128;
    uint32_t wsm = smem_u32(Wb);

    int t  = threadIdx.x;
    int r0 = blockIdx.x * 84;
    int a  = blockIdx.y;
    int n  = blockIdx.z;
    if (t < 128) {
        float sc = g[t] * rsqrtf(v[t] + 1e-5f);
        sS[t] = sc;
        tS[t] = (b[t] - m[t]) * sc + be[t];
    }

    int lane = t & 31, warp = t >> 5;
    int grp = lane >> 2, q4 = lane & 3;
    int co_base  = (warp & 3) * 32;
    int colbase  = (warp >> 2) * 48;
    int wci2 = t >> 5, wco4 = t & 31;

    float acc[2][6][4];
#pragma unroll
    for (int u = 0; u < 2; u++)
#pragma unroll
        for (int j = 0; j < 6; j++)
#pragma unroll
            for (int i = 0; i < 4; i++) acc[u][j][i] = 0.f;

    const unsigned* srcn = src + (size_t)n * 64 * AR;

    auto cpW = [&](int chunk, int buf) {
        uint32_t base = wsm + buf * WBUF_B;
#pragma unroll
        for (int i = 0; i < 9; i++) {
            uint32_t d = base + (uint32_t)(i * 4352 + wci2 * 544 + wco4 * 16);
            const __half2* s = wh + ((size_t)i * 64 + chunk * 8 + wci2) * 128 + wco4 * 4;
            CP_ASYNC16(d, s);
        }
        CP_COMMIT();
    };
    uint32_t pv[10];
    auto ldB = [&](int chunk) {
#pragma unroll
        for (int i = 0; i < 10; i++) {
            int e = t + i * 256;
            pv[i] = 0u;
            if (e < 2352) {
                int ci2 = e / 294;
                int rem = e - ci2 * 294;
                int ar  = rem / 98;
                int qq  = rem - ar * 98;
                int as  = a + ar - 1;
                int rs  = r0 - 1 + qq;
                if ((unsigned)as < 180u && (unsigned)rs < 180u)
                    pv[i] = srcn[((size_t)(chunk * 8 + ci2)) * AR + as * 180 + rs];
            }
        }
    };
    auto stB = [&](int buf) {
        uint32_t* Bw = (uint32_t*)(Bb + buf * BBUF_B);
#pragma unroll
        for (int i = 0; i < 10; i++) {
            int e = t + i * 256;
            if (e < 2352) {
                int ci2 = e / 294;
                int rem = e - ci2 * 294;
                int ar  = rem / 98;
                int qq  = rem - ar * 98;
                Bw[ci2 * 312 + ar * 104 + qq] = pv[i];
            }
        }
    };

    cpW(0, 0);
    ldB(0);
    CP_WAIT0();
    stB(0);
    __syncthreads();

#pragma unroll 1
    for (int c = 0; c < 8; c++) {
        int buf = c & 1;
        if (c < 7) { cpW(c + 1, buf ^ 1); ldB(c + 1); }

        const __half2* Wh2 = (const __half2*)(Wb + buf * WBUF_B);
        const __half2* Bh2 = (const __half2*)(Bb + buf * BBUF_B);
#pragma unroll
        for (int tap = 0; tap < 9; tap++) {
            int ky = tap / 3, kx = tap - 3 * (tap / 3);
            const __half2* wA = Wh2 + tap * 1088;
            unsigned af[2][4];
#pragma unroll
            for (int u = 0; u < 2; u++) {
                int cb = co_base + u * 16 + grp;
                af[u][0] = *(const unsigned*)(wA + q4 * 136 + cb);
                af[u][1] = *(const unsigned*)(wA + q4 * 136 + cb + 8);
                af[u][2] = *(const unsigned*)(wA + (q4 + 4) * 136 + cb);
                af[u][3] = *(const unsigned*)(wA + (q4 + 4) * 136 + cb + 8);
            }
            const __half2* bB = Bh2 + ky * 104 + kx + grp + colbase;
            unsigned bf[6][2];
#pragma unroll
            for (int jn = 0; jn < 6; jn++) {
                bf[jn][0] = *(const unsigned*)(bB + q4 * 312 + jn * 8);
                bf[jn][1] = *(const unsigned*)(bB + (q4 + 4) * 312 + jn * 8);
            }
#pragma unroll
            for (int u = 0; u < 2; u++)
#pragma unroll
                for (int jn = 0; jn < 6; jn++) {
                    asm volatile(
                        "mma.sync.aligned.m16n8k16.row.col.f32.f16.f16.f32 "
                        "{%0,%1,%2,%3}, {%4,%5,%6,%7}, {%8,%9}, {%0,%1,%2,%3};"
                        : "+f"(acc[u][jn][0]), "+f"(acc[u][jn][1]),
                          "+f"(acc[u][jn][2]), "+f"(acc[u][jn][3])
                        : "r"(af[u][0]), "r"(af[u][1]), "r"(af[u][2]), "r"(af[u][3]),
                          "r"(bf[jn][0]), "r"(bf[jn][1]));
                }
        }

        if (c < 7) { CP_WAIT0(); stB(buf ^ 1); }
        __syncthreads();
    }

#pragma unroll
    for (int u = 0; u < 2; u++) {
        int co0 = co_base + u * 16 + grp;
        int co1 = co0 + 8;
        float sc0 = sS[co0], tt0 = tS[co0];
        float sc1 = sS[co1], tt1 = tS[co1];
        if (OUT_HALF) {
            __half* dst = (__half*)dstv;
            size_t w0 = ((size_t)(n * 64 + (co0 >> 1))) * AR + a * 180 + r0 + colbase;
            size_t w1 = ((size_t)(n * 64 + (co1 >> 1))) * AR + a * 180 + r0 + colbase;
            int par = co0 & 1;
#pragma unroll
            for (int jn = 0; jn < 6; jn++) {
                int col = q4 * 2 + jn * 8;
                dst[2 * (w0 + col)     + par] = __float2half_rn(fmaxf(acc[u][jn][0] * sc0 + tt0, 0.f));
                dst[2 * (w0 + col + 1) + par] = __float2half_rn(fmaxf(acc[u][jn][1] * sc0 + tt0, 0.f));
                dst[2 * (w1 + col)     + par] = __float2half_rn(fmaxf(acc[u][jn][2] * sc1 + tt1, 0.f));
                dst[2 * (w1 + col + 1) + par] = __float2half_rn(fmaxf(acc[u][jn][3] * sc1 + tt1, 0.f));
            }
        } else {
            float* dst = (float*)dstv;
            size_t i0 = ((size_t)(n * DIM + co0) * 180 + a) * 180 + r0 + colbase + q4 * 2;
            size_t i1 = ((size_t)(n * DIM + co1) * 180 + a) * 180 + r0 + colbase + q4 * 2;
#pragma unroll
            for (int jn = 0; jn < 6; jn++) {
                float2 o0, o1;
                o0.x = fmaxf(acc[u][jn][0] * sc0 + tt0, 0.f);
                o0.y = fmaxf(acc[u][jn][1] * sc0 + tt0, 0.f);
                o1.x = fmaxf(acc[u][jn][2] * sc1 + tt1, 0.f);
                o1.y = fmaxf(acc[u][jn][3] * sc1 + tt1, 0.f);
                *(float2*)(dst + i0 + jn * 8) = o0;
                *(float2*)(dst + i1 + jn * 8) = o1;
            }
        }
    }
}

// ---------------- launch ----------------
extern "C" void kernel_launch(void* const* d_in, const int* in_sizes, int n_in,
                              void* d_out, int out_size) {
    const float* x   = (const float*)d_in[0];
    const float* w1  = (const float*)d_in[1];
    const float* b1  = (const float*)d_in[2];
    const float* g1  = (const float*)d_in[3];
    const float* be1 = (const float*)d_in[4];
    const float* m1  = (const float*)d_in[5];
    const float* v1  = (const float*)d_in[6];
    const float* w2  = (const float*)d_in[7];
    const float* b2  = (const float*)d_in[8];
    const float* g2  = (const float*)d_in[9];
    const float* be2 = (const float*)d_in[10];
    const float* m2  = (const float*)d_in[11];
    const float* v2  = (const float*)d_in[12];
    const float* w3  = (const float*)d_in[13];
    const float* b3  = (const float*)d_in[14];
    const float* g3  = (const float*)d_in[15];
    const float* be3 = (const float*)d_in[16];
    const float* m3  = (const float*)d_in[17];
    const float* v3  = (const float*)d_in[18];
    float* out = (float*)d_out;

    void *p_w1h, *p_w2h, *p_w3h, *p_acc, *p_y2;
    cudaGetSymbolAddress(&p_w1h, g_w1h);
    cudaGetSymbolAddress(&p_w2h, g_w2h);
    cudaGetSymbolAddress(&p_w3h, g_w3h);
    cudaGetSymbolAddress(&p_acc, g_acc);
    cudaGetSymbolAddress(&p_y2,  g_y2);

    cudaFuncSetAttribute(conv3h_kernel<0>, cudaFuncAttributeMaxDynamicSharedMemorySize, C3_SMEM);
    cudaFuncSetAttribute(conv3h_kernel<1>, cudaFuncAttributeMaxDynamicSharedMemorySize, C3_SMEM);

    csr_kernel<<<A_ANG, 128>>>(w1, w2, w3);
    conv1h_kernel<<<dim3(HW / 64, Nn), 256>>>(x, (const __half2*)p_w1h,
                                              b1, g1, be1, m1, v1);
    dhtg_kernel<<<dim3(A_ANG, Nn, 2), 256>>>();
    conv3h_kernel<1><<<dim3(2, A_ANG, Nn), 256, C3_SMEM>>>(              // profiled
        (const unsigned*)p_acc, (const __half2*)p_w2h, b2, g2, be2, m2, v2, p_y2);
    conv3h_kernel<0><<<dim3(2, A_ANG, Nn), 256, C3_SMEM>>>(
        (const unsigned*)p_y2, (const __half2*)p_w3h, b3, g3, be3, m3, v3, out);
}